// round 1
// baseline (speedup 1.0000x reference)
#include <cuda_runtime.h>
#include <math.h>

#define MDIM 64
#define NDIM 4096
#define BN   32
#define KB   32
#define KCHEB 14

// Scratch (allocation-free rule: __device__ globals)
__device__ float g_Gt[MDIM * MDIM];    // G~ = 2*G - I (symmetric)
__device__ float g_Y [MDIM * NDIM];    // Y = X @ Q_S
__device__ float g_Zt[MDIM * NDIM];    // Z~ = f(G) applied per column

// ---------------------------------------------------------------------------
// Kernel 1: G~ = 2 * (F^T F) / (||F^T F||_F + 1e-12) - I
// ---------------------------------------------------------------------------
__global__ __launch_bounds__(256) void prep_kernel(const float* __restrict__ F) {
    __shared__ float Fs[MDIM][MDIM + 1];
    __shared__ float FFs[MDIM][MDIM + 4];
    __shared__ float red[8];
    __shared__ float s_inv;

    int t = threadIdx.x;
    for (int o = t; o < MDIM * MDIM; o += 256)
        Fs[o >> 6][o & 63] = F[o];
    __syncthreads();

    // FF[i][j] = sum_k F[k][i] * F[k][j]; thread: row i, 16 cols
    int i  = t >> 2;
    int j0 = (t & 3) * 16;
    float acc[16];
#pragma unroll
    for (int u = 0; u < 16; u++) acc[u] = 0.0f;
    for (int k = 0; k < MDIM; k++) {
        float a = Fs[k][i];
#pragma unroll
        for (int u = 0; u < 16; u++) acc[u] = fmaf(a, Fs[k][j0 + u], acc[u]);
    }
    float ss = 0.0f;
#pragma unroll
    for (int u = 0; u < 16; u++) {
        FFs[i][j0 + u] = acc[u];
        ss = fmaf(acc[u], acc[u], ss);
    }
#pragma unroll
    for (int off = 16; off > 0; off >>= 1)
        ss += __shfl_xor_sync(0xffffffffu, ss, off);
    if ((t & 31) == 0) red[t >> 5] = ss;
    __syncthreads();
    if (t == 0) {
        float tot = 0.0f;
        for (int w = 0; w < 8; w++) tot += red[w];
        s_inv = 2.0f / (sqrtf(tot) + 1e-12f);
    }
    __syncthreads();
    float inv = s_inv;
#pragma unroll
    for (int u = 0; u < 16; u++) {
        int j = j0 + u;
        g_Gt[i * MDIM + j] = FFs[i][j] * inv - (i == j ? 1.0f : 0.0f);
    }
}

// ---------------------------------------------------------------------------
// Kernel 2: Y(64 x 4096) = A(64 x 4096) @ B(4096 x 4096)   (B = Q_S)
// ---------------------------------------------------------------------------
__global__ __launch_bounds__(256) void gemm_ab_kernel(const float* __restrict__ A,
                                                      const float* __restrict__ B,
                                                      float* __restrict__ C) {
    __shared__ __align__(16) float As[KB][68];  // As[k][i]
    __shared__ __align__(16) float Bs[KB][36];  // Bs[k][j]

    int t  = threadIdx.x;
    int jg = blockIdx.x * BN;
    int i0 = (t & 15) * 4;
    int j0 = (t >> 4) * 2;

    int la_i = t >> 2;          // 0..63
    int la_k = (t & 3) * 8;     // 0,8,16,24
    int lb_k = t >> 3;          // 0..31
    int lb_j = (t & 7) * 4;     // 0..28

    float acc[4][2];
#pragma unroll
    for (int r = 0; r < 4; r++) { acc[r][0] = 0.0f; acc[r][1] = 0.0f; }

    for (int kb = 0; kb < NDIM; kb += KB) {
        float4 a0 = *(const float4*)&A[la_i * NDIM + kb + la_k];
        float4 a1 = *(const float4*)&A[la_i * NDIM + kb + la_k + 4];
        As[la_k + 0][la_i] = a0.x; As[la_k + 1][la_i] = a0.y;
        As[la_k + 2][la_i] = a0.z; As[la_k + 3][la_i] = a0.w;
        As[la_k + 4][la_i] = a1.x; As[la_k + 5][la_i] = a1.y;
        As[la_k + 6][la_i] = a1.z; As[la_k + 7][la_i] = a1.w;
        *(float4*)&Bs[lb_k][lb_j] = *(const float4*)&B[(size_t)(kb + lb_k) * NDIM + jg + lb_j];
        __syncthreads();
#pragma unroll
        for (int k = 0; k < KB; k++) {
            float4 av = *(const float4*)&As[k][i0];
            float2 bv = *(const float2*)&Bs[k][j0];
            acc[0][0] = fmaf(av.x, bv.x, acc[0][0]); acc[0][1] = fmaf(av.x, bv.y, acc[0][1]);
            acc[1][0] = fmaf(av.y, bv.x, acc[1][0]); acc[1][1] = fmaf(av.y, bv.y, acc[1][1]);
            acc[2][0] = fmaf(av.z, bv.x, acc[2][0]); acc[2][1] = fmaf(av.z, bv.y, acc[2][1]);
            acc[3][0] = fmaf(av.w, bv.x, acc[3][0]); acc[3][1] = fmaf(av.w, bv.y, acc[3][1]);
        }
        __syncthreads();
    }
#pragma unroll
    for (int r = 0; r < 4; r++) {
        float2 v = make_float2(acc[r][0], acc[r][1]);
        *(float2*)&C[(i0 + r) * NDIM + jg + j0] = v;
    }
}

// ---------------------------------------------------------------------------
// Kernel 3: Z(64 x 4096) = A(64 x 4096) @ B^T   (B = Q_S, row-major)
// ---------------------------------------------------------------------------
__global__ __launch_bounds__(256) void gemm_abt_kernel(const float* __restrict__ A,
                                                       const float* __restrict__ B,
                                                       float* __restrict__ C) {
    __shared__ __align__(16) float As[KB][68];
    __shared__ __align__(16) float Bs[KB][36];

    int t  = threadIdx.x;
    int jg = blockIdx.x * BN;
    int i0 = (t & 15) * 4;
    int j0 = (t >> 4) * 2;

    int la_i = t >> 2;
    int la_k = (t & 3) * 8;
    int lb_j = t >> 3;          // 0..31 (column of C = row of B)
    int lb_k = (t & 7) * 4;     // 0..28

    float acc[4][2];
#pragma unroll
    for (int r = 0; r < 4; r++) { acc[r][0] = 0.0f; acc[r][1] = 0.0f; }

    for (int kb = 0; kb < NDIM; kb += KB) {
        float4 a0 = *(const float4*)&A[la_i * NDIM + kb + la_k];
        float4 a1 = *(const float4*)&A[la_i * NDIM + kb + la_k + 4];
        As[la_k + 0][la_i] = a0.x; As[la_k + 1][la_i] = a0.y;
        As[la_k + 2][la_i] = a0.z; As[la_k + 3][la_i] = a0.w;
        As[la_k + 4][la_i] = a1.x; As[la_k + 5][la_i] = a1.y;
        As[la_k + 6][la_i] = a1.z; As[la_k + 7][la_i] = a1.w;
        float4 b = *(const float4*)&B[(size_t)(jg + lb_j) * NDIM + kb + lb_k];
        Bs[lb_k + 0][lb_j] = b.x; Bs[lb_k + 1][lb_j] = b.y;
        Bs[lb_k + 2][lb_j] = b.z; Bs[lb_k + 3][lb_j] = b.w;
        __syncthreads();
#pragma unroll
        for (int k = 0; k < KB; k++) {
            float4 av = *(const float4*)&As[k][i0];
            float2 bv = *(const float2*)&Bs[k][j0];
            acc[0][0] = fmaf(av.x, bv.x, acc[0][0]); acc[0][1] = fmaf(av.x, bv.y, acc[0][1]);
            acc[1][0] = fmaf(av.y, bv.x, acc[1][0]); acc[1][1] = fmaf(av.y, bv.y, acc[1][1]);
            acc[2][0] = fmaf(av.z, bv.x, acc[2][0]); acc[2][1] = fmaf(av.z, bv.y, acc[2][1]);
            acc[3][0] = fmaf(av.w, bv.x, acc[3][0]); acc[3][1] = fmaf(av.w, bv.y, acc[3][1]);
        }
        __syncthreads();
    }
#pragma unroll
    for (int r = 0; r < 4; r++) {
        float2 v = make_float2(acc[r][0], acc[r][1]);
        *(float2*)&C[(i0 + r) * NDIM + jg + j0] = v;
    }
}

// ---------------------------------------------------------------------------
// Kernel 4: Chebyshev application of (I - a_j G)^{-1} per column.
// Z~[:,j] = sum_{k=0}^{KCHEB-1} c_k(a_j) T_k(G~) Y[:,j],  G~ = 2G - I.
// c_k(a) = (2/|a|) * (2q/(1-q^2)) * eps_k * (sgn(a) q)^k,
//   b = 2/a - 1, q = 1/(|b| + sqrt(b^2-1)), eps_0=1, eps_k=2.
// ---------------------------------------------------------------------------
__global__ __launch_bounds__(256) void cheb_kernel(const float* __restrict__ lamS,
                                                   const float* __restrict__ gammap,
                                                   float* __restrict__ Zt) {
    __shared__ __align__(16) float Gs[MDIM][68];
    __shared__ __align__(16) float Ta[MDIM][36];
    __shared__ __align__(16) float Tb[MDIM][36];
    __shared__ float sh_base[BN];
    __shared__ float sh_r[BN];

    int t  = threadIdx.x;
    int jg = blockIdx.x * BN;

    for (int o = t; o < MDIM * MDIM; o += 256)
        Gs[o >> 6][o & 63] = g_Gt[o];
    {
        int i  = t >> 2;
        int c8 = (t & 3) * 8;
        float4 y0 = *(const float4*)&g_Y[i * NDIM + jg + c8];
        float4 y1 = *(const float4*)&g_Y[i * NDIM + jg + c8 + 4];
        *(float4*)&Ta[i][c8]     = y0;
        *(float4*)&Ta[i][c8 + 4] = y1;
    }
    if (t < BN) {
        float gam = gammap[0];
        float a = gam * lamS[jg + t];
        float base, r;
        if (fabsf(a) < 1e-7f) {
            base = 1.0f; r = 0.0f;
        } else {
            float b  = 2.0f / a - 1.0f;
            float ab = fabsf(b);
            float s  = sqrtf(fmaf(ab, ab, -1.0f));
            float q  = 1.0f / (ab + s);
            float sg = (a > 0.0f) ? 1.0f : -1.0f;
            r    = sg * q;
            base = (2.0f / a) * sg * 2.0f * q / (1.0f - q * q);
        }
        sh_base[t] = base;
        sh_r[t]    = r;
    }
    __syncthreads();

    int i0 = (t & 15) * 4;
    int j0 = (t >> 4) * 2;

    float base0 = sh_base[j0],     r0 = sh_r[j0];
    float base1 = sh_base[j0 + 1], r1 = sh_r[j0 + 1];
    // c_0 = base; for k>=1: c_k = 2*base*r^k  (track p = 2*base*r^k)
    float p0 = 2.0f * base0 * r0;
    float p1 = 2.0f * base1 * r1;

    float acc[4][2], tp[4][2], tc[4][2], u[4][2];

    // k = 0: T0 = Y
#pragma unroll
    for (int rI = 0; rI < 4; rI++) {
        float y0 = Ta[i0 + rI][j0];
        float y1 = Ta[i0 + rI][j0 + 1];
        acc[rI][0] = base0 * y0;
        acc[rI][1] = base1 * y1;
        tp[rI][0] = y0; tp[rI][1] = y1;   // T0 own elements
    }

    // k = 1: T1 = G~ @ T0, read Ta, write Tb
#pragma unroll
    for (int rI = 0; rI < 4; rI++) { u[rI][0] = 0.0f; u[rI][1] = 0.0f; }
#pragma unroll 8
    for (int k = 0; k < MDIM; k++) {
        float4 gv = *(const float4*)&Gs[k][i0];
        float2 tv = *(const float2*)&Ta[k][j0];
        u[0][0] = fmaf(gv.x, tv.x, u[0][0]); u[0][1] = fmaf(gv.x, tv.y, u[0][1]);
        u[1][0] = fmaf(gv.y, tv.x, u[1][0]); u[1][1] = fmaf(gv.y, tv.y, u[1][1]);
        u[2][0] = fmaf(gv.z, tv.x, u[2][0]); u[2][1] = fmaf(gv.z, tv.y, u[2][1]);
        u[3][0] = fmaf(gv.w, tv.x, u[3][0]); u[3][1] = fmaf(gv.w, tv.y, u[3][1]);
    }
#pragma unroll
    for (int rI = 0; rI < 4; rI++) {
        acc[rI][0] = fmaf(p0, u[rI][0], acc[rI][0]);
        acc[rI][1] = fmaf(p1, u[rI][1], acc[rI][1]);
        tc[rI][0] = u[rI][0]; tc[rI][1] = u[rI][1];
        Tb[i0 + rI][j0]     = u[rI][0];
        Tb[i0 + rI][j0 + 1] = u[rI][1];
    }
    __syncthreads();

    // k = 2 .. KCHEB-1: T_{k+1} = 2 G~ T_k - T_{k-1}
    int cur = 1;  // 1 => current in Tb, 0 => current in Ta
    for (int kk = 2; kk < KCHEB; kk++) {
        p0 *= r0; p1 *= r1;
#pragma unroll
        for (int rI = 0; rI < 4; rI++) { u[rI][0] = 0.0f; u[rI][1] = 0.0f; }
        if (cur == 1) {
#pragma unroll 8
            for (int k = 0; k < MDIM; k++) {
                float4 gv = *(const float4*)&Gs[k][i0];
                float2 tv = *(const float2*)&Tb[k][j0];
                u[0][0] = fmaf(gv.x, tv.x, u[0][0]); u[0][1] = fmaf(gv.x, tv.y, u[0][1]);
                u[1][0] = fmaf(gv.y, tv.x, u[1][0]); u[1][1] = fmaf(gv.y, tv.y, u[1][1]);
                u[2][0] = fmaf(gv.z, tv.x, u[2][0]); u[2][1] = fmaf(gv.z, tv.y, u[2][1]);
                u[3][0] = fmaf(gv.w, tv.x, u[3][0]); u[3][1] = fmaf(gv.w, tv.y, u[3][1]);
            }
        } else {
#pragma unroll 8
            for (int k = 0; k < MDIM; k++) {
                float4 gv = *(const float4*)&Gs[k][i0];
                float2 tv = *(const float2*)&Ta[k][j0];
                u[0][0] = fmaf(gv.x, tv.x, u[0][0]); u[0][1] = fmaf(gv.x, tv.y, u[0][1]);
                u[1][0] = fmaf(gv.y, tv.x, u[1][0]); u[1][1] = fmaf(gv.y, tv.y, u[1][1]);
                u[2][0] = fmaf(gv.z, tv.x, u[2][0]); u[2][1] = fmaf(gv.z, tv.y, u[2][1]);
                u[3][0] = fmaf(gv.w, tv.x, u[3][0]); u[3][1] = fmaf(gv.w, tv.y, u[3][1]);
            }
        }
        // tn = 2u - tp; accumulate; rotate own-element state; write to other buffer
#pragma unroll
        for (int rI = 0; rI < 4; rI++) {
            float tn0 = fmaf(2.0f, u[rI][0], -tp[rI][0]);
            float tn1 = fmaf(2.0f, u[rI][1], -tp[rI][1]);
            acc[rI][0] = fmaf(p0, tn0, acc[rI][0]);
            acc[rI][1] = fmaf(p1, tn1, acc[rI][1]);
            tp[rI][0] = tc[rI][0]; tp[rI][1] = tc[rI][1];
            tc[rI][0] = tn0;       tc[rI][1] = tn1;
            if (cur == 1) { Ta[i0 + rI][j0] = tn0; Ta[i0 + rI][j0 + 1] = tn1; }
            else          { Tb[i0 + rI][j0] = tn0; Tb[i0 + rI][j0 + 1] = tn1; }
        }
        cur ^= 1;
        __syncthreads();
    }

#pragma unroll
    for (int rI = 0; rI < 4; rI++) {
        float2 v = make_float2(acc[rI][0], acc[rI][1]);
        *(float2*)&Zt[(i0 + rI) * NDIM + jg + j0] = v;
    }
}

// ---------------------------------------------------------------------------
extern "C" void kernel_launch(void* const* d_in, const int* in_sizes, int n_in,
                              void* d_out, int out_size) {
    const float* X    = (const float*)d_in[0];   // (64, 4096)
    const float* F    = (const float*)d_in[1];   // (64, 64)
    const float* Q_S  = (const float*)d_in[2];   // (4096, 4096)
    const float* lamS = (const float*)d_in[3];   // (4096,)
    const float* gam  = (const float*)d_in[4];   // scalar
    float* Z = (float*)d_out;                    // (64, 4096)

    float *Gt, *Y, *Zt;
    cudaGetSymbolAddress((void**)&Gt, g_Gt);
    cudaGetSymbolAddress((void**)&Y,  g_Y);
    cudaGetSymbolAddress((void**)&Zt, g_Zt);

    prep_kernel<<<1, 256>>>(F);
    gemm_ab_kernel<<<NDIM / BN, 256>>>(X, Q_S, Y);
    cheb_kernel<<<NDIM / BN, 256>>>(lamS, gam, Zt);
    gemm_abt_kernel<<<NDIM / BN, 256>>>(Zt, Q_S, Z);
}

// round 3
// speedup vs baseline: 1.8755x; 1.8755x over previous
#include <cuda_runtime.h>
#include <cuda_bf16.h>
#include <cstdint>
#include <math.h>

#define MDIM 64
#define NDIM 4096
#define BN   32
#define KB   64
#define KCHEB 14
#define ASTR 72   // bf16 stride for A tiles (144B rows -> conflict-free ldmatrix)
#define BSTR 40   // bf16 stride for B tiles (80B rows  -> conflict-free ldmatrix)

// Scratch (allocation-free rule: __device__ globals)
__device__ float g_Gt[MDIM * MDIM];    // G~ = 2*G - I (symmetric)
__device__ float g_Y [MDIM * NDIM];    // Y = X @ Q_S
__device__ float g_Zt[MDIM * NDIM];    // Z~ = f(G) applied per column

// ---------------------------------------------------------------------------
// PTX helpers: ldmatrix + bf16 mma (legacy tensor path, sm_80+)
// ---------------------------------------------------------------------------
__device__ __forceinline__ uint32_t sptr(const void* p) {
    return (uint32_t)__cvta_generic_to_shared(p);
}
__device__ __forceinline__ void ldsm4(uint32_t r[4], uint32_t addr) {
    asm volatile("ldmatrix.sync.aligned.m8n8.x4.shared.b16 {%0,%1,%2,%3}, [%4];"
                 : "=r"(r[0]), "=r"(r[1]), "=r"(r[2]), "=r"(r[3]) : "r"(addr));
}
__device__ __forceinline__ void ldsm2t(uint32_t r[2], uint32_t addr) {
    asm volatile("ldmatrix.sync.aligned.m8n8.x2.trans.shared.b16 {%0,%1}, [%2];"
                 : "=r"(r[0]), "=r"(r[1]) : "r"(addr));
}
__device__ __forceinline__ void mma16816(float d[4], const uint32_t a[4], const uint32_t b[2]) {
    asm volatile("mma.sync.aligned.m16n8k16.row.col.f32.bf16.bf16.f32 "
                 "{%0,%1,%2,%3}, {%4,%5,%6,%7}, {%8,%9}, {%0,%1,%2,%3};"
                 : "+f"(d[0]), "+f"(d[1]), "+f"(d[2]), "+f"(d[3])
                 : "r"(a[0]), "r"(a[1]), "r"(a[2]), "r"(a[3]),
                   "r"(b[0]), "r"(b[1]));
}
__device__ __forceinline__ void bf16split(float x, __nv_bfloat16& h, __nv_bfloat16& l) {
    h = __float2bfloat16(x);
    l = __float2bfloat16(x - __bfloat162float(h));
}

// ---------------------------------------------------------------------------
// Kernel 1: G~ = 2 * (F^T F) / (||F^T F||_F + 1e-12) - I
// ---------------------------------------------------------------------------
__global__ __launch_bounds__(256) void prep_kernel(const float* __restrict__ F) {
    __shared__ float Fs[MDIM][MDIM + 1];
    __shared__ float FFs[MDIM][MDIM + 4];
    __shared__ float red[8];
    __shared__ float s_inv;

    int t = threadIdx.x;
    for (int o = t; o < MDIM * MDIM; o += 256)
        Fs[o >> 6][o & 63] = F[o];
    __syncthreads();

    int i  = t >> 2;
    int j0 = (t & 3) * 16;
    float acc[16];
#pragma unroll
    for (int u = 0; u < 16; u++) acc[u] = 0.0f;
    for (int k = 0; k < MDIM; k++) {
        float a = Fs[k][i];
#pragma unroll
        for (int u = 0; u < 16; u++) acc[u] = fmaf(a, Fs[k][j0 + u], acc[u]);
    }
    float ss = 0.0f;
#pragma unroll
    for (int u = 0; u < 16; u++) {
        FFs[i][j0 + u] = acc[u];
        ss = fmaf(acc[u], acc[u], ss);
    }
#pragma unroll
    for (int off = 16; off > 0; off >>= 1)
        ss += __shfl_xor_sync(0xffffffffu, ss, off);
    if ((t & 31) == 0) red[t >> 5] = ss;
    __syncthreads();
    if (t == 0) {
        float tot = 0.0f;
        for (int w = 0; w < 8; w++) tot += red[w];
        s_inv = 2.0f / (sqrtf(tot) + 1e-12f);
    }
    __syncthreads();
    float inv = s_inv;
#pragma unroll
    for (int u = 0; u < 16; u++) {
        int j = j0 + u;
        g_Gt[i * MDIM + j] = FFs[i][j] * inv - (i == j ? 1.0f : 0.0f);
    }
}

// ---------------------------------------------------------------------------
// Tensor-core GEMM: C(64 x 4096) = A(64 x 4096) @ B or B^T  (fp32 in/out,
// bf16 hi/lo 3-term split on tensor cores, fp32 accumulate).
// TRANSB = 0: B is (K x N) row-major (C = A B)
// TRANSB = 1: B is (N x K) row-major (C = A B^T)
// ---------------------------------------------------------------------------
template <int TRANSB>
__global__ __launch_bounds__(256) void gemm_tc(const float* __restrict__ A,
                                               const float* __restrict__ B,
                                               float* __restrict__ C) {
    __shared__ __align__(16) __nv_bfloat16 Ah[MDIM][ASTR];
    __shared__ __align__(16) __nv_bfloat16 Al[MDIM][ASTR];
    __shared__ __align__(16) __nv_bfloat16 Bh[KB][BSTR];
    __shared__ __align__(16) __nv_bfloat16 Bl[KB][BSTR];

    const int t    = threadIdx.x;
    const int jg   = blockIdx.x * BN;
    const int lane = t & 31;
    const int warp = t >> 5;
    const int mw   = (warp & 3) * 16;   // warp M offset
    const int nw   = (warp >> 2) * 16;  // warp N offset

    // A staging indices: thread -> (row am, 16 consecutive k at ak)
    const int am = t >> 2;
    const int ak = (t & 3) * 16;
    // B staging indices
    int bk, bn;
    if (TRANSB) { bn = t >> 3; bk = (t & 7) * 8; }   // 8 k for one n
    else        { bk = t >> 2; bn = (t & 3) * 8; }   // 8 n for one k

    float ra[16];
    float rb[8];

    // prefetch chunk 0
    {
        const float* Ap = A + am * NDIM;
#pragma unroll
        for (int q = 0; q < 4; q++)
            *(float4*)&ra[4 * q] = *(const float4*)(Ap + ak + 4 * q);
        const float* Bp = TRANSB ? (B + (size_t)(jg + bn) * NDIM + bk)
                                 : (B + (size_t)bk * NDIM + jg + bn);
        *(float4*)&rb[0] = *(const float4*)(Bp);
        *(float4*)&rb[4] = *(const float4*)(Bp + 4);
    }

    float acc[2][4];
#pragma unroll
    for (int nt = 0; nt < 2; nt++)
#pragma unroll
        for (int u = 0; u < 4; u++) acc[nt][u] = 0.0f;

    for (int kb = 0; kb < NDIM; kb += KB) {
        // convert + store staged registers to smem
#pragma unroll
        for (int i = 0; i < 8; i++) {
            __nv_bfloat16 h0, h1, l0, l1;
            bf16split(ra[2 * i], h0, l0);
            bf16split(ra[2 * i + 1], h1, l1);
            __nv_bfloat162 ph; ph.x = h0; ph.y = h1;
            __nv_bfloat162 pl; pl.x = l0; pl.y = l1;
            *(__nv_bfloat162*)&Ah[am][ak + 2 * i] = ph;
            *(__nv_bfloat162*)&Al[am][ak + 2 * i] = pl;
        }
        if (TRANSB) {
#pragma unroll
            for (int i = 0; i < 8; i++) {
                __nv_bfloat16 h, l;
                bf16split(rb[i], h, l);
                Bh[bk + i][bn] = h;
                Bl[bk + i][bn] = l;
            }
        } else {
#pragma unroll
            for (int i = 0; i < 4; i++) {
                __nv_bfloat16 h0, h1, l0, l1;
                bf16split(rb[2 * i], h0, l0);
                bf16split(rb[2 * i + 1], h1, l1);
                __nv_bfloat162 ph; ph.x = h0; ph.y = h1;
                __nv_bfloat162 pl; pl.x = l0; pl.y = l1;
                *(__nv_bfloat162*)&Bh[bk][bn + 2 * i] = ph;
                *(__nv_bfloat162*)&Bl[bk][bn + 2 * i] = pl;
            }
        }
        __syncthreads();

        // prefetch next chunk (latency hidden behind mma below)
        if (kb + KB < NDIM) {
            const float* Ap = A + am * NDIM + kb + KB;
#pragma unroll
            for (int q = 0; q < 4; q++)
                *(float4*)&ra[4 * q] = *(const float4*)(Ap + ak + 4 * q);
            const float* Bp = TRANSB ? (B + (size_t)(jg + bn) * NDIM + kb + KB + bk)
                                     : (B + (size_t)(kb + KB + bk) * NDIM + jg + bn);
            *(float4*)&rb[0] = *(const float4*)(Bp);
            *(float4*)&rb[4] = *(const float4*)(Bp + 4);
        }

        // tensor-core inner loop over 4 k16 steps
        const int lr = lane & 15;
        const int lc = (lane >> 4) * 8;
#pragma unroll
        for (int ks = 0; ks < 4; ks++) {
            uint32_t ah[4], al[4];
            ldsm4(ah, sptr(&Ah[mw + lr][ks * 16 + lc]));
            ldsm4(al, sptr(&Al[mw + lr][ks * 16 + lc]));
#pragma unroll
            for (int nt = 0; nt < 2; nt++) {
                uint32_t bh[2], bl[2];
                const int br = ks * 16 + lr;
                ldsm2t(bh, sptr(&Bh[br][nw + nt * 8]));
                ldsm2t(bl, sptr(&Bl[br][nw + nt * 8]));
                mma16816(acc[nt], ah, bh);  // hi*hi
                mma16816(acc[nt], ah, bl);  // hi*lo
                mma16816(acc[nt], al, bh);  // lo*hi
            }
        }
        __syncthreads();
    }

    // epilogue: fragment -> fp32 global
    const int row = mw + (lane >> 2);
    const int col = jg + nw + (lane & 3) * 2;
#pragma unroll
    for (int nt = 0; nt < 2; nt++) {
        *(float2*)&C[(size_t)row * NDIM + col + nt * 8] =
            make_float2(acc[nt][0], acc[nt][1]);
        *(float2*)&C[(size_t)(row + 8) * NDIM + col + nt * 8] =
            make_float2(acc[nt][2], acc[nt][3]);
    }
}

// ---------------------------------------------------------------------------
// Kernel: Chebyshev application of (I - a_j G)^{-1} per column.
// Z~[:,j] = sum_{k=0}^{KCHEB-1} c_k(a_j) T_k(G~) Y[:,j],  G~ = 2G - I.
// ---------------------------------------------------------------------------
__global__ __launch_bounds__(256) void cheb_kernel(const float* __restrict__ lamS,
                                                   const float* __restrict__ gammap,
                                                   float* __restrict__ Zt) {
    __shared__ __align__(16) float Gs[MDIM][68];
    __shared__ __align__(16) float Ta[MDIM][36];
    __shared__ __align__(16) float Tb[MDIM][36];
    __shared__ float sh_base[BN];
    __shared__ float sh_r[BN];

    int t  = threadIdx.x;
    int jg = blockIdx.x * BN;

    for (int o = t; o < MDIM * MDIM; o += 256)
        Gs[o >> 6][o & 63] = g_Gt[o];
    {
        int i  = t >> 2;
        int c8 = (t & 3) * 8;
        float4 y0 = *(const float4*)&g_Y[i * NDIM + jg + c8];
        float4 y1 = *(const float4*)&g_Y[i * NDIM + jg + c8 + 4];
        *(float4*)&Ta[i][c8]     = y0;
        *(float4*)&Ta[i][c8 + 4] = y1;
    }
    if (t < BN) {
        float gam = gammap[0];
        float a = gam * lamS[jg + t];
        float base, r;
        if (fabsf(a) < 1e-7f) {
            base = 1.0f; r = 0.0f;
        } else {
            float b  = 2.0f / a - 1.0f;
            float ab = fabsf(b);
            float s  = sqrtf(fmaf(ab, ab, -1.0f));
            float q  = 1.0f / (ab + s);
            float sg = (a > 0.0f) ? 1.0f : -1.0f;
            r    = sg * q;
            base = (2.0f / a) * sg * 2.0f * q / (1.0f - q * q);
        }
        sh_base[t] = base;
        sh_r[t]    = r;
    }
    __syncthreads();

    int i0 = (t & 15) * 4;
    int j0 = (t >> 4) * 2;

    float base0 = sh_base[j0],     r0 = sh_r[j0];
    float base1 = sh_base[j0 + 1], r1 = sh_r[j0 + 1];
    float p0 = 2.0f * base0 * r0;
    float p1 = 2.0f * base1 * r1;

    float acc[4][2], tp[4][2], tc[4][2], u[4][2];

#pragma unroll
    for (int rI = 0; rI < 4; rI++) {
        float y0 = Ta[i0 + rI][j0];
        float y1 = Ta[i0 + rI][j0 + 1];
        acc[rI][0] = base0 * y0;
        acc[rI][1] = base1 * y1;
        tp[rI][0] = y0; tp[rI][1] = y1;
    }

#pragma unroll
    for (int rI = 0; rI < 4; rI++) { u[rI][0] = 0.0f; u[rI][1] = 0.0f; }
#pragma unroll 8
    for (int k = 0; k < MDIM; k++) {
        float4 gv = *(const float4*)&Gs[k][i0];
        float2 tv = *(const float2*)&Ta[k][j0];
        u[0][0] = fmaf(gv.x, tv.x, u[0][0]); u[0][1] = fmaf(gv.x, tv.y, u[0][1]);
        u[1][0] = fmaf(gv.y, tv.x, u[1][0]); u[1][1] = fmaf(gv.y, tv.y, u[1][1]);
        u[2][0] = fmaf(gv.z, tv.x, u[2][0]); u[2][1] = fmaf(gv.z, tv.y, u[2][1]);
        u[3][0] = fmaf(gv.w, tv.x, u[3][0]); u[3][1] = fmaf(gv.w, tv.y, u[3][1]);
    }
#pragma unroll
    for (int rI = 0; rI < 4; rI++) {
        acc[rI][0] = fmaf(p0, u[rI][0], acc[rI][0]);
        acc[rI][1] = fmaf(p1, u[rI][1], acc[rI][1]);
        tc[rI][0] = u[rI][0]; tc[rI][1] = u[rI][1];
        Tb[i0 + rI][j0]     = u[rI][0];
        Tb[i0 + rI][j0 + 1] = u[rI][1];
    }
    __syncthreads();

    int cur = 1;
    for (int kk = 2; kk < KCHEB; kk++) {
        p0 *= r0; p1 *= r1;
#pragma unroll
        for (int rI = 0; rI < 4; rI++) { u[rI][0] = 0.0f; u[rI][1] = 0.0f; }
        if (cur == 1) {
#pragma unroll 8
            for (int k = 0; k < MDIM; k++) {
                float4 gv = *(const float4*)&Gs[k][i0];
                float2 tv = *(const float2*)&Tb[k][j0];
                u[0][0] = fmaf(gv.x, tv.x, u[0][0]); u[0][1] = fmaf(gv.x, tv.y, u[0][1]);
                u[1][0] = fmaf(gv.y, tv.x, u[1][0]); u[1][1] = fmaf(gv.y, tv.y, u[1][1]);
                u[2][0] = fmaf(gv.z, tv.x, u[2][0]); u[2][1] = fmaf(gv.z, tv.y, u[2][1]);
                u[3][0] = fmaf(gv.w, tv.x, u[3][0]); u[3][1] = fmaf(gv.w, tv.y, u[3][1]);
            }
        } else {
#pragma unroll 8
            for (int k = 0; k < MDIM; k++) {
                float4 gv = *(const float4*)&Gs[k][i0];
                float2 tv = *(const float2*)&Ta[k][j0];
                u[0][0] = fmaf(gv.x, tv.x, u[0][0]); u[0][1] = fmaf(gv.x, tv.y, u[0][1]);
                u[1][0] = fmaf(gv.y, tv.x, u[1][0]); u[1][1] = fmaf(gv.y, tv.y, u[1][1]);
                u[2][0] = fmaf(gv.z, tv.x, u[2][0]); u[2][1] = fmaf(gv.z, tv.y, u[2][1]);
                u[3][0] = fmaf(gv.w, tv.x, u[3][0]); u[3][1] = fmaf(gv.w, tv.y, u[3][1]);
            }
        }
#pragma unroll
        for (int rI = 0; rI < 4; rI++) {
            float tn0 = fmaf(2.0f, u[rI][0], -tp[rI][0]);
            float tn1 = fmaf(2.0f, u[rI][1], -tp[rI][1]);
            acc[rI][0] = fmaf(p0, tn0, acc[rI][0]);
            acc[rI][1] = fmaf(p1, tn1, acc[rI][1]);
            tp[rI][0] = tc[rI][0]; tp[rI][1] = tc[rI][1];
            tc[rI][0] = tn0;       tc[rI][1] = tn1;
            if (cur == 1) { Ta[i0 + rI][j0] = tn0; Ta[i0 + rI][j0 + 1] = tn1; }
            else          { Tb[i0 + rI][j0] = tn0; Tb[i0 + rI][j0 + 1] = tn1; }
        }
        cur ^= 1;
        __syncthreads();
    }

#pragma unroll
    for (int rI = 0; rI < 4; rI++) {
        float2 v = make_float2(acc[rI][0], acc[rI][1]);
        *(float2*)&Zt[(i0 + rI) * NDIM + jg + j0] = v;
    }
}

// ---------------------------------------------------------------------------
extern "C" void kernel_launch(void* const* d_in, const int* in_sizes, int n_in,
                              void* d_out, int out_size) {
    const float* X    = (const float*)d_in[0];   // (64, 4096)
    const float* F    = (const float*)d_in[1];   // (64, 64)
    const float* Q_S  = (const float*)d_in[2];   // (4096, 4096)
    const float* lamS = (const float*)d_in[3];   // (4096,)
    const float* gam  = (const float*)d_in[4];   // scalar
    float* Z = (float*)d_out;                    // (64, 4096)

    float *Y, *Zt;
    cudaGetSymbolAddress((void**)&Y,  g_Y);
    cudaGetSymbolAddress((void**)&Zt, g_Zt);

    prep_kernel<<<1, 256>>>(F);
    gemm_tc<0><<<NDIM / BN, 256>>>(X, Q_S, Y);      // Y = X @ Q_S
    cheb_kernel<<<NDIM / BN, 256>>>(lamS, gam, Zt); // Zt = f(G) Y
    gemm_tc<1><<<NDIM / BN, 256>>>(Zt, Q_S, Z);     // Z = Zt @ Q_S^T
}

// round 4
// speedup vs baseline: 2.0981x; 1.1187x over previous
#include <cuda_runtime.h>
#include <cuda_bf16.h>
#include <cstdint>
#include <math.h>

#define MDIM 64
#define NDIM 4096
#define BN   32
#define KB   32
#define NST  4
#define KSPL 2048
#define NCH  (KSPL / KB)   // 64 chunks per K-split
#define KCHEB 14

#define AF_STRIDE 36
#define BF_STRIDE 36
#define AH_STRIDE 40
#define BH_STRIDE 40

#define SMEM_BYTES (NST*64*AF_STRIDE*4 + NST*32*BF_STRIDE*4 + (64*AH_STRIDE + 64*AH_STRIDE + 32*BH_STRIDE + 32*BH_STRIDE)*2)

// Scratch (allocation-free rule: __device__ globals)
__device__ float g_Gt[MDIM * MDIM];    // G~ = 2*G - I (symmetric)
__device__ float g_Y [MDIM * NDIM];    // Y = X @ Q_S  (accumulated by K-split atomics)
__device__ float g_Zt[MDIM * NDIM];    // Z~ = f(G) Y

// ---------------------------------------------------------------------------
// PTX helpers
// ---------------------------------------------------------------------------
__device__ __forceinline__ uint32_t sptr(const void* p) {
    return (uint32_t)__cvta_generic_to_shared(p);
}
__device__ __forceinline__ void ldsm4(uint32_t r[4], uint32_t addr) {
    asm volatile("ldmatrix.sync.aligned.m8n8.x4.shared.b16 {%0,%1,%2,%3}, [%4];"
                 : "=r"(r[0]), "=r"(r[1]), "=r"(r[2]), "=r"(r[3]) : "r"(addr));
}
__device__ __forceinline__ void ldsm4t(uint32_t r[4], uint32_t addr) {
    asm volatile("ldmatrix.sync.aligned.m8n8.x4.trans.shared.b16 {%0,%1,%2,%3}, [%4];"
                 : "=r"(r[0]), "=r"(r[1]), "=r"(r[2]), "=r"(r[3]) : "r"(addr));
}
__device__ __forceinline__ void mma16816(float d[4], const uint32_t a[4], const uint32_t b[2]) {
    asm volatile("mma.sync.aligned.m16n8k16.row.col.f32.bf16.bf16.f32 "
                 "{%0,%1,%2,%3}, {%4,%5,%6,%7}, {%8,%9}, {%0,%1,%2,%3};"
                 : "+f"(d[0]), "+f"(d[1]), "+f"(d[2]), "+f"(d[3])
                 : "r"(a[0]), "r"(a[1]), "r"(a[2]), "r"(a[3]),
                   "r"(b[0]), "r"(b[1]));
}
__device__ __forceinline__ void cpa16(uint32_t dst, const void* src) {
    asm volatile("cp.async.cg.shared.global [%0], [%1], 16;" :: "r"(dst), "l"(src));
}
__device__ __forceinline__ void cpcommit() {
    asm volatile("cp.async.commit_group;");
}
__device__ __forceinline__ void cpwait() {
    asm volatile("cp.async.wait_group %0;" :: "n"(NST - 1));
}
__device__ __forceinline__ void bf16split(float x, __nv_bfloat16& h, __nv_bfloat16& l) {
    h = __float2bfloat16(x);
    l = __float2bfloat16(x - __bfloat162float(h));
}

// ---------------------------------------------------------------------------
// Zero-init (required each replay: outputs are accumulated via atomicAdd)
// ---------------------------------------------------------------------------
__global__ __launch_bounds__(256) void zero_kernel(float* __restrict__ a,
                                                   float* __restrict__ b) {
    int i = blockIdx.x * 256 + threadIdx.x;
    a[i] = 0.0f;
    b[i] = 0.0f;
}

// ---------------------------------------------------------------------------
// Kernel 1: G~ = 2 * (F^T F) / (||F^T F||_F + 1e-12) - I
// ---------------------------------------------------------------------------
__global__ __launch_bounds__(256) void prep_kernel(const float* __restrict__ F) {
    __shared__ float Fs[MDIM][MDIM + 1];
    __shared__ float FFs[MDIM][MDIM + 4];
    __shared__ float red[8];
    __shared__ float s_inv;

    int t = threadIdx.x;
    for (int o = t; o < MDIM * MDIM; o += 256)
        Fs[o >> 6][o & 63] = F[o];
    __syncthreads();

    int i  = t >> 2;
    int j0 = (t & 3) * 16;
    float acc[16];
#pragma unroll
    for (int u = 0; u < 16; u++) acc[u] = 0.0f;
    for (int k = 0; k < MDIM; k++) {
        float a = Fs[k][i];
#pragma unroll
        for (int u = 0; u < 16; u++) acc[u] = fmaf(a, Fs[k][j0 + u], acc[u]);
    }
    float ss = 0.0f;
#pragma unroll
    for (int u = 0; u < 16; u++) {
        FFs[i][j0 + u] = acc[u];
        ss = fmaf(acc[u], acc[u], ss);
    }
#pragma unroll
    for (int off = 16; off > 0; off >>= 1)
        ss += __shfl_xor_sync(0xffffffffu, ss, off);
    if ((t & 31) == 0) red[t >> 5] = ss;
    __syncthreads();
    if (t == 0) {
        float tot = 0.0f;
        for (int w = 0; w < 8; w++) tot += red[w];
        s_inv = 2.0f / (sqrtf(tot) + 1e-12f);
    }
    __syncthreads();
    float inv = s_inv;
#pragma unroll
    for (int u = 0; u < 16; u++) {
        int j = j0 + u;
        g_Gt[i * MDIM + j] = FFs[i][j] * inv - (i == j ? 1.0f : 0.0f);
    }
}

// ---------------------------------------------------------------------------
// cp.async stage fill for one KB-chunk
// ---------------------------------------------------------------------------
template <int TRANSB>
__device__ __forceinline__ void issue_chunk(float* Af, float* Bf,
                                            const float* __restrict__ A,
                                            const float* __restrict__ B,
                                            int stage, int kbase, int jg, int t) {
    float* As = Af + stage * (64 * AF_STRIDE);
#pragma unroll
    for (int h = 0; h < 2; h++) {
        int q = t + h * 256;
        int row = q >> 3;
        int cf  = (q & 7) * 4;
        cpa16(sptr(As + row * AF_STRIDE + cf), A + (size_t)row * NDIM + kbase + cf);
    }
    float* Bs = Bf + stage * (32 * BF_STRIDE);
    int row = t >> 3;
    int cf  = (t & 7) * 4;
    const float* src = TRANSB ? (B + (size_t)(jg + row) * NDIM + kbase + cf)
                              : (B + (size_t)(kbase + row) * NDIM + jg + cf);
    cpa16(sptr(Bs + row * BF_STRIDE + cf), src);
}

// ---------------------------------------------------------------------------
// Tensor-core GEMM, K-split x2, cp.async 4-stage pipeline, atomicAdd epilogue.
// C(64 x 4096) += A(64 x Kslice) @ B-slice (bf16 hi/lo 3-term split).
// ---------------------------------------------------------------------------
template <int TRANSB>
__global__ __launch_bounds__(256) void gemm_tc(const float* __restrict__ A,
                                               const float* __restrict__ B,
                                               float* __restrict__ C) {
    extern __shared__ __align__(16) char smem[];
    float* Af = (float*)smem;                             // NST*64*AF_STRIDE
    float* Bf = Af + NST * 64 * AF_STRIDE;                // NST*32*BF_STRIDE
    __nv_bfloat16* Ah = (__nv_bfloat16*)(Bf + NST * 32 * BF_STRIDE);
    __nv_bfloat16* Al = Ah + 64 * AH_STRIDE;
    __nv_bfloat16* Bh = Al + 64 * AH_STRIDE;
    __nv_bfloat16* Bl = Bh + 32 * BH_STRIDE;

    const int t    = threadIdx.x;
    const int lane = t & 31;
    const int warp = t >> 5;
    const int jg   = blockIdx.x * BN;
    const int k0g  = blockIdx.y * KSPL;
    const int mw   = (warp & 3) * 16;
    const int nw   = (warp >> 2) * 16;

    float acc[2][4];
#pragma unroll
    for (int nt = 0; nt < 2; nt++)
#pragma unroll
        for (int u = 0; u < 4; u++) acc[nt][u] = 0.0f;

    // prologue: fill NST-1 stages
#pragma unroll
    for (int c = 0; c < NST - 1; c++) {
        issue_chunk<TRANSB>(Af, Bf, A, B, c, k0g + c * KB, jg, t);
        cpcommit();
    }

    const int lr = lane & 15;
    const int g8 = (lane >> 4) * 8;

    for (int c = 0; c < NCH; c++) {
        int cn = c + NST - 1;
        if (cn < NCH)
            issue_chunk<TRANSB>(Af, Bf, A, B, cn % NST, k0g + cn * KB, jg, t);
        cpcommit();           // always commit (keeps wait_group accounting exact)
        cpwait();             // chunk c's stage is complete
        __syncthreads();

        // convert stage -> bf16 hi/lo tiles
        {
            const float* As = Af + (c % NST) * (64 * AF_STRIDE);
            int m  = t >> 2;
            int kk = (t & 3) * 8;
            float4 v0 = *(const float4*)(As + m * AF_STRIDE + kk);
            float4 v1 = *(const float4*)(As + m * AF_STRIDE + kk + 4);
            float va[8] = {v0.x, v0.y, v0.z, v0.w, v1.x, v1.y, v1.z, v1.w};
#pragma unroll
            for (int i = 0; i < 4; i++) {
                __nv_bfloat16 h0, h1, l0, l1;
                bf16split(va[2 * i], h0, l0);
                bf16split(va[2 * i + 1], h1, l1);
                __nv_bfloat162 ph; ph.x = h0; ph.y = h1;
                __nv_bfloat162 pl; pl.x = l0; pl.y = l1;
                *(__nv_bfloat162*)(Ah + m * AH_STRIDE + kk + 2 * i) = ph;
                *(__nv_bfloat162*)(Al + m * AH_STRIDE + kk + 2 * i) = pl;
            }
            const float* Bs = Bf + (c % NST) * (32 * BF_STRIDE);
            if (TRANSB) {
                int n  = t >> 3;
                int kq = (t & 7) * 4;
                float4 b = *(const float4*)(Bs + n * BF_STRIDE + kq);
                float vb[4] = {b.x, b.y, b.z, b.w};
#pragma unroll
                for (int i = 0; i < 4; i++) {
                    __nv_bfloat16 h, l;
                    bf16split(vb[i], h, l);
                    Bh[(kq + i) * BH_STRIDE + n] = h;
                    Bl[(kq + i) * BH_STRIDE + n] = l;
                }
            } else {
                int kk2 = t >> 3;
                int nq  = (t & 7) * 4;
                float4 b = *(const float4*)(Bs + kk2 * BF_STRIDE + nq);
                float vb[4] = {b.x, b.y, b.z, b.w};
#pragma unroll
                for (int i = 0; i < 2; i++) {
                    __nv_bfloat16 h0, h1, l0, l1;
                    bf16split(vb[2 * i], h0, l0);
                    bf16split(vb[2 * i + 1], h1, l1);
                    __nv_bfloat162 ph; ph.x = h0; ph.y = h1;
                    __nv_bfloat162 pl; pl.x = l0; pl.y = l1;
                    *(__nv_bfloat162*)(Bh + kk2 * BH_STRIDE + nq + 2 * i) = ph;
                    *(__nv_bfloat162*)(Bl + kk2 * BH_STRIDE + nq + 2 * i) = pl;
                }
            }
        }
        __syncthreads();

        // tensor-core inner loop: 2 x k16
#pragma unroll
        for (int ks = 0; ks < 2; ks++) {
            uint32_t ah[4], al[4], bh[4], bl[4];
            ldsm4 (ah, sptr(Ah + (mw + lr) * AH_STRIDE + ks * 16 + g8));
            ldsm4 (al, sptr(Al + (mw + lr) * AH_STRIDE + ks * 16 + g8));
            ldsm4t(bh, sptr(Bh + (ks * 16 + lr) * BH_STRIDE + nw + g8));
            ldsm4t(bl, sptr(Bl + (ks * 16 + lr) * BH_STRIDE + nw + g8));
            mma16816(acc[0], ah, bh);      // hi*hi  (n8 tile 0)
            mma16816(acc[0], ah, bl);      // hi*lo
            mma16816(acc[0], al, bh);      // lo*hi
            mma16816(acc[1], ah, bh + 2);  // n8 tile 1
            mma16816(acc[1], ah, bl + 2);
            mma16816(acc[1], al, bh + 2);
        }
        __syncthreads();
    }

    // epilogue: deterministic for 2 K-split addends onto zeroed C
    const int row = mw + (lane >> 2);
    const int col = jg + nw + (lane & 3) * 2;
#pragma unroll
    for (int nt = 0; nt < 2; nt++) {
        atomicAdd(&C[(size_t)row * NDIM + col + nt * 8],       acc[nt][0]);
        atomicAdd(&C[(size_t)row * NDIM + col + nt * 8 + 1],   acc[nt][1]);
        atomicAdd(&C[(size_t)(row + 8) * NDIM + col + nt * 8],     acc[nt][2]);
        atomicAdd(&C[(size_t)(row + 8) * NDIM + col + nt * 8 + 1], acc[nt][3]);
    }
}

// ---------------------------------------------------------------------------
// Chebyshev application of (I - a_j G)^{-1} per column (unchanged).
// ---------------------------------------------------------------------------
__global__ __launch_bounds__(256) void cheb_kernel(const float* __restrict__ lamS,
                                                   const float* __restrict__ gammap,
                                                   float* __restrict__ Zt) {
    __shared__ __align__(16) float Gs[MDIM][68];
    __shared__ __align__(16) float Ta[MDIM][36];
    __shared__ __align__(16) float Tb[MDIM][36];
    __shared__ float sh_base[BN];
    __shared__ float sh_r[BN];

    int t  = threadIdx.x;
    int jg = blockIdx.x * BN;

    for (int o = t; o < MDIM * MDIM; o += 256)
        Gs[o >> 6][o & 63] = g_Gt[o];
    {
        int i  = t >> 2;
        int c8 = (t & 3) * 8;
        float4 y0 = *(const float4*)&g_Y[i * NDIM + jg + c8];
        float4 y1 = *(const float4*)&g_Y[i * NDIM + jg + c8 + 4];
        *(float4*)&Ta[i][c8]     = y0;
        *(float4*)&Ta[i][c8 + 4] = y1;
    }
    if (t < BN) {
        float gam = gammap[0];
        float a = gam * lamS[jg + t];
        float base, r;
        if (fabsf(a) < 1e-7f) {
            base = 1.0f; r = 0.0f;
        } else {
            float b  = 2.0f / a - 1.0f;
            float ab = fabsf(b);
            float s  = sqrtf(fmaf(ab, ab, -1.0f));
            float q  = 1.0f / (ab + s);
            float sg = (a > 0.0f) ? 1.0f : -1.0f;
            r    = sg * q;
            base = (2.0f / a) * sg * 2.0f * q / (1.0f - q * q);
        }
        sh_base[t] = base;
        sh_r[t]    = r;
    }
    __syncthreads();

    int i0 = (t & 15) * 4;
    int j0 = (t >> 4) * 2;

    float base0 = sh_base[j0],     r0 = sh_r[j0];
    float base1 = sh_base[j0 + 1], r1 = sh_r[j0 + 1];
    float p0 = 2.0f * base0 * r0;
    float p1 = 2.0f * base1 * r1;

    float acc[4][2], tp[4][2], tc[4][2], u[4][2];

#pragma unroll
    for (int rI = 0; rI < 4; rI++) {
        float y0 = Ta[i0 + rI][j0];
        float y1 = Ta[i0 + rI][j0 + 1];
        acc[rI][0] = base0 * y0;
        acc[rI][1] = base1 * y1;
        tp[rI][0] = y0; tp[rI][1] = y1;
    }

#pragma unroll
    for (int rI = 0; rI < 4; rI++) { u[rI][0] = 0.0f; u[rI][1] = 0.0f; }
#pragma unroll 8
    for (int k = 0; k < MDIM; k++) {
        float4 gv = *(const float4*)&Gs[k][i0];
        float2 tv = *(const float2*)&Ta[k][j0];
        u[0][0] = fmaf(gv.x, tv.x, u[0][0]); u[0][1] = fmaf(gv.x, tv.y, u[0][1]);
        u[1][0] = fmaf(gv.y, tv.x, u[1][0]); u[1][1] = fmaf(gv.y, tv.y, u[1][1]);
        u[2][0] = fmaf(gv.z, tv.x, u[2][0]); u[2][1] = fmaf(gv.z, tv.y, u[2][1]);
        u[3][0] = fmaf(gv.w, tv.x, u[3][0]); u[3][1] = fmaf(gv.w, tv.y, u[3][1]);
    }
#pragma unroll
    for (int rI = 0; rI < 4; rI++) {
        acc[rI][0] = fmaf(p0, u[rI][0], acc[rI][0]);
        acc[rI][1] = fmaf(p1, u[rI][1], acc[rI][1]);
        tc[rI][0] = u[rI][0]; tc[rI][1] = u[rI][1];
        Tb[i0 + rI][j0]     = u[rI][0];
        Tb[i0 + rI][j0 + 1] = u[rI][1];
    }
    __syncthreads();

    int cur = 1;
    for (int kk = 2; kk < KCHEB; kk++) {
        p0 *= r0; p1 *= r1;
#pragma unroll
        for (int rI = 0; rI < 4; rI++) { u[rI][0] = 0.0f; u[rI][1] = 0.0f; }
        if (cur == 1) {
#pragma unroll 8
            for (int k = 0; k < MDIM; k++) {
                float4 gv = *(const float4*)&Gs[k][i0];
                float2 tv = *(const float2*)&Tb[k][j0];
                u[0][0] = fmaf(gv.x, tv.x, u[0][0]); u[0][1] = fmaf(gv.x, tv.y, u[0][1]);
                u[1][0] = fmaf(gv.y, tv.x, u[1][0]); u[1][1] = fmaf(gv.y, tv.y, u[1][1]);
                u[2][0] = fmaf(gv.z, tv.x, u[2][0]); u[2][1] = fmaf(gv.z, tv.y, u[2][1]);
                u[3][0] = fmaf(gv.w, tv.x, u[3][0]); u[3][1] = fmaf(gv.w, tv.y, u[3][1]);
            }
        } else {
#pragma unroll 8
            for (int k = 0; k < MDIM; k++) {
                float4 gv = *(const float4*)&Gs[k][i0];
                float2 tv = *(const float2*)&Ta[k][j0];
                u[0][0] = fmaf(gv.x, tv.x, u[0][0]); u[0][1] = fmaf(gv.x, tv.y, u[0][1]);
                u[1][0] = fmaf(gv.y, tv.x, u[1][0]); u[1][1] = fmaf(gv.y, tv.y, u[1][1]);
                u[2][0] = fmaf(gv.z, tv.x, u[2][0]); u[2][1] = fmaf(gv.z, tv.y, u[2][1]);
                u[3][0] = fmaf(gv.w, tv.x, u[3][0]); u[3][1] = fmaf(gv.w, tv.y, u[3][1]);
            }
        }
#pragma unroll
        for (int rI = 0; rI < 4; rI++) {
            float tn0 = fmaf(2.0f, u[rI][0], -tp[rI][0]);
            float tn1 = fmaf(2.0f, u[rI][1], -tp[rI][1]);
            acc[rI][0] = fmaf(p0, tn0, acc[rI][0]);
            acc[rI][1] = fmaf(p1, tn1, acc[rI][1]);
            tp[rI][0] = tc[rI][0]; tp[rI][1] = tc[rI][1];
            tc[rI][0] = tn0;       tc[rI][1] = tn1;
            if (cur == 1) { Ta[i0 + rI][j0] = tn0; Ta[i0 + rI][j0 + 1] = tn1; }
            else          { Tb[i0 + rI][j0] = tn0; Tb[i0 + rI][j0 + 1] = tn1; }
        }
        cur ^= 1;
        __syncthreads();
    }

#pragma unroll
    for (int rI = 0; rI < 4; rI++) {
        float2 v = make_float2(acc[rI][0], acc[rI][1]);
        *(float2*)&Zt[(i0 + rI) * NDIM + jg + j0] = v;
    }
}

// ---------------------------------------------------------------------------
extern "C" void kernel_launch(void* const* d_in, const int* in_sizes, int n_in,
                              void* d_out, int out_size) {
    const float* X    = (const float*)d_in[0];   // (64, 4096)
    const float* F    = (const float*)d_in[1];   // (64, 64)
    const float* Q_S  = (const float*)d_in[2];   // (4096, 4096)
    const float* lamS = (const float*)d_in[3];   // (4096,)
    const float* gam  = (const float*)d_in[4];   // scalar
    float* Z = (float*)d_out;                    // (64, 4096)

    float *Y, *Zt;
    cudaGetSymbolAddress((void**)&Y,  g_Y);
    cudaGetSymbolAddress((void**)&Zt, g_Zt);

    static bool attr_set = false;
    if (!attr_set) {
        cudaFuncSetAttribute(gemm_tc<0>, cudaFuncAttributeMaxDynamicSharedMemorySize, SMEM_BYTES);
        cudaFuncSetAttribute(gemm_tc<1>, cudaFuncAttributeMaxDynamicSharedMemorySize, SMEM_BYTES);
        attr_set = true;
    }

    dim3 ggrid(NDIM / BN, 2);

    zero_kernel<<<(MDIM * NDIM) / 256, 256>>>(Y, Z);          // Y = 0, Z = 0
    prep_kernel<<<1, 256>>>(F);
    gemm_tc<0><<<ggrid, 256, SMEM_BYTES>>>(X, Q_S, Y);        // Y += X @ Q_S
    cheb_kernel<<<NDIM / BN, 256>>>(lamS, gam, Zt);           // Zt = f(G) Y
    gemm_tc<1><<<ggrid, 256, SMEM_BYTES>>>(Zt, Q_S, Z);       // Z += Zt @ Q_S^T
}

// round 5
// speedup vs baseline: 2.5852x; 1.2322x over previous
#include <cuda_runtime.h>
#include <cuda_bf16.h>
#include <cstdint>
#include <math.h>

#define MDIM 64
#define NDIM 4096
#define BN   32
#define KB   32
#define NST  4
#define KSPL 2048
#define NCH  (KSPL / KB)
#define KCHEB 14

// smem strides in bf16 elements (conflict-free for ldmatrix, 16B aligned)
#define AST 40
#define BST 40
#define GST 72
#define TST 40

#define STAGE_A (64 * AST)                    // 2560 bf16
#define STAGE_B (32 * BST)                    // 1280 bf16
#define STAGE_ELEMS (2 * STAGE_A + 2 * STAGE_B)  // 7680 bf16
#define GEMM_SMEM (NST * STAGE_ELEMS * 2)     // 61440 B

// Scratch (allocation-free rule: __device__ globals)
__device__ float g_Gt[MDIM * MDIM];
__device__ float g_Y [MDIM * NDIM];
__device__ __nv_bfloat16 g_Qh[(size_t)NDIM * NDIM];
__device__ __nv_bfloat16 g_Ql[(size_t)NDIM * NDIM];
__device__ __nv_bfloat16 g_Xh[MDIM * NDIM];
__device__ __nv_bfloat16 g_Xl[MDIM * NDIM];
__device__ __nv_bfloat16 g_Zh[MDIM * NDIM];
__device__ __nv_bfloat16 g_Zl[MDIM * NDIM];

// ---------------------------------------------------------------------------
// PTX helpers
// ---------------------------------------------------------------------------
__device__ __forceinline__ uint32_t sptr(const void* p) {
    return (uint32_t)__cvta_generic_to_shared(p);
}
__device__ __forceinline__ void ldsm4(uint32_t r[4], uint32_t addr) {
    asm volatile("ldmatrix.sync.aligned.m8n8.x4.shared.b16 {%0,%1,%2,%3}, [%4];"
                 : "=r"(r[0]), "=r"(r[1]), "=r"(r[2]), "=r"(r[3]) : "r"(addr));
}
__device__ __forceinline__ void ldsm4t(uint32_t r[4], uint32_t addr) {
    asm volatile("ldmatrix.sync.aligned.m8n8.x4.trans.shared.b16 {%0,%1,%2,%3}, [%4];"
                 : "=r"(r[0]), "=r"(r[1]), "=r"(r[2]), "=r"(r[3]) : "r"(addr));
}
__device__ __forceinline__ void mma16816(float d[4], const uint32_t a[4],
                                         uint32_t b0, uint32_t b1) {
    asm volatile("mma.sync.aligned.m16n8k16.row.col.f32.bf16.bf16.f32 "
                 "{%0,%1,%2,%3}, {%4,%5,%6,%7}, {%8,%9}, {%0,%1,%2,%3};"
                 : "+f"(d[0]), "+f"(d[1]), "+f"(d[2]), "+f"(d[3])
                 : "r"(a[0]), "r"(a[1]), "r"(a[2]), "r"(a[3]),
                   "r"(b0), "r"(b1));
}
__device__ __forceinline__ void cpa16(uint32_t dst, const void* src) {
    asm volatile("cp.async.cg.shared.global [%0], [%1], 16;" :: "r"(dst), "l"(src));
}
__device__ __forceinline__ void cpcommit() { asm volatile("cp.async.commit_group;"); }
__device__ __forceinline__ void cpwait()   { asm volatile("cp.async.wait_group %0;" :: "n"(NST - 1)); }

__device__ __forceinline__ void bf16split(float x, __nv_bfloat16& h, __nv_bfloat16& l) {
    h = __float2bfloat16(x);
    l = __float2bfloat16(x - __bfloat162float(h));
}
__device__ __forceinline__ void split2pack(float a, float b, uint32_t& hp, uint32_t& lp) {
    __nv_bfloat16 ha, la, hb, lb;
    bf16split(a, ha, la);
    bf16split(b, hb, lb);
    __nv_bfloat162 h; h.x = ha; h.y = hb;
    __nv_bfloat162 l; l.x = la; l.y = lb;
    hp = *(uint32_t*)&h;
    lp = *(uint32_t*)&l;
}

// ---------------------------------------------------------------------------
// Convert Q_S and X to bf16 hi/lo (one float4 per thread)
// ---------------------------------------------------------------------------
__global__ __launch_bounds__(256) void conv_kernel(const float4* __restrict__ Q,
                                                   const float4* __restrict__ X) {
    const size_t QN4 = (size_t)NDIM * NDIM / 4;
    size_t gid = (size_t)blockIdx.x * 256 + threadIdx.x;
    float4 v;
    __nv_bfloat16 *dh, *dl;
    size_t off;
    if (gid < QN4) { v = Q[gid]; dh = g_Qh; dl = g_Ql; off = gid * 4; }
    else { size_t x = gid - QN4; v = X[x]; dh = g_Xh; dl = g_Xl; off = x * 4; }
    uint32_t h0, l0, h1, l1;
    split2pack(v.x, v.y, h0, l0);
    split2pack(v.z, v.w, h1, l1);
    *(uint2*)(dh + off) = make_uint2(h0, h1);
    *(uint2*)(dl + off) = make_uint2(l0, l1);
}

// ---------------------------------------------------------------------------
// Zero-init Y and Z (outputs accumulated via atomicAdd each replay)
// ---------------------------------------------------------------------------
__global__ __launch_bounds__(256) void zero_kernel(float* __restrict__ a,
                                                   float* __restrict__ b) {
    int i = blockIdx.x * 256 + threadIdx.x;
    a[i] = 0.0f;
    b[i] = 0.0f;
}

// ---------------------------------------------------------------------------
// G~ = 2 * (F^T F) / (||F^T F||_F + 1e-12) - I
// ---------------------------------------------------------------------------
__global__ __launch_bounds__(256) void prep_kernel(const float* __restrict__ F) {
    __shared__ float Fs[MDIM][MDIM + 1];
    __shared__ float FFs[MDIM][MDIM + 4];
    __shared__ float red[8];
    __shared__ float s_inv;

    int t = threadIdx.x;
    for (int o = t; o < MDIM * MDIM; o += 256)
        Fs[o >> 6][o & 63] = F[o];
    __syncthreads();

    int i  = t >> 2;
    int j0 = (t & 3) * 16;
    float acc[16];
#pragma unroll
    for (int u = 0; u < 16; u++) acc[u] = 0.0f;
    for (int k = 0; k < MDIM; k++) {
        float a = Fs[k][i];
#pragma unroll
        for (int u = 0; u < 16; u++) acc[u] = fmaf(a, Fs[k][j0 + u], acc[u]);
    }
    float ss = 0.0f;
#pragma unroll
    for (int u = 0; u < 16; u++) {
        FFs[i][j0 + u] = acc[u];
        ss = fmaf(acc[u], acc[u], ss);
    }
#pragma unroll
    for (int off = 16; off > 0; off >>= 1)
        ss += __shfl_xor_sync(0xffffffffu, ss, off);
    if ((t & 31) == 0) red[t >> 5] = ss;
    __syncthreads();
    if (t == 0) {
        float tot = 0.0f;
        for (int w = 0; w < 8; w++) tot += red[w];
        s_inv = 2.0f / (sqrtf(tot) + 1e-12f);
    }
    __syncthreads();
    float inv = s_inv;
#pragma unroll
    for (int u = 0; u < 16; u++) {
        int j = j0 + u;
        g_Gt[i * MDIM + j] = FFs[i][j] * inv - (i == j ? 1.0f : 0.0f);
    }
}

// ---------------------------------------------------------------------------
// cp.async stage fill: A tile 64 x KB (hi+lo), B tile (hi+lo)
// ---------------------------------------------------------------------------
template <int TRANSB>
__device__ __forceinline__ void issue_bf(__nv_bfloat16* st,
                                         const __nv_bfloat16* __restrict__ Agh,
                                         const __nv_bfloat16* __restrict__ Agl,
                                         const __nv_bfloat16* __restrict__ Bgh,
                                         const __nv_bfloat16* __restrict__ Bgl,
                                         int kbase, int jg, int t) {
    int ar = t >> 2, ag = (t & 3) * 8;
    cpa16(sptr(st + ar * AST + ag),           Agh + (size_t)ar * NDIM + kbase + ag);
    cpa16(sptr(st + STAGE_A + ar * AST + ag), Agl + (size_t)ar * NDIM + kbase + ag);
    int br = (t & 127) >> 2, bg = (t & 3) * 8;
    const __nv_bfloat16* bsrc = (t < 128) ? Bgh : Bgl;
    __nv_bfloat16* bdst = st + 2 * STAGE_A + ((t < 128) ? 0 : STAGE_B) + br * BST + bg;
    size_t bidx = TRANSB ? ((size_t)(jg + br) * NDIM + kbase + bg)
                         : ((size_t)(kbase + br) * NDIM + jg + bg);
    cpa16(sptr(bdst), bsrc + bidx);
}

// ---------------------------------------------------------------------------
// Pure-bf16 tensor GEMM, 3-term hi/lo split, K-split x2, 4-stage cp.async.
// TRANSB=0: C += A @ B (B is K x N);  TRANSB=1: C += A @ B^T (B is N x K)
// ---------------------------------------------------------------------------
template <int TRANSB>
__global__ __launch_bounds__(256) void gemm_bf(const __nv_bfloat16* __restrict__ Agh,
                                               const __nv_bfloat16* __restrict__ Agl,
                                               const __nv_bfloat16* __restrict__ Bgh,
                                               const __nv_bfloat16* __restrict__ Bgl,
                                               float* __restrict__ C) {
    extern __shared__ __align__(16) __nv_bfloat16 sm[];
    const int t    = threadIdx.x;
    const int lane = t & 31;
    const int warp = t >> 5;
    const int jg   = blockIdx.x * BN;
    const int k0g  = blockIdx.y * KSPL;
    const int mw   = (warp & 3) * 16;
    const int nw   = (warp >> 2) * 16;
    const int lr   = lane & 15;
    const int g8   = (lane >> 4) * 8;

    float acc[2][4];
#pragma unroll
    for (int nt = 0; nt < 2; nt++)
#pragma unroll
        for (int u = 0; u < 4; u++) acc[nt][u] = 0.0f;

#pragma unroll
    for (int c = 0; c < NST - 1; c++) {
        issue_bf<TRANSB>(sm + c * STAGE_ELEMS, Agh, Agl, Bgh, Bgl, k0g + c * KB, jg, t);
        cpcommit();
    }

    for (int c = 0; c < NCH; c++) {
        int cn = c + NST - 1;
        if (cn < NCH)
            issue_bf<TRANSB>(sm + (cn % NST) * STAGE_ELEMS, Agh, Agl, Bgh, Bgl,
                             k0g + cn * KB, jg, t);
        cpcommit();
        cpwait();
        __syncthreads();

        __nv_bfloat16* st = sm + (c % NST) * STAGE_ELEMS;
        __nv_bfloat16* Ah = st;
        __nv_bfloat16* Al = st + STAGE_A;
        __nv_bfloat16* Bh = st + 2 * STAGE_A;
        __nv_bfloat16* Bl = Bh + STAGE_B;

#pragma unroll
        for (int ks = 0; ks < 2; ks++) {
            uint32_t ah[4], al[4], bh[4], bl[4];
            ldsm4(ah, sptr(Ah + (mw + lr) * AST + ks * 16 + g8));
            ldsm4(al, sptr(Al + (mw + lr) * AST + ks * 16 + g8));
            if (TRANSB == 0) {
                ldsm4t(bh, sptr(Bh + (ks * 16 + lr) * BST + nw + g8));
                ldsm4t(bl, sptr(Bl + (ks * 16 + lr) * BST + nw + g8));
                mma16816(acc[0], ah, bh[0], bh[1]);
                mma16816(acc[0], ah, bl[0], bl[1]);
                mma16816(acc[0], al, bh[0], bh[1]);
                mma16816(acc[1], ah, bh[2], bh[3]);
                mma16816(acc[1], ah, bl[2], bl[3]);
                mma16816(acc[1], al, bh[2], bh[3]);
            } else {
                ldsm4(bh, sptr(Bh + (nw + lr) * BST + ks * 16 + g8));
                ldsm4(bl, sptr(Bl + (nw + lr) * BST + ks * 16 + g8));
                mma16816(acc[0], ah, bh[0], bh[2]);
                mma16816(acc[0], ah, bl[0], bl[2]);
                mma16816(acc[0], al, bh[0], bh[2]);
                mma16816(acc[1], ah, bh[1], bh[3]);
                mma16816(acc[1], ah, bl[1], bl[3]);
                mma16816(acc[1], al, bh[1], bh[3]);
            }
        }
        __syncthreads();
    }

    const int row = mw + (lane >> 2);
    const int col = jg + nw + (lane & 3) * 2;
#pragma unroll
    for (int nt = 0; nt < 2; nt++) {
        atomicAdd(&C[(size_t)row * NDIM + col + nt * 8],           acc[nt][0]);
        atomicAdd(&C[(size_t)row * NDIM + col + nt * 8 + 1],       acc[nt][1]);
        atomicAdd(&C[(size_t)(row + 8) * NDIM + col + nt * 8],     acc[nt][2]);
        atomicAdd(&C[(size_t)(row + 8) * NDIM + col + nt * 8 + 1], acc[nt][3]);
    }
}

// ---------------------------------------------------------------------------
// Tensor-core Chebyshev: G~ fragments resident, T recurrence via 3 rotating
// bf16 hi/lo smem buffers, fp32 fragment accumulation, bf16 hi/lo output.
// ---------------------------------------------------------------------------
__global__ __launch_bounds__(256) void cheb_tc(const float* __restrict__ lamS,
                                               const float* __restrict__ gammap) {
    extern __shared__ __align__(16) __nv_bfloat16 cs[];
    __nv_bfloat16* Gh = cs;                      // 64*GST
    __nv_bfloat16* Gl = cs + 64 * GST;
    __nv_bfloat16* Tbh = cs + 2 * 64 * GST;      // 3 buffers of 64*TST
    __nv_bfloat16* Tbl = Tbh + 3 * 64 * TST;
    __shared__ float sh_base[BN];
    __shared__ float sh_r[BN];

    const int t    = threadIdx.x;
    const int lane = t & 31;
    const int warp = t >> 5;
    const int jg   = blockIdx.x * BN;
    const int mw   = (warp & 3) * 16;
    const int nw   = (warp >> 2) * 16;
    const int lr   = lane & 15;
    const int g8   = (lane >> 4) * 8;

    // split G~ into smem hi/lo
    for (int o = t; o < MDIM * MDIM; o += 256) {
        int r = o >> 6, c = o & 63;
        __nv_bfloat16 h, l;
        bf16split(g_Gt[o], h, l);
        Gh[r * GST + c] = h;
        Gl[r * GST + c] = l;
    }
    // split Y tile into T buffer 0
    for (int o = t; o < MDIM * BN; o += 256) {
        int r = o >> 5, c = o & 31;
        __nv_bfloat16 h, l;
        bf16split(g_Y[(size_t)r * NDIM + jg + c], h, l);
        Tbh[r * TST + c] = h;
        Tbl[r * TST + c] = l;
    }
    // per-column coefficients
    if (t < BN) {
        float gam = gammap[0];
        float a = gam * lamS[jg + t];
        float base, r;
        if (fabsf(a) < 1e-7f) {
            base = 1.0f; r = 0.0f;
        } else {
            float b  = 2.0f / a - 1.0f;
            float ab = fabsf(b);
            float s  = sqrtf(fmaf(ab, ab, -1.0f));
            float q  = 1.0f / (ab + s);
            float sg = (a > 0.0f) ? 1.0f : -1.0f;
            r    = sg * q;
            base = (2.0f / a) * sg * 2.0f * q / (1.0f - q * q);
        }
        sh_base[t] = base;
        sh_r[t]    = r;
    }
    __syncthreads();

    // G fragments (resident for the whole kernel)
    uint32_t gh[4][4], gl[4][4];
#pragma unroll
    for (int ks = 0; ks < 4; ks++) {
        ldsm4(gh[ks], sptr(Gh + (mw + lr) * GST + ks * 16 + g8));
        ldsm4(gl[ks], sptr(Gl + (mw + lr) * GST + ks * 16 + g8));
    }

    const int row0 = mw + (lane >> 2);
    float basev[2][2], rv[2][2], pv[2][2];
#pragma unroll
    for (int nt = 0; nt < 2; nt++) {
        int c0 = nw + nt * 8 + 2 * (lane & 3);
        basev[nt][0] = sh_base[c0];     basev[nt][1] = sh_base[c0 + 1];
        rv[nt][0]    = sh_r[c0];        rv[nt][1]    = sh_r[c0 + 1];
        pv[nt][0] = 2.0f * basev[nt][0] * rv[nt][0];
        pv[nt][1] = 2.0f * basev[nt][1] * rv[nt][1];
    }

    float acc[2][4], prev[2][4], tp[2][4];
#pragma unroll
    for (int nt = 0; nt < 2; nt++) {
        int c0 = nw + nt * 8 + 2 * (lane & 3);
        float2 y0 = *(const float2*)&g_Y[(size_t)row0 * NDIM + jg + c0];
        float2 y1 = *(const float2*)&g_Y[(size_t)(row0 + 8) * NDIM + jg + c0];
        prev[nt][0] = y0.x; prev[nt][1] = y0.y; prev[nt][2] = y1.x; prev[nt][3] = y1.y;
        acc[nt][0] = basev[nt][0] * y0.x;
        acc[nt][1] = basev[nt][1] * y0.y;
        acc[nt][2] = basev[nt][0] * y1.x;
        acc[nt][3] = basev[nt][1] * y1.y;
        tp[nt][0] = tp[nt][1] = tp[nt][2] = tp[nt][3] = 0.0f;
    }

    // iterations k = 1 .. KCHEB-1: buffer (k-1)%3 holds T_{k-1}; write T_k to k%3
    for (int k = 1; k < KCHEB; k++) {
        __syncthreads();
        const __nv_bfloat16* Th = Tbh + ((k - 1) % 3) * (64 * TST);
        const __nv_bfloat16* Tl = Tbl + ((k - 1) % 3) * (64 * TST);
        float u[2][4];
#pragma unroll
        for (int nt = 0; nt < 2; nt++)
#pragma unroll
            for (int i = 0; i < 4; i++) u[nt][i] = 0.0f;
#pragma unroll
        for (int ks = 0; ks < 4; ks++) {
            uint32_t th[4], tl[4];
            ldsm4t(th, sptr(Th + (ks * 16 + lr) * TST + nw + g8));
            ldsm4t(tl, sptr(Tl + (ks * 16 + lr) * TST + nw + g8));
            mma16816(u[0], gh[ks], th[0], th[1]);
            mma16816(u[0], gh[ks], tl[0], tl[1]);
            mma16816(u[0], gl[ks], th[0], th[1]);
            mma16816(u[1], gh[ks], th[2], th[3]);
            mma16816(u[1], gh[ks], tl[2], tl[3]);
            mma16816(u[1], gl[ks], th[2], th[3]);
        }
        float tn[2][4];
#pragma unroll
        for (int nt = 0; nt < 2; nt++)
#pragma unroll
            for (int i = 0; i < 4; i++)
                tn[nt][i] = (k == 1) ? u[nt][i] : fmaf(2.0f, u[nt][i], -tp[nt][i]);
        // accumulate c_k * T_k
#pragma unroll
        for (int nt = 0; nt < 2; nt++) {
            acc[nt][0] = fmaf(pv[nt][0], tn[nt][0], acc[nt][0]);
            acc[nt][1] = fmaf(pv[nt][1], tn[nt][1], acc[nt][1]);
            acc[nt][2] = fmaf(pv[nt][0], tn[nt][2], acc[nt][2]);
            acc[nt][3] = fmaf(pv[nt][1], tn[nt][3], acc[nt][3]);
            pv[nt][0] *= rv[nt][0];
            pv[nt][1] *= rv[nt][1];
        }
        // store T_k for next iteration (skip at last)
        if (k < KCHEB - 1) {
            __nv_bfloat16* Wh = Tbh + (k % 3) * (64 * TST);
            __nv_bfloat16* Wl = Tbl + (k % 3) * (64 * TST);
#pragma unroll
            for (int nt = 0; nt < 2; nt++) {
                int c0 = nw + nt * 8 + 2 * (lane & 3);
                uint32_t hp, lp;
                split2pack(tn[nt][0], tn[nt][1], hp, lp);
                *(uint32_t*)(Wh + row0 * TST + c0) = hp;
                *(uint32_t*)(Wl + row0 * TST + c0) = lp;
                split2pack(tn[nt][2], tn[nt][3], hp, lp);
                *(uint32_t*)(Wh + (row0 + 8) * TST + c0) = hp;
                *(uint32_t*)(Wl + (row0 + 8) * TST + c0) = lp;
            }
        }
        // rotate recurrence state
#pragma unroll
        for (int nt = 0; nt < 2; nt++)
#pragma unroll
            for (int i = 0; i < 4; i++) {
                tp[nt][i]   = prev[nt][i];
                prev[nt][i] = tn[nt][i];
            }
    }

    // write Z~ as bf16 hi/lo
#pragma unroll
    for (int nt = 0; nt < 2; nt++) {
        int c0 = nw + nt * 8 + 2 * (lane & 3);
        uint32_t hp, lp;
        split2pack(acc[nt][0], acc[nt][1], hp, lp);
        *(uint32_t*)(g_Zh + (size_t)row0 * NDIM + jg + c0) = hp;
        *(uint32_t*)(g_Zl + (size_t)row0 * NDIM + jg + c0) = lp;
        split2pack(acc[nt][2], acc[nt][3], hp, lp);
        *(uint32_t*)(g_Zh + (size_t)(row0 + 8) * NDIM + jg + c0) = hp;
        *(uint32_t*)(g_Zl + (size_t)(row0 + 8) * NDIM + jg + c0) = lp;
    }
}

#define CHEB_SMEM ((2 * 64 * GST + 6 * 64 * TST) * 2)

// ---------------------------------------------------------------------------
extern "C" void kernel_launch(void* const* d_in, const int* in_sizes, int n_in,
                              void* d_out, int out_size) {
    const float* X    = (const float*)d_in[0];   // (64, 4096)
    const float* F    = (const float*)d_in[1];   // (64, 64)
    const float* Q_S  = (const float*)d_in[2];   // (4096, 4096)
    const float* lamS = (const float*)d_in[3];   // (4096,)
    const float* gam  = (const float*)d_in[4];   // scalar
    float* Z = (float*)d_out;                    // (64, 4096)

    float *Y;
    __nv_bfloat16 *Qh, *Ql, *Xh, *Xl, *Zh, *Zl;
    cudaGetSymbolAddress((void**)&Y,  g_Y);
    cudaGetSymbolAddress((void**)&Qh, g_Qh);
    cudaGetSymbolAddress((void**)&Ql, g_Ql);
    cudaGetSymbolAddress((void**)&Xh, g_Xh);
    cudaGetSymbolAddress((void**)&Xl, g_Xl);
    cudaGetSymbolAddress((void**)&Zh, g_Zh);
    cudaGetSymbolAddress((void**)&Zl, g_Zl);

    static bool attr_set = false;
    if (!attr_set) {
        cudaFuncSetAttribute(gemm_bf<0>, cudaFuncAttributeMaxDynamicSharedMemorySize, GEMM_SMEM);
        cudaFuncSetAttribute(gemm_bf<1>, cudaFuncAttributeMaxDynamicSharedMemorySize, GEMM_SMEM);
        cudaFuncSetAttribute(cheb_tc,    cudaFuncAttributeMaxDynamicSharedMemorySize, CHEB_SMEM);
        attr_set = true;
    }

    const int conv_blocks = (NDIM * NDIM / 4 + MDIM * NDIM / 4) / 256;  // 16640
    dim3 ggrid(NDIM / BN, 2);

    conv_kernel<<<conv_blocks, 256>>>((const float4*)Q_S, (const float4*)X);
    zero_kernel<<<(MDIM * NDIM) / 256, 256>>>(Y, Z);
    prep_kernel<<<1, 256>>>(F);
    gemm_bf<0><<<ggrid, 256, GEMM_SMEM>>>(Xh, Xl, Qh, Ql, Y);   // Y += X @ Q_S
    cheb_tc<<<NDIM / BN, 256, CHEB_SMEM>>>(lamS, gam);          // Zh/Zl = f(G) Y
    gemm_bf<1><<<ggrid, 256, GEMM_SMEM>>>(Zh, Zl, Qh, Ql, Z);   // Z += Z~ @ Q_S^T
}

// round 6
// speedup vs baseline: 2.6694x; 1.0326x over previous
#include <cuda_runtime.h>
#include <cuda_bf16.h>
#include <cstdint>
#include <math.h>

#define MDIM 64
#define NDIM 4096
#define BN   32
#define KB   32
#define NST  4
#define KSPL 1024
#define NCH  (KSPL / KB)     // 32 chunks per K-split
#define NSPLIT (NDIM / KSPL) // 4
#define KCHEB 14

// smem strides in bf16 elements (conflict-free for ldmatrix, 16B aligned)
#define AST 40
#define BST 40
#define GST 72
#define TST 40

#define STAGE_A (64 * AST)                       // 2560 bf16
#define STAGE_B (32 * BST)                       // 1280 bf16
#define STAGE_ELEMS (2 * STAGE_A + 2 * STAGE_B)  // 7680 bf16
#define GEMM_SMEM (NST * STAGE_ELEMS * 2)        // 61440 B

// Scratch (allocation-free rule: __device__ globals)
__device__ float g_Gt[MDIM * MDIM];
__device__ float g_Y [MDIM * NDIM];
__device__ __nv_bfloat16 g_Qh[(size_t)NDIM * NDIM];
__device__ __nv_bfloat16 g_Ql[(size_t)NDIM * NDIM];
__device__ __nv_bfloat16 g_Xh[MDIM * NDIM];
__device__ __nv_bfloat16 g_Xl[MDIM * NDIM];
__device__ __nv_bfloat16 g_Zh[MDIM * NDIM];
__device__ __nv_bfloat16 g_Zl[MDIM * NDIM];

// ---------------------------------------------------------------------------
// PTX helpers
// ---------------------------------------------------------------------------
__device__ __forceinline__ uint32_t sptr(const void* p) {
    return (uint32_t)__cvta_generic_to_shared(p);
}
__device__ __forceinline__ void ldsm4(uint32_t r[4], uint32_t addr) {
    asm volatile("ldmatrix.sync.aligned.m8n8.x4.shared.b16 {%0,%1,%2,%3}, [%4];"
                 : "=r"(r[0]), "=r"(r[1]), "=r"(r[2]), "=r"(r[3]) : "r"(addr));
}
__device__ __forceinline__ void ldsm4t(uint32_t r[4], uint32_t addr) {
    asm volatile("ldmatrix.sync.aligned.m8n8.x4.trans.shared.b16 {%0,%1,%2,%3}, [%4];"
                 : "=r"(r[0]), "=r"(r[1]), "=r"(r[2]), "=r"(r[3]) : "r"(addr));
}
__device__ __forceinline__ void mma16816(float d[4], const uint32_t a[4],
                                         uint32_t b0, uint32_t b1) {
    asm volatile("mma.sync.aligned.m16n8k16.row.col.f32.bf16.bf16.f32 "
                 "{%0,%1,%2,%3}, {%4,%5,%6,%7}, {%8,%9}, {%0,%1,%2,%3};"
                 : "+f"(d[0]), "+f"(d[1]), "+f"(d[2]), "+f"(d[3])
                 : "r"(a[0]), "r"(a[1]), "r"(a[2]), "r"(a[3]),
                   "r"(b0), "r"(b1));
}
__device__ __forceinline__ void cpa16(uint32_t dst, const void* src) {
    asm volatile("cp.async.cg.shared.global [%0], [%1], 16;" :: "r"(dst), "l"(src));
}
__device__ __forceinline__ void cpcommit() { asm volatile("cp.async.commit_group;"); }
__device__ __forceinline__ void cpwait_oldest() {
    asm volatile("cp.async.wait_group %0;" :: "n"(NST - 2));
}

__device__ __forceinline__ void bf16split(float x, __nv_bfloat16& h, __nv_bfloat16& l) {
    h = __float2bfloat16(x);
    l = __float2bfloat16(x - __bfloat162float(h));
}
__device__ __forceinline__ void split2pack(float a, float b, uint32_t& hp, uint32_t& lp) {
    __nv_bfloat16 ha, la, hb, lb;
    bf16split(a, ha, la);
    bf16split(b, hb, lb);
    __nv_bfloat162 h; h.x = ha; h.y = hb;
    __nv_bfloat162 l; l.x = la; l.y = lb;
    hp = *(uint32_t*)&h;
    lp = *(uint32_t*)&l;
}

// ---------------------------------------------------------------------------
// Convert Q_S and X to bf16 hi/lo (one float4 per thread)
// ---------------------------------------------------------------------------
__global__ __launch_bounds__(256) void conv_kernel(const float4* __restrict__ Q,
                                                   const float4* __restrict__ X) {
    const size_t QN4 = (size_t)NDIM * NDIM / 4;
    size_t gid = (size_t)blockIdx.x * 256 + threadIdx.x;
    float4 v;
    __nv_bfloat16 *dh, *dl;
    size_t off;
    if (gid < QN4) { v = Q[gid]; dh = g_Qh; dl = g_Ql; off = gid * 4; }
    else { size_t x = gid - QN4; v = X[x]; dh = g_Xh; dl = g_Xl; off = x * 4; }
    uint32_t h0, l0, h1, l1;
    split2pack(v.x, v.y, h0, l0);
    split2pack(v.z, v.w, h1, l1);
    *(uint2*)(dh + off) = make_uint2(h0, h1);
    *(uint2*)(dl + off) = make_uint2(l0, l1);
}

// ---------------------------------------------------------------------------
// Zero-init Y and Z (outputs accumulated via atomicAdd each replay)
// ---------------------------------------------------------------------------
__global__ __launch_bounds__(256) void zero_kernel(float* __restrict__ a,
                                                   float* __restrict__ b) {
    int i = blockIdx.x * 256 + threadIdx.x;
    a[i] = 0.0f;
    b[i] = 0.0f;
}

// ---------------------------------------------------------------------------
// G~ = 2 * (F^T F) / (||F^T F||_F + 1e-12) - I
// ---------------------------------------------------------------------------
__global__ __launch_bounds__(256) void prep_kernel(const float* __restrict__ F) {
    __shared__ float Fs[MDIM][MDIM + 1];
    __shared__ float FFs[MDIM][MDIM + 4];
    __shared__ float red[8];
    __shared__ float s_inv;

    int t = threadIdx.x;
    for (int o = t; o < MDIM * MDIM; o += 256)
        Fs[o >> 6][o & 63] = F[o];
    __syncthreads();

    int i  = t >> 2;
    int j0 = (t & 3) * 16;
    float acc[16];
#pragma unroll
    for (int u = 0; u < 16; u++) acc[u] = 0.0f;
    for (int k = 0; k < MDIM; k++) {
        float a = Fs[k][i];
#pragma unroll
        for (int u = 0; u < 16; u++) acc[u] = fmaf(a, Fs[k][j0 + u], acc[u]);
    }
    float ss = 0.0f;
#pragma unroll
    for (int u = 0; u < 16; u++) {
        FFs[i][j0 + u] = acc[u];
        ss = fmaf(acc[u], acc[u], ss);
    }
#pragma unroll
    for (int off = 16; off > 0; off >>= 1)
        ss += __shfl_xor_sync(0xffffffffu, ss, off);
    if ((t & 31) == 0) red[t >> 5] = ss;
    __syncthreads();
    if (t == 0) {
        float tot = 0.0f;
        for (int w = 0; w < 8; w++) tot += red[w];
        s_inv = 2.0f / (sqrtf(tot) + 1e-12f);
    }
    __syncthreads();
    float inv = s_inv;
#pragma unroll
    for (int u = 0; u < 16; u++) {
        int j = j0 + u;
        g_Gt[i * MDIM + j] = FFs[i][j] * inv - (i == j ? 1.0f : 0.0f);
    }
}

// ---------------------------------------------------------------------------
// cp.async stage fill: A tile 64 x KB (hi+lo), B tile (hi+lo)
// ---------------------------------------------------------------------------
template <int TRANSB>
__device__ __forceinline__ void issue_bf(__nv_bfloat16* st,
                                         const __nv_bfloat16* __restrict__ Agh,
                                         const __nv_bfloat16* __restrict__ Agl,
                                         const __nv_bfloat16* __restrict__ Bgh,
                                         const __nv_bfloat16* __restrict__ Bgl,
                                         int kbase, int jg, int t) {
    int ar = t >> 2, ag = (t & 3) * 8;
    cpa16(sptr(st + ar * AST + ag),           Agh + (size_t)ar * NDIM + kbase + ag);
    cpa16(sptr(st + STAGE_A + ar * AST + ag), Agl + (size_t)ar * NDIM + kbase + ag);
    int br = (t & 127) >> 2, bg = (t & 3) * 8;
    const __nv_bfloat16* bsrc = (t < 128) ? Bgh : Bgl;
    __nv_bfloat16* bdst = st + 2 * STAGE_A + ((t < 128) ? 0 : STAGE_B) + br * BST + bg;
    size_t bidx = TRANSB ? ((size_t)(jg + br) * NDIM + kbase + bg)
                         : ((size_t)(kbase + br) * NDIM + jg + bg);
    cpa16(sptr(bdst), bsrc + bidx);
}

// ---------------------------------------------------------------------------
// Pure-bf16 tensor GEMM, 3-term hi/lo split, K-split x4, 4-stage cp.async,
// single __syncthreads per mainloop iteration.
// TRANSB=0: C += A @ B (B is K x N);  TRANSB=1: C += A @ B^T (B is N x K)
// ---------------------------------------------------------------------------
template <int TRANSB>
__global__ __launch_bounds__(256) void gemm_bf(const __nv_bfloat16* __restrict__ Agh,
                                               const __nv_bfloat16* __restrict__ Agl,
                                               const __nv_bfloat16* __restrict__ Bgh,
                                               const __nv_bfloat16* __restrict__ Bgl,
                                               float* __restrict__ C) {
    extern __shared__ __align__(16) __nv_bfloat16 sm[];
    const int t    = threadIdx.x;
    const int lane = t & 31;
    const int warp = t >> 5;
    const int jg   = blockIdx.x * BN;
    const int k0g  = blockIdx.y * KSPL;
    const int mw   = (warp & 3) * 16;
    const int nw   = (warp >> 2) * 16;
    const int lr   = lane & 15;
    const int g8   = (lane >> 4) * 8;

    float acc[2][4];
#pragma unroll
    for (int nt = 0; nt < 2; nt++)
#pragma unroll
        for (int u = 0; u < 4; u++) acc[nt][u] = 0.0f;

#pragma unroll
    for (int c = 0; c < NST - 1; c++) {
        issue_bf<TRANSB>(sm + c * STAGE_ELEMS, Agh, Agl, Bgh, Bgl, k0g + c * KB, jg, t);
        cpcommit();
    }

    for (int c = 0; c < NCH; c++) {
        cpwait_oldest();          // chunk c's cp.asyncs (this thread's) complete
        __syncthreads();          // all threads' chunk-c data visible; stage (c-1) free

        // issue next stage early so its LDGs overlap the mma work below
        int cn = c + NST - 1;
        if (cn < NCH)
            issue_bf<TRANSB>(sm + (cn % NST) * STAGE_ELEMS, Agh, Agl, Bgh, Bgl,
                             k0g + cn * KB, jg, t);
        cpcommit();               // always commit: keeps group accounting exact

        __nv_bfloat16* st = sm + (c % NST) * STAGE_ELEMS;
        __nv_bfloat16* Ah = st;
        __nv_bfloat16* Al = st + STAGE_A;
        __nv_bfloat16* Bh = st + 2 * STAGE_A;
        __nv_bfloat16* Bl = Bh + STAGE_B;

#pragma unroll
        for (int ks = 0; ks < 2; ks++) {
            uint32_t ah[4], al[4], bh[4], bl[4];
            ldsm4(ah, sptr(Ah + (mw + lr) * AST + ks * 16 + g8));
            ldsm4(al, sptr(Al + (mw + lr) * AST + ks * 16 + g8));
            if (TRANSB == 0) {
                ldsm4t(bh, sptr(Bh + (ks * 16 + lr) * BST + nw + g8));
                ldsm4t(bl, sptr(Bl + (ks * 16 + lr) * BST + nw + g8));
                mma16816(acc[0], ah, bh[0], bh[1]);
                mma16816(acc[0], ah, bl[0], bl[1]);
                mma16816(acc[0], al, bh[0], bh[1]);
                mma16816(acc[1], ah, bh[2], bh[3]);
                mma16816(acc[1], ah, bl[2], bl[3]);
                mma16816(acc[1], al, bh[2], bh[3]);
            } else {
                ldsm4(bh, sptr(Bh + (nw + lr) * BST + ks * 16 + g8));
                ldsm4(bl, sptr(Bl + (nw + lr) * BST + ks * 16 + g8));
                mma16816(acc[0], ah, bh[0], bh[2]);
                mma16816(acc[0], ah, bl[0], bl[2]);
                mma16816(acc[0], al, bh[0], bh[2]);
                mma16816(acc[1], ah, bh[1], bh[3]);
                mma16816(acc[1], ah, bl[1], bl[3]);
                mma16816(acc[1], al, bh[1], bh[3]);
            }
        }
    }

    const int row = mw + (lane >> 2);
    const int col = jg + nw + (lane & 3) * 2;
#pragma unroll
    for (int nt = 0; nt < 2; nt++) {
        atomicAdd(&C[(size_t)row * NDIM + col + nt * 8],           acc[nt][0]);
        atomicAdd(&C[(size_t)row * NDIM + col + nt * 8 + 1],       acc[nt][1]);
        atomicAdd(&C[(size_t)(row + 8) * NDIM + col + nt * 8],     acc[nt][2]);
        atomicAdd(&C[(size_t)(row + 8) * NDIM + col + nt * 8 + 1], acc[nt][3]);
    }
}

// ---------------------------------------------------------------------------
// Tensor-core Chebyshev: G~ fragments resident, T recurrence via 3 rotating
// bf16 hi/lo smem buffers, fp32 fragment accumulation, bf16 hi/lo output.
// ---------------------------------------------------------------------------
__global__ __launch_bounds__(256) void cheb_tc(const float* __restrict__ lamS,
                                               const float* __restrict__ gammap) {
    extern __shared__ __align__(16) __nv_bfloat16 cs[];
    __nv_bfloat16* Gh = cs;                      // 64*GST
    __nv_bfloat16* Gl = cs + 64 * GST;
    __nv_bfloat16* Tbh = cs + 2 * 64 * GST;      // 3 buffers of 64*TST
    __nv_bfloat16* Tbl = Tbh + 3 * 64 * TST;
    __shared__ float sh_base[BN];
    __shared__ float sh_r[BN];

    const int t    = threadIdx.x;
    const int lane = t & 31;
    const int warp = t >> 5;
    const int jg   = blockIdx.x * BN;
    const int mw   = (warp & 3) * 16;
    const int nw   = (warp >> 2) * 16;
    const int lr   = lane & 15;
    const int g8   = (lane >> 4) * 8;

    for (int o = t; o < MDIM * MDIM; o += 256) {
        int r = o >> 6, c = o & 63;
        __nv_bfloat16 h, l;
        bf16split(g_Gt[o], h, l);
        Gh[r * GST + c] = h;
        Gl[r * GST + c] = l;
    }
    for (int o = t; o < MDIM * BN; o += 256) {
        int r = o >> 5, c = o & 31;
        __nv_bfloat16 h, l;
        bf16split(g_Y[(size_t)r * NDIM + jg + c], h, l);
        Tbh[r * TST + c] = h;
        Tbl[r * TST + c] = l;
    }
    if (t < BN) {
        float gam = gammap[0];
        float a = gam * lamS[jg + t];
        float base, r;
        if (fabsf(a) < 1e-7f) {
            base = 1.0f; r = 0.0f;
        } else {
            float b  = 2.0f / a - 1.0f;
            float ab = fabsf(b);
            float s  = sqrtf(fmaf(ab, ab, -1.0f));
            float q  = 1.0f / (ab + s);
            float sg = (a > 0.0f) ? 1.0f : -1.0f;
            r    = sg * q;
            base = (2.0f / a) * sg * 2.0f * q / (1.0f - q * q);
        }
        sh_base[t] = base;
        sh_r[t]    = r;
    }
    __syncthreads();

    uint32_t gh[4][4], gl[4][4];
#pragma unroll
    for (int ks = 0; ks < 4; ks++) {
        ldsm4(gh[ks], sptr(Gh + (mw + lr) * GST + ks * 16 + g8));
        ldsm4(gl[ks], sptr(Gl + (mw + lr) * GST + ks * 16 + g8));
    }

    const int row0 = mw + (lane >> 2);
    float basev[2][2], rv[2][2], pv[2][2];
#pragma unroll
    for (int nt = 0; nt < 2; nt++) {
        int c0 = nw + nt * 8 + 2 * (lane & 3);
        basev[nt][0] = sh_base[c0];     basev[nt][1] = sh_base[c0 + 1];
        rv[nt][0]    = sh_r[c0];        rv[nt][1]    = sh_r[c0 + 1];
        pv[nt][0] = 2.0f * basev[nt][0] * rv[nt][0];
        pv[nt][1] = 2.0f * basev[nt][1] * rv[nt][1];
    }

    float acc[2][4], prev[2][4], tp[2][4];
#pragma unroll
    for (int nt = 0; nt < 2; nt++) {
        int c0 = nw + nt * 8 + 2 * (lane & 3);
        float2 y0 = *(const float2*)&g_Y[(size_t)row0 * NDIM + jg + c0];
        float2 y1 = *(const float2*)&g_Y[(size_t)(row0 + 8) * NDIM + jg + c0];
        prev[nt][0] = y0.x; prev[nt][1] = y0.y; prev[nt][2] = y1.x; prev[nt][3] = y1.y;
        acc[nt][0] = basev[nt][0] * y0.x;
        acc[nt][1] = basev[nt][1] * y0.y;
        acc[nt][2] = basev[nt][0] * y1.x;
        acc[nt][3] = basev[nt][1] * y1.y;
        tp[nt][0] = tp[nt][1] = tp[nt][2] = tp[nt][3] = 0.0f;
    }

    for (int k = 1; k < KCHEB; k++) {
        __syncthreads();
        const __nv_bfloat16* Th = Tbh + ((k - 1) % 3) * (64 * TST);
        const __nv_bfloat16* Tl = Tbl + ((k - 1) % 3) * (64 * TST);
        float u[2][4];
#pragma unroll
        for (int nt = 0; nt < 2; nt++)
#pragma unroll
            for (int i = 0; i < 4; i++) u[nt][i] = 0.0f;
#pragma unroll
        for (int ks = 0; ks < 4; ks++) {
            uint32_t th[4], tl[4];
            ldsm4t(th, sptr(Th + (ks * 16 + lr) * TST + nw + g8));
            ldsm4t(tl, sptr(Tl + (ks * 16 + lr) * TST + nw + g8));
            mma16816(u[0], gh[ks], th[0], th[1]);
            mma16816(u[0], gh[ks], tl[0], tl[1]);
            mma16816(u[0], gl[ks], th[0], th[1]);
            mma16816(u[1], gh[ks], th[2], th[3]);
            mma16816(u[1], gh[ks], tl[2], tl[3]);
            mma16816(u[1], gl[ks], th[2], th[3]);
        }
        float tn[2][4];
#pragma unroll
        for (int nt = 0; nt < 2; nt++)
#pragma unroll
            for (int i = 0; i < 4; i++)
                tn[nt][i] = (k == 1) ? u[nt][i] : fmaf(2.0f, u[nt][i], -tp[nt][i]);
#pragma unroll
        for (int nt = 0; nt < 2; nt++) {
            acc[nt][0] = fmaf(pv[nt][0], tn[nt][0], acc[nt][0]);
            acc[nt][1] = fmaf(pv[nt][1], tn[nt][1], acc[nt][1]);
            acc[nt][2] = fmaf(pv[nt][0], tn[nt][2], acc[nt][2]);
            acc[nt][3] = fmaf(pv[nt][1], tn[nt][3], acc[nt][3]);
            pv[nt][0] *= rv[nt][0];
            pv[nt][1] *= rv[nt][1];
        }
        if (k < KCHEB - 1) {
            __nv_bfloat16* Wh = Tbh + (k % 3) * (64 * TST);
            __nv_bfloat16* Wl = Tbl + (k % 3) * (64 * TST);
#pragma unroll
            for (int nt = 0; nt < 2; nt++) {
                int c0 = nw + nt * 8 + 2 * (lane & 3);
                uint32_t hp, lp;
                split2pack(tn[nt][0], tn[nt][1], hp, lp);
                *(uint32_t*)(Wh + row0 * TST + c0) = hp;
                *(uint32_t*)(Wl + row0 * TST + c0) = lp;
                split2pack(tn[nt][2], tn[nt][3], hp, lp);
                *(uint32_t*)(Wh + (row0 + 8) * TST + c0) = hp;
                *(uint32_t*)(Wl + (row0 + 8) * TST + c0) = lp;
            }
        }
#pragma unroll
        for (int nt = 0; nt < 2; nt++)
#pragma unroll
            for (int i = 0; i < 4; i++) {
                tp[nt][i]   = prev[nt][i];
                prev[nt][i] = tn[nt][i];
            }
    }

#pragma unroll
    for (int nt = 0; nt < 2; nt++) {
        int c0 = nw + nt * 8 + 2 * (lane & 3);
        uint32_t hp, lp;
        split2pack(acc[nt][0], acc[nt][1], hp, lp);
        *(uint32_t*)(g_Zh + (size_t)row0 * NDIM + jg + c0) = hp;
        *(uint32_t*)(g_Zl + (size_t)row0 * NDIM + jg + c0) = lp;
        split2pack(acc[nt][2], acc[nt][3], hp, lp);
        *(uint32_t*)(g_Zh + (size_t)(row0 + 8) * NDIM + jg + c0) = hp;
        *(uint32_t*)(g_Zl + (size_t)(row0 + 8) * NDIM + jg + c0) = lp;
    }
}

#define CHEB_SMEM ((2 * 64 * GST + 6 * 64 * TST) * 2)

// ---------------------------------------------------------------------------
extern "C" void kernel_launch(void* const* d_in, const int* in_sizes, int n_in,
                              void* d_out, int out_size) {
    const float* X    = (const float*)d_in[0];   // (64, 4096)
    const float* F    = (const float*)d_in[1];   // (64, 64)
    const float* Q_S  = (const float*)d_in[2];   // (4096, 4096)
    const float* lamS = (const float*)d_in[3];   // (4096,)
    const float* gam  = (const float*)d_in[4];   // scalar
    float* Z = (float*)d_out;                    // (64, 4096)

    float *Y;
    __nv_bfloat16 *Qh, *Ql, *Xh, *Xl, *Zh, *Zl;
    cudaGetSymbolAddress((void**)&Y,  g_Y);
    cudaGetSymbolAddress((void**)&Qh, g_Qh);
    cudaGetSymbolAddress((void**)&Ql, g_Ql);
    cudaGetSymbolAddress((void**)&Xh, g_Xh);
    cudaGetSymbolAddress((void**)&Xl, g_Xl);
    cudaGetSymbolAddress((void**)&Zh, g_Zh);
    cudaGetSymbolAddress((void**)&Zl, g_Zl);

    static bool attr_set = false;
    if (!attr_set) {
        cudaFuncSetAttribute(gemm_bf<0>, cudaFuncAttributeMaxDynamicSharedMemorySize, GEMM_SMEM);
        cudaFuncSetAttribute(gemm_bf<1>, cudaFuncAttributeMaxDynamicSharedMemorySize, GEMM_SMEM);
        cudaFuncSetAttribute(cheb_tc,    cudaFuncAttributeMaxDynamicSharedMemorySize, CHEB_SMEM);
        attr_set = true;
    }

    const int conv_blocks = (NDIM * NDIM / 4 + MDIM * NDIM / 4) / 256;  // 16640
    dim3 ggrid(NDIM / BN, NSPLIT);

    conv_kernel<<<conv_blocks, 256>>>((const float4*)Q_S, (const float4*)X);
    zero_kernel<<<(MDIM * NDIM) / 256, 256>>>(Y, Z);
    prep_kernel<<<1, 256>>>(F);
    gemm_bf<0><<<ggrid, 256, GEMM_SMEM>>>(Xh, Xl, Qh, Ql, Y);   // Y += X @ Q_S
    cheb_tc<<<NDIM / BN, 256, CHEB_SMEM>>>(lamS, gam);          // Zh/Zl = f(G) Y
    gemm_bf<1><<<ggrid, 256, GEMM_SMEM>>>(Zh, Zl, Qh, Ql, Z);   // Z += Z~ @ Q_S^T
}

// round 7
// speedup vs baseline: 2.8453x; 1.0659x over previous
#include <cuda_runtime.h>
#include <cuda_bf16.h>
#include <cstdint>
#include <math.h>

#define MDIM 64
#define NDIM 4096
#define BN   64
#define KB   32
#define NST  4
#define KSPL 512
#define NCH  (KSPL / KB)     // 16 chunks per K-split
#define NSPLIT (NDIM / KSPL) // 8
#define KCHEB 14

// smem strides in bf16 elements (16B-aligned rows, conflict-free ldmatrix)
#define AST 40   // A tile rows: 64 x 32k
#define B0ST 80  // TRANSB=0: B tile [k=32][n=64]
#define B1ST 40  // TRANSB=1: B tile [n=64][k=32]
#define GST 72
#define TST 40

#define STAGE_A (64 * AST)            // 2560 bf16 (per hi or lo)
#define STAGE_B 2560                  // 32*80 or 64*40 (per hi or lo)
#define STAGE_ELEMS (2 * STAGE_A + 2 * STAGE_B)  // 10240 bf16
#define GEMM_SMEM (NST * STAGE_ELEMS * 2)        // 81920 B

// Scratch (allocation-free rule: __device__ globals)
__device__ float g_Gt[MDIM * MDIM];
__device__ float g_Y [MDIM * NDIM];
__device__ __nv_bfloat16 g_Qh[(size_t)NDIM * NDIM];
__device__ __nv_bfloat16 g_Ql[(size_t)NDIM * NDIM];
__device__ __nv_bfloat16 g_Xh[MDIM * NDIM];
__device__ __nv_bfloat16 g_Xl[MDIM * NDIM];
__device__ __nv_bfloat16 g_Zh[MDIM * NDIM];
__device__ __nv_bfloat16 g_Zl[MDIM * NDIM];

// ---------------------------------------------------------------------------
// PTX helpers
// ---------------------------------------------------------------------------
__device__ __forceinline__ uint32_t sptr(const void* p) {
    return (uint32_t)__cvta_generic_to_shared(p);
}
__device__ __forceinline__ void ldsm4(uint32_t r[4], uint32_t addr) {
    asm volatile("ldmatrix.sync.aligned.m8n8.x4.shared.b16 {%0,%1,%2,%3}, [%4];"
                 : "=r"(r[0]), "=r"(r[1]), "=r"(r[2]), "=r"(r[3]) : "r"(addr));
}
__device__ __forceinline__ void ldsm4t(uint32_t r[4], uint32_t addr) {
    asm volatile("ldmatrix.sync.aligned.m8n8.x4.trans.shared.b16 {%0,%1,%2,%3}, [%4];"
                 : "=r"(r[0]), "=r"(r[1]), "=r"(r[2]), "=r"(r[3]) : "r"(addr));
}
__device__ __forceinline__ void mma16816(float d[4], const uint32_t a[4],
                                         uint32_t b0, uint32_t b1) {
    asm volatile("mma.sync.aligned.m16n8k16.row.col.f32.bf16.bf16.f32 "
                 "{%0,%1,%2,%3}, {%4,%5,%6,%7}, {%8,%9}, {%0,%1,%2,%3};"
                 : "+f"(d[0]), "+f"(d[1]), "+f"(d[2]), "+f"(d[3])
                 : "r"(a[0]), "r"(a[1]), "r"(a[2]), "r"(a[3]),
                   "r"(b0), "r"(b1));
}
__device__ __forceinline__ void cpa16(uint32_t dst, const void* src) {
    asm volatile("cp.async.cg.shared.global [%0], [%1], 16;" :: "r"(dst), "l"(src));
}
__device__ __forceinline__ void cpcommit() { asm volatile("cp.async.commit_group;"); }
__device__ __forceinline__ void cpwait_oldest() {
    asm volatile("cp.async.wait_group %0;" :: "n"(NST - 2));
}

__device__ __forceinline__ void bf16split(float x, __nv_bfloat16& h, __nv_bfloat16& l) {
    h = __float2bfloat16(x);
    l = __float2bfloat16(x - __bfloat162float(h));
}
__device__ __forceinline__ void split2pack(float a, float b, uint32_t& hp, uint32_t& lp) {
    __nv_bfloat16 ha, la, hb, lb;
    bf16split(a, ha, la);
    bf16split(b, hb, lb);
    __nv_bfloat162 h; h.x = ha; h.y = hb;
    __nv_bfloat162 l; l.x = la; l.y = lb;
    hp = *(uint32_t*)&h;
    lp = *(uint32_t*)&l;
}

// ---------------------------------------------------------------------------
// Convert Q_S and X to bf16 hi/lo (one float4 per thread)
// ---------------------------------------------------------------------------
__global__ __launch_bounds__(256) void conv_kernel(const float4* __restrict__ Q,
                                                   const float4* __restrict__ X) {
    const size_t QN4 = (size_t)NDIM * NDIM / 4;
    size_t gid = (size_t)blockIdx.x * 256 + threadIdx.x;
    float4 v;
    __nv_bfloat16 *dh, *dl;
    size_t off;
    if (gid < QN4) { v = Q[gid]; dh = g_Qh; dl = g_Ql; off = gid * 4; }
    else { size_t x = gid - QN4; v = X[x]; dh = g_Xh; dl = g_Xl; off = x * 4; }
    uint32_t h0, l0, h1, l1;
    split2pack(v.x, v.y, h0, l0);
    split2pack(v.z, v.w, h1, l1);
    *(uint2*)(dh + off) = make_uint2(h0, h1);
    *(uint2*)(dl + off) = make_uint2(l0, l1);
}

// ---------------------------------------------------------------------------
// Zero-init Y and Z (outputs accumulated via atomicAdd each replay)
// ---------------------------------------------------------------------------
__global__ __launch_bounds__(256) void zero_kernel(float* __restrict__ a,
                                                   float* __restrict__ b) {
    int i = blockIdx.x * 256 + threadIdx.x;
    a[i] = 0.0f;
    b[i] = 0.0f;
}

// ---------------------------------------------------------------------------
// G~ = 2 * (F^T F) / (||F^T F||_F + 1e-12) - I
// ---------------------------------------------------------------------------
__global__ __launch_bounds__(256) void prep_kernel(const float* __restrict__ F) {
    __shared__ float Fs[MDIM][MDIM + 1];
    __shared__ float FFs[MDIM][MDIM + 4];
    __shared__ float red[8];
    __shared__ float s_inv;

    int t = threadIdx.x;
    for (int o = t; o < MDIM * MDIM; o += 256)
        Fs[o >> 6][o & 63] = F[o];
    __syncthreads();

    int i  = t >> 2;
    int j0 = (t & 3) * 16;
    float acc[16];
#pragma unroll
    for (int u = 0; u < 16; u++) acc[u] = 0.0f;
    for (int k = 0; k < MDIM; k++) {
        float a = Fs[k][i];
#pragma unroll
        for (int u = 0; u < 16; u++) acc[u] = fmaf(a, Fs[k][j0 + u], acc[u]);
    }
    float ss = 0.0f;
#pragma unroll
    for (int u = 0; u < 16; u++) {
        FFs[i][j0 + u] = acc[u];
        ss = fmaf(acc[u], acc[u], ss);
    }
#pragma unroll
    for (int off = 16; off > 0; off >>= 1)
        ss += __shfl_xor_sync(0xffffffffu, ss, off);
    if ((t & 31) == 0) red[t >> 5] = ss;
    __syncthreads();
    if (t == 0) {
        float tot = 0.0f;
        for (int w = 0; w < 8; w++) tot += red[w];
        s_inv = 2.0f / (sqrtf(tot) + 1e-12f);
    }
    __syncthreads();
    float inv = s_inv;
#pragma unroll
    for (int u = 0; u < 16; u++) {
        int j = j0 + u;
        g_Gt[i * MDIM + j] = FFs[i][j] * inv - (i == j ? 1.0f : 0.0f);
    }
}

// ---------------------------------------------------------------------------
// cp.async stage fill: A 64x32 (hi+lo), B 8KB (hi+lo); 4 cpa16 per thread
// ---------------------------------------------------------------------------
template <int TRANSB>
__device__ __forceinline__ void issue_bf(__nv_bfloat16* st,
                                         const __nv_bfloat16* __restrict__ Agh,
                                         const __nv_bfloat16* __restrict__ Agl,
                                         const __nv_bfloat16* __restrict__ Bgh,
                                         const __nv_bfloat16* __restrict__ Bgl,
                                         int kbase, int jg, int t) {
    int ar = t >> 2, ag = (t & 3) * 8;
    cpa16(sptr(st + ar * AST + ag),           Agh + (size_t)ar * NDIM + kbase + ag);
    cpa16(sptr(st + STAGE_A + ar * AST + ag), Agl + (size_t)ar * NDIM + kbase + ag);
    __nv_bfloat16* Bh = st + 2 * STAGE_A;
    __nv_bfloat16* Bl = Bh + STAGE_B;
    if (TRANSB) {
        int br = t >> 2, bg = (t & 3) * 8;   // row = n (0..63), col = k
        size_t bidx = (size_t)(jg + br) * NDIM + kbase + bg;
        cpa16(sptr(Bh + br * B1ST + bg), Bgh + bidx);
        cpa16(sptr(Bl + br * B1ST + bg), Bgl + bidx);
    } else {
        int br = t >> 3, bg = (t & 7) * 8;   // row = k (0..31), col = n
        size_t bidx = (size_t)(kbase + br) * NDIM + jg + bg;
        cpa16(sptr(Bh + br * B0ST + bg), Bgh + bidx);
        cpa16(sptr(Bl + br * B0ST + bg), Bgl + bidx);
    }
}

// ---------------------------------------------------------------------------
// Pure-bf16 tensor GEMM, 3-term hi/lo split, BN=64, K-split x8,
// 4-stage cp.async, single __syncthreads per mainloop iteration.
// TRANSB=0: C += A @ B (B is K x N);  TRANSB=1: C += A @ B^T (B is N x K)
// ---------------------------------------------------------------------------
template <int TRANSB>
__global__ __launch_bounds__(256) void gemm_bf(const __nv_bfloat16* __restrict__ Agh,
                                               const __nv_bfloat16* __restrict__ Agl,
                                               const __nv_bfloat16* __restrict__ Bgh,
                                               const __nv_bfloat16* __restrict__ Bgl,
                                               float* __restrict__ C) {
    extern __shared__ __align__(16) __nv_bfloat16 sm[];
    const int t    = threadIdx.x;
    const int lane = t & 31;
    const int warp = t >> 5;
    const int jg   = blockIdx.x * BN;
    const int k0g  = blockIdx.y * KSPL;
    const int mw   = (warp & 3) * 16;    // warp M offset (0..48)
    const int nw   = (warp >> 2) * 32;   // warp N offset (0 or 32)
    const int lr   = lane & 15;
    const int g8   = (lane >> 4) * 8;

    float acc[4][4];
#pragma unroll
    for (int nt = 0; nt < 4; nt++)
#pragma unroll
        for (int u = 0; u < 4; u++) acc[nt][u] = 0.0f;

#pragma unroll
    for (int c = 0; c < NST - 1; c++) {
        issue_bf<TRANSB>(sm + c * STAGE_ELEMS, Agh, Agl, Bgh, Bgl, k0g + c * KB, jg, t);
        cpcommit();
    }

    for (int c = 0; c < NCH; c++) {
        cpwait_oldest();
        __syncthreads();

        int cn = c + NST - 1;
        if (cn < NCH)
            issue_bf<TRANSB>(sm + (cn % NST) * STAGE_ELEMS, Agh, Agl, Bgh, Bgl,
                             k0g + cn * KB, jg, t);
        cpcommit();

        __nv_bfloat16* st = sm + (c % NST) * STAGE_ELEMS;
        __nv_bfloat16* Ah = st;
        __nv_bfloat16* Al = st + STAGE_A;
        __nv_bfloat16* Bh = st + 2 * STAGE_A;
        __nv_bfloat16* Bl = Bh + STAGE_B;

#pragma unroll
        for (int ks = 0; ks < 2; ks++) {
            uint32_t ah[4], al[4];
            ldsm4(ah, sptr(Ah + (mw + lr) * AST + ks * 16 + g8));
            ldsm4(al, sptr(Al + (mw + lr) * AST + ks * 16 + g8));
#pragma unroll
            for (int half = 0; half < 2; half++) {
                uint32_t bh[4], bl[4];
                if (TRANSB == 0) {
                    ldsm4t(bh, sptr(Bh + (ks * 16 + lr) * B0ST + nw + half * 16 + g8));
                    ldsm4t(bl, sptr(Bl + (ks * 16 + lr) * B0ST + nw + half * 16 + g8));
                    mma16816(acc[half * 2],     ah, bh[0], bh[1]);
                    mma16816(acc[half * 2],     ah, bl[0], bl[1]);
                    mma16816(acc[half * 2],     al, bh[0], bh[1]);
                    mma16816(acc[half * 2 + 1], ah, bh[2], bh[3]);
                    mma16816(acc[half * 2 + 1], ah, bl[2], bl[3]);
                    mma16816(acc[half * 2 + 1], al, bh[2], bh[3]);
                } else {
                    ldsm4(bh, sptr(Bh + (nw + half * 16 + lr) * B1ST + ks * 16 + g8));
                    ldsm4(bl, sptr(Bl + (nw + half * 16 + lr) * B1ST + ks * 16 + g8));
                    mma16816(acc[half * 2],     ah, bh[0], bh[2]);
                    mma16816(acc[half * 2],     ah, bl[0], bl[2]);
                    mma16816(acc[half * 2],     al, bh[0], bh[2]);
                    mma16816(acc[half * 2 + 1], ah, bh[1], bh[3]);
                    mma16816(acc[half * 2 + 1], ah, bl[1], bl[3]);
                    mma16816(acc[half * 2 + 1], al, bh[1], bh[3]);
                }
            }
        }
    }

    const int row = mw + (lane >> 2);
#pragma unroll
    for (int nt = 0; nt < 4; nt++) {
        const int col = jg + nw + (nt >> 1) * 16 + (nt & 1) * 8 + (lane & 3) * 2;
        atomicAdd(&C[(size_t)row * NDIM + col],           acc[nt][0]);
        atomicAdd(&C[(size_t)row * NDIM + col + 1],       acc[nt][1]);
        atomicAdd(&C[(size_t)(row + 8) * NDIM + col],     acc[nt][2]);
        atomicAdd(&C[(size_t)(row + 8) * NDIM + col + 1], acc[nt][3]);
    }
}

// ---------------------------------------------------------------------------
// Tensor-core Chebyshev: G~ fragments resident, T recurrence via 3 rotating
// bf16 hi/lo smem buffers, fp32 fragment accumulation, bf16 hi/lo output.
// ---------------------------------------------------------------------------
__global__ __launch_bounds__(256) void cheb_tc(const float* __restrict__ lamS,
                                               const float* __restrict__ gammap) {
    extern __shared__ __align__(16) __nv_bfloat16 cs[];
    __nv_bfloat16* Gh = cs;
    __nv_bfloat16* Gl = cs + 64 * GST;
    __nv_bfloat16* Tbh = cs + 2 * 64 * GST;
    __nv_bfloat16* Tbl = Tbh + 3 * 64 * TST;
    __shared__ float sh_base[32];
    __shared__ float sh_r[32];

    const int t    = threadIdx.x;
    const int lane = t & 31;
    const int warp = t >> 5;
    const int jg   = blockIdx.x * 32;
    const int mw   = (warp & 3) * 16;
    const int nw   = (warp >> 2) * 16;
    const int lr   = lane & 15;
    const int g8   = (lane >> 4) * 8;

    for (int o = t; o < MDIM * MDIM; o += 256) {
        int r = o >> 6, c = o & 63;
        __nv_bfloat16 h, l;
        bf16split(g_Gt[o], h, l);
        Gh[r * GST + c] = h;
        Gl[r * GST + c] = l;
    }
    for (int o = t; o < MDIM * 32; o += 256) {
        int r = o >> 5, c = o & 31;
        __nv_bfloat16 h, l;
        bf16split(g_Y[(size_t)r * NDIM + jg + c], h, l);
        Tbh[r * TST + c] = h;
        Tbl[r * TST + c] = l;
    }
    if (t < 32) {
        float gam = gammap[0];
        float a = gam * lamS[jg + t];
        float base, r;
        if (fabsf(a) < 1e-7f) {
            base = 1.0f; r = 0.0f;
        } else {
            float b  = 2.0f / a - 1.0f;
            float ab = fabsf(b);
            float s  = sqrtf(fmaf(ab, ab, -1.0f));
            float q  = 1.0f / (ab + s);
            float sg = (a > 0.0f) ? 1.0f : -1.0f;
            r    = sg * q;
            base = (2.0f / a) * sg * 2.0f * q / (1.0f - q * q);
        }
        sh_base[t] = base;
        sh_r[t]    = r;
    }
    __syncthreads();

    uint32_t gh[4][4], gl[4][4];
#pragma unroll
    for (int ks = 0; ks < 4; ks++) {
        ldsm4(gh[ks], sptr(Gh + (mw + lr) * GST + ks * 16 + g8));
        ldsm4(gl[ks], sptr(Gl + (mw + lr) * GST + ks * 16 + g8));
    }

    const int row0 = mw + (lane >> 2);
    float basev[2][2], rv[2][2], pv[2][2];
#pragma unroll
    for (int nt = 0; nt < 2; nt++) {
        int c0 = nw + nt * 8 + 2 * (lane & 3);
        basev[nt][0] = sh_base[c0];     basev[nt][1] = sh_base[c0 + 1];
        rv[nt][0]    = sh_r[c0];        rv[nt][1]    = sh_r[c0 + 1];
        pv[nt][0] = 2.0f * basev[nt][0] * rv[nt][0];
        pv[nt][1] = 2.0f * basev[nt][1] * rv[nt][1];
    }

    float acc[2][4], prev[2][4], tp[2][4];
#pragma unroll
    for (int nt = 0; nt < 2; nt++) {
        int c0 = nw + nt * 8 + 2 * (lane & 3);
        float2 y0 = *(const float2*)&g_Y[(size_t)row0 * NDIM + jg + c0];
        float2 y1 = *(const float2*)&g_Y[(size_t)(row0 + 8) * NDIM + jg + c0];
        prev[nt][0] = y0.x; prev[nt][1] = y0.y; prev[nt][2] = y1.x; prev[nt][3] = y1.y;
        acc[nt][0] = basev[nt][0] * y0.x;
        acc[nt][1] = basev[nt][1] * y0.y;
        acc[nt][2] = basev[nt][0] * y1.x;
        acc[nt][3] = basev[nt][1] * y1.y;
        tp[nt][0] = tp[nt][1] = tp[nt][2] = tp[nt][3] = 0.0f;
    }

    for (int k = 1; k < KCHEB; k++) {
        __syncthreads();
        const __nv_bfloat16* Th = Tbh + ((k - 1) % 3) * (64 * TST);
        const __nv_bfloat16* Tl = Tbl + ((k - 1) % 3) * (64 * TST);
        float u[2][4];
#pragma unroll
        for (int nt = 0; nt < 2; nt++)
#pragma unroll
            for (int i = 0; i < 4; i++) u[nt][i] = 0.0f;
#pragma unroll
        for (int ks = 0; ks < 4; ks++) {
            uint32_t th[4], tl[4];
            ldsm4t(th, sptr(Th + (ks * 16 + lr) * TST + nw + g8));
            ldsm4t(tl, sptr(Tl + (ks * 16 + lr) * TST + nw + g8));
            mma16816(u[0], gh[ks], th[0], th[1]);
            mma16816(u[0], gh[ks], tl[0], tl[1]);
            mma16816(u[0], gl[ks], th[0], th[1]);
            mma16816(u[1], gh[ks], th[2], th[3]);
            mma16816(u[1], gh[ks], tl[2], tl[3]);
            mma16816(u[1], gl[ks], th[2], th[3]);
        }
        float tn[2][4];
#pragma unroll
        for (int nt = 0; nt < 2; nt++)
#pragma unroll
            for (int i = 0; i < 4; i++)
                tn[nt][i] = (k == 1) ? u[nt][i] : fmaf(2.0f, u[nt][i], -tp[nt][i]);
#pragma unroll
        for (int nt = 0; nt < 2; nt++) {
            acc[nt][0] = fmaf(pv[nt][0], tn[nt][0], acc[nt][0]);
            acc[nt][1] = fmaf(pv[nt][1], tn[nt][1], acc[nt][1]);
            acc[nt][2] = fmaf(pv[nt][0], tn[nt][2], acc[nt][2]);
            acc[nt][3] = fmaf(pv[nt][1], tn[nt][3], acc[nt][3]);
            pv[nt][0] *= rv[nt][0];
            pv[nt][1] *= rv[nt][1];
        }
        if (k < KCHEB - 1) {
            __nv_bfloat16* Wh = Tbh + (k % 3) * (64 * TST);
            __nv_bfloat16* Wl = Tbl + (k % 3) * (64 * TST);
#pragma unroll
            for (int nt = 0; nt < 2; nt++) {
                int c0 = nw + nt * 8 + 2 * (lane & 3);
                uint32_t hp, lp;
                split2pack(tn[nt][0], tn[nt][1], hp, lp);
                *(uint32_t*)(Wh + row0 * TST + c0) = hp;
                *(uint32_t*)(Wl + row0 * TST + c0) = lp;
                split2pack(tn[nt][2], tn[nt][3], hp, lp);
                *(uint32_t*)(Wh + (row0 + 8) * TST + c0) = hp;
                *(uint32_t*)(Wl + (row0 + 8) * TST + c0) = lp;
            }
        }
#pragma unroll
        for (int nt = 0; nt < 2; nt++)
#pragma unroll
            for (int i = 0; i < 4; i++) {
                tp[nt][i]   = prev[nt][i];
                prev[nt][i] = tn[nt][i];
            }
    }

#pragma unroll
    for (int nt = 0; nt < 2; nt++) {
        int c0 = nw + nt * 8 + 2 * (lane & 3);
        uint32_t hp, lp;
        split2pack(acc[nt][0], acc[nt][1], hp, lp);
        *(uint32_t*)(g_Zh + (size_t)row0 * NDIM + jg + c0) = hp;
        *(uint32_t*)(g_Zl + (size_t)row0 * NDIM + jg + c0) = lp;
        split2pack(acc[nt][2], acc[nt][3], hp, lp);
        *(uint32_t*)(g_Zh + (size_t)(row0 + 8) * NDIM + jg + c0) = hp;
        *(uint32_t*)(g_Zl + (size_t)(row0 + 8) * NDIM + jg + c0) = lp;
    }
}

#define CHEB_SMEM ((2 * 64 * GST + 6 * 64 * TST) * 2)

// ---------------------------------------------------------------------------
extern "C" void kernel_launch(void* const* d_in, const int* in_sizes, int n_in,
                              void* d_out, int out_size) {
    const float* X    = (const float*)d_in[0];   // (64, 4096)
    const float* F    = (const float*)d_in[1];   // (64, 64)
    const float* Q_S  = (const float*)d_in[2];   // (4096, 4096)
    const float* lamS = (const float*)d_in[3];   // (4096,)
    const float* gam  = (const float*)d_in[4];   // scalar
    float* Z = (float*)d_out;                    // (64, 4096)

    float *Y;
    __nv_bfloat16 *Qh, *Ql, *Xh, *Xl, *Zh, *Zl;
    cudaGetSymbolAddress((void**)&Y,  g_Y);
    cudaGetSymbolAddress((void**)&Qh, g_Qh);
    cudaGetSymbolAddress((void**)&Ql, g_Ql);
    cudaGetSymbolAddress((void**)&Xh, g_Xh);
    cudaGetSymbolAddress((void**)&Xl, g_Xl);
    cudaGetSymbolAddress((void**)&Zh, g_Zh);
    cudaGetSymbolAddress((void**)&Zl, g_Zl);

    static bool attr_set = false;
    if (!attr_set) {
        cudaFuncSetAttribute(gemm_bf<0>, cudaFuncAttributeMaxDynamicSharedMemorySize, GEMM_SMEM);
        cudaFuncSetAttribute(gemm_bf<1>, cudaFuncAttributeMaxDynamicSharedMemorySize, GEMM_SMEM);
        cudaFuncSetAttribute(cheb_tc,    cudaFuncAttributeMaxDynamicSharedMemorySize, CHEB_SMEM);
        attr_set = true;
    }

    const int conv_blocks = (NDIM * NDIM / 4 + MDIM * NDIM / 4) / 256;  // 16640
    dim3 ggrid(NDIM / BN, NSPLIT);

    conv_kernel<<<conv_blocks, 256>>>((const float4*)Q_S, (const float4*)X);
    zero_kernel<<<(MDIM * NDIM) / 256, 256>>>(Y, Z);
    prep_kernel<<<1, 256>>>(F);
    gemm_bf<0><<<ggrid, 256, GEMM_SMEM>>>(Xh, Xl, Qh, Ql, Y);   // Y += X @ Q_S
    cheb_tc<<<NDIM / 32, 256, CHEB_SMEM>>>(lamS, gam);          // Zh/Zl = f(G) Y
    gemm_bf<1><<<ggrid, 256, GEMM_SMEM>>>(Zh, Zl, Qh, Ql, Z);   // Z += Z~ @ Q_S^T
}

// round 8
// speedup vs baseline: 2.9286x; 1.0293x over previous
#include <cuda_runtime.h>
#include <cuda_bf16.h>
#include <cstdint>
#include <math.h>

#define MDIM 64
#define NDIM 4096
#define BN   64
#define KB   64
#define NST  3
#define KSPL 1024
#define NCH  (KSPL / KB)     // 16 chunks per K-split
#define NSPLIT (NDIM / KSPL) // 4
#define KCHEB 14

#define ROWB 144                       // smem row stride bytes (64 bf16 =128B data +16 pad)
#define TILE_BYTES (64 * ROWB)         // 9216
#define STAGE_BYTES (4 * TILE_BYTES)   // 36864 (Ah, Al, Bh, Bl)
#define GEMM_SMEM (128 + NST * STAGE_BYTES)   // 110720

#define GST 72
#define TST 40

// Scratch (allocation-free rule: __device__ globals)
__device__ float g_Gt[MDIM * MDIM];
__device__ float g_Y [MDIM * NDIM];
__device__ __align__(128) __nv_bfloat16 g_Qh[(size_t)NDIM * NDIM];
__device__ __align__(128) __nv_bfloat16 g_Ql[(size_t)NDIM * NDIM];
__device__ __align__(128) __nv_bfloat16 g_Xh[MDIM * NDIM];
__device__ __align__(128) __nv_bfloat16 g_Xl[MDIM * NDIM];
__device__ __align__(128) __nv_bfloat16 g_Zh[MDIM * NDIM];
__device__ __align__(128) __nv_bfloat16 g_Zl[MDIM * NDIM];

// ---------------------------------------------------------------------------
// PTX helpers
// ---------------------------------------------------------------------------
__device__ __forceinline__ uint32_t sptr(const void* p) {
    return (uint32_t)__cvta_generic_to_shared(p);
}
__device__ __forceinline__ void ldsm4(uint32_t r[4], uint32_t addr) {
    asm volatile("ldmatrix.sync.aligned.m8n8.x4.shared.b16 {%0,%1,%2,%3}, [%4];"
                 : "=r"(r[0]), "=r"(r[1]), "=r"(r[2]), "=r"(r[3]) : "r"(addr));
}
__device__ __forceinline__ void ldsm4t(uint32_t r[4], uint32_t addr) {
    asm volatile("ldmatrix.sync.aligned.m8n8.x4.trans.shared.b16 {%0,%1,%2,%3}, [%4];"
                 : "=r"(r[0]), "=r"(r[1]), "=r"(r[2]), "=r"(r[3]) : "r"(addr));
}
__device__ __forceinline__ void mma16816(float d[4], const uint32_t a[4],
                                         uint32_t b0, uint32_t b1) {
    asm volatile("mma.sync.aligned.m16n8k16.row.col.f32.bf16.bf16.f32 "
                 "{%0,%1,%2,%3}, {%4,%5,%6,%7}, {%8,%9}, {%0,%1,%2,%3};"
                 : "+f"(d[0]), "+f"(d[1]), "+f"(d[2]), "+f"(d[3])
                 : "r"(a[0]), "r"(a[1]), "r"(a[2]), "r"(a[3]),
                   "r"(b0), "r"(b1));
}
// TMA 1D bulk: global -> shared, completion via mbarrier tx-bytes
__device__ __forceinline__ void bulk_ld(uint32_t dst, const void* src,
                                        uint32_t bytes, uint32_t mbar) {
    asm volatile("cp.async.bulk.shared::cluster.global.mbarrier::complete_tx::bytes "
                 "[%0], [%1], %2, [%3];"
                 :: "r"(dst), "l"(src), "r"(bytes), "r"(mbar) : "memory");
}
__device__ __forceinline__ void mbar_init(uint32_t a, uint32_t cnt) {
    asm volatile("mbarrier.init.shared.b64 [%0], %1;" :: "r"(a), "r"(cnt) : "memory");
}
__device__ __forceinline__ void mbar_expect_tx(uint32_t a, uint32_t bytes) {
    asm volatile("mbarrier.arrive.expect_tx.shared.b64 _, [%0], %1;"
                 :: "r"(a), "r"(bytes) : "memory");
}
__device__ __forceinline__ void mbar_arrive(uint32_t a) {
    asm volatile("mbarrier.arrive.shared.b64 _, [%0];" :: "r"(a) : "memory");
}
__device__ __forceinline__ void mbar_wait(uint32_t a, uint32_t parity) {
    asm volatile(
        "{\n\t.reg .pred P;\n\t"
        "WAIT_%=:\n\t"
        "mbarrier.try_wait.parity.acquire.cta.shared::cta.b64 P, [%0], %1, 0x989680;\n\t"
        "@P bra.uni DONE_%=;\n\t"
        "bra.uni WAIT_%=;\n\t"
        "DONE_%=:\n\t}"
        :: "r"(a), "r"(parity) : "memory");
}
__device__ __forceinline__ void fence_async_init() {
    asm volatile("fence.proxy.async.shared::cta;" ::: "memory");
}

__device__ __forceinline__ void bf16split(float x, __nv_bfloat16& h, __nv_bfloat16& l) {
    h = __float2bfloat16(x);
    l = __float2bfloat16(x - __bfloat162float(h));
}
__device__ __forceinline__ void split2pack(float a, float b, uint32_t& hp, uint32_t& lp) {
    __nv_bfloat16 ha, la, hb, lb;
    bf16split(a, ha, la);
    bf16split(b, hb, lb);
    __nv_bfloat162 h; h.x = ha; h.y = hb;
    __nv_bfloat162 l; l.x = la; l.y = lb;
    hp = *(uint32_t*)&h;
    lp = *(uint32_t*)&l;
}

// ---------------------------------------------------------------------------
// Convert Q_S and X to bf16 hi/lo (one float4 per thread)
// ---------------------------------------------------------------------------
__global__ __launch_bounds__(256) void conv_kernel(const float4* __restrict__ Q,
                                                   const float4* __restrict__ X) {
    const size_t QN4 = (size_t)NDIM * NDIM / 4;
    size_t gid = (size_t)blockIdx.x * 256 + threadIdx.x;
    float4 v;
    __nv_bfloat16 *dh, *dl;
    size_t off;
    if (gid < QN4) { v = Q[gid]; dh = g_Qh; dl = g_Ql; off = gid * 4; }
    else { size_t x = gid - QN4; v = X[x]; dh = g_Xh; dl = g_Xl; off = x * 4; }
    uint32_t h0, l0, h1, l1;
    split2pack(v.x, v.y, h0, l0);
    split2pack(v.z, v.w, h1, l1);
    *(uint2*)(dh + off) = make_uint2(h0, h1);
    *(uint2*)(dl + off) = make_uint2(l0, l1);
}

// ---------------------------------------------------------------------------
// Zero-init Y and Z (outputs accumulated via atomicAdd each replay)
// ---------------------------------------------------------------------------
__global__ __launch_bounds__(256) void zero_kernel(float* __restrict__ a,
                                                   float* __restrict__ b) {
    int i = blockIdx.x * 256 + threadIdx.x;
    a[i] = 0.0f;
    b[i] = 0.0f;
}

// ---------------------------------------------------------------------------
// G~ = 2 * (F^T F) / (||F^T F||_F + 1e-12) - I
// ---------------------------------------------------------------------------
__global__ __launch_bounds__(256) void prep_kernel(const float* __restrict__ F) {
    __shared__ float Fs[MDIM][MDIM + 1];
    __shared__ float FFs[MDIM][MDIM + 4];
    __shared__ float red[8];
    __shared__ float s_inv;

    int t = threadIdx.x;
    for (int o = t; o < MDIM * MDIM; o += 256)
        Fs[o >> 6][o & 63] = F[o];
    __syncthreads();

    int i  = t >> 2;
    int j0 = (t & 3) * 16;
    float acc[16];
#pragma unroll
    for (int u = 0; u < 16; u++) acc[u] = 0.0f;
    for (int k = 0; k < MDIM; k++) {
        float a = Fs[k][i];
#pragma unroll
        for (int u = 0; u < 16; u++) acc[u] = fmaf(a, Fs[k][j0 + u], acc[u]);
    }
    float ss = 0.0f;
#pragma unroll
    for (int u = 0; u < 16; u++) {
        FFs[i][j0 + u] = acc[u];
        ss = fmaf(acc[u], acc[u], ss);
    }
#pragma unroll
    for (int off = 16; off > 0; off >>= 1)
        ss += __shfl_xor_sync(0xffffffffu, ss, off);
    if ((t & 31) == 0) red[t >> 5] = ss;
    __syncthreads();
    if (t == 0) {
        float tot = 0.0f;
        for (int w = 0; w < 8; w++) tot += red[w];
        s_inv = 2.0f / (sqrtf(tot) + 1e-12f);
    }
    __syncthreads();
    float inv = s_inv;
#pragma unroll
    for (int u = 0; u < 16; u++) {
        int j = j0 + u;
        g_Gt[i * MDIM + j] = FFs[i][j] * inv - (i == j ? 1.0f : 0.0f);
    }
}

// ---------------------------------------------------------------------------
// TMA-staged pure-bf16 tensor GEMM, 3-term hi/lo split, BN=64, KB=64,
// NST=3 mbarrier ring, one 128B bulk copy per thread per chunk.
// TRANSB=0: C += A @ B (B is K x N);  TRANSB=1: C += A @ B^T (B is N x K)
// ---------------------------------------------------------------------------
template <int TRANSB>
__global__ __launch_bounds__(256) void gemm_bf(const __nv_bfloat16* __restrict__ Agh,
                                               const __nv_bfloat16* __restrict__ Agl,
                                               const __nv_bfloat16* __restrict__ Bgh,
                                               const __nv_bfloat16* __restrict__ Bgl,
                                               float* __restrict__ C) {
    extern __shared__ __align__(128) char sm[];
    const uint32_t smb = sptr(sm);

    const int t    = threadIdx.x;
    const int lane = t & 31;
    const int warp = t >> 5;
    const int jg   = blockIdx.x * BN;
    const int k0g  = blockIdx.y * KSPL;
    const int mw   = (warp & 3) * 16;    // warp M offset
    const int nw   = (warp >> 2) * 32;   // warp N offset (0 or 32)
    const int lr   = lane & 15;
    const int g8   = (lane >> 4) * 8;

    // mbarriers: full[s] at smb + s*16, empty[s] at smb + s*16 + 8
    if (t == 0) {
#pragma unroll
        for (int s = 0; s < NST; s++) {
            mbar_init(smb + s * 16, 256);
            mbar_init(smb + s * 16 + 8, 256);
        }
        fence_async_init();
    }
    __syncthreads();

    // this thread's copy role: tile (0=Ah,1=Al,2=Bh,3=Bl), row within tile
    const int tile = t >> 6;
    const int rowc = t & 63;
    const __nv_bfloat16* srcbase;
    size_t rowoff;   // element offset of row start, before kbase/jg column offset
    if (tile == 0)      { srcbase = Agh; rowoff = (size_t)rowc * NDIM; }
    else if (tile == 1) { srcbase = Agl; rowoff = (size_t)rowc * NDIM; }
    else {
        const __nv_bfloat16* bb = (tile == 2) ? Bgh : Bgl;
        srcbase = bb;
        rowoff = TRANSB ? (size_t)(jg + rowc) * NDIM : (size_t)rowc * NDIM + jg;
    }

    float acc[4][4];
#pragma unroll
    for (int nt = 0; nt < 4; nt++)
#pragma unroll
        for (int u = 0; u < 4; u++) acc[nt][u] = 0.0f;

    // prologue: fill stages 0..NST-2
#pragma unroll
    for (int cn = 0; cn < NST - 1; cn++) {
        int kbase = k0g + cn * KB;
        size_t src = rowoff + ((TRANSB || tile < 2) ? (size_t)kbase
                                                    : (size_t)kbase * NDIM);
        uint32_t full = smb + (cn % NST) * 16;
        uint32_t dst  = smb + 128 + (cn % NST) * STAGE_BYTES + tile * TILE_BYTES + rowc * ROWB;
        mbar_expect_tx(full, 128);
        bulk_ld(dst, srcbase + src, 128, full);
    }

    for (int c = 0; c < NCH; c++) {
        // issue chunk cn into its stage (after the stage drains)
        int cn = c + NST - 1;
        if (cn < NCH) {
            int s2 = cn % NST;
            if (cn >= NST)
                mbar_wait(smb + s2 * 16 + 8, ((cn - NST) / NST) & 1);
            int kbase = k0g + cn * KB;
            size_t src = rowoff + ((TRANSB || tile < 2) ? (size_t)kbase
                                                        : (size_t)kbase * NDIM);
            uint32_t full = smb + s2 * 16;
            uint32_t dst  = smb + 128 + s2 * STAGE_BYTES + tile * TILE_BYTES + rowc * ROWB;
            mbar_expect_tx(full, 128);
            bulk_ld(dst, srcbase + src, 128, full);
        }

        // consume chunk c
        const int s = c % NST;
        mbar_wait(smb + s * 16, (c / NST) & 1);

        const uint32_t Ah = smb + 128 + s * STAGE_BYTES;
        const uint32_t Al = Ah + TILE_BYTES;
        const uint32_t Bh = Ah + 2 * TILE_BYTES;
        const uint32_t Bl = Ah + 3 * TILE_BYTES;

#pragma unroll
        for (int ks = 0; ks < 4; ks++) {
            uint32_t ah[4], al[4];
            ldsm4(ah, Ah + (mw + lr) * ROWB + (ks * 16 + g8) * 2);
            ldsm4(al, Al + (mw + lr) * ROWB + (ks * 16 + g8) * 2);
#pragma unroll
            for (int half = 0; half < 2; half++) {
                uint32_t bh[4], bl[4];
                if (TRANSB == 0) {
                    ldsm4t(bh, Bh + (ks * 16 + lr) * ROWB + (nw + half * 16 + g8) * 2);
                    ldsm4t(bl, Bl + (ks * 16 + lr) * ROWB + (nw + half * 16 + g8) * 2);
                    mma16816(acc[half * 2],     ah, bh[0], bh[1]);
                    mma16816(acc[half * 2],     ah, bl[0], bl[1]);
                    mma16816(acc[half * 2],     al, bh[0], bh[1]);
                    mma16816(acc[half * 2 + 1], ah, bh[2], bh[3]);
                    mma16816(acc[half * 2 + 1], ah, bl[2], bl[3]);
                    mma16816(acc[half * 2 + 1], al, bh[2], bh[3]);
                } else {
                    ldsm4(bh, Bh + (nw + half * 16 + lr) * ROWB + (ks * 16 + g8) * 2);
                    ldsm4(bl, Bl + (nw + half * 16 + lr) * ROWB + (ks * 16 + g8) * 2);
                    mma16816(acc[half * 2],     ah, bh[0], bh[2]);
                    mma16816(acc[half * 2],     ah, bl[0], bl[2]);
                    mma16816(acc[half * 2],     al, bh[0], bh[2]);
                    mma16816(acc[half * 2 + 1], ah, bh[1], bh[3]);
                    mma16816(acc[half * 2 + 1], ah, bl[1], bl[3]);
                    mma16816(acc[half * 2 + 1], al, bh[1], bh[3]);
                }
            }
        }
        mbar_arrive(smb + s * 16 + 8);   // stage drained
    }

    const int row = mw + (lane >> 2);
#pragma unroll
    for (int nt = 0; nt < 4; nt++) {
        const int col = jg + nw + (nt >> 1) * 16 + (nt & 1) * 8 + (lane & 3) * 2;
        atomicAdd(&C[(size_t)row * NDIM + col],           acc[nt][0]);
        atomicAdd(&C[(size_t)row * NDIM + col + 1],       acc[nt][1]);
        atomicAdd(&C[(size_t)(row + 8) * NDIM + col],     acc[nt][2]);
        atomicAdd(&C[(size_t)(row + 8) * NDIM + col + 1], acc[nt][3]);
    }
}

// ---------------------------------------------------------------------------
// Tensor-core Chebyshev: G~ fragments resident, T recurrence via 3 rotating
// bf16 hi/lo smem buffers, fp32 fragment accumulation, bf16 hi/lo output.
// ---------------------------------------------------------------------------
__global__ __launch_bounds__(256) void cheb_tc(const float* __restrict__ lamS,
                                               const float* __restrict__ gammap) {
    extern __shared__ __align__(16) __nv_bfloat16 cs[];
    __nv_bfloat16* Gh = cs;
    __nv_bfloat16* Gl = cs + 64 * GST;
    __nv_bfloat16* Tbh = cs + 2 * 64 * GST;
    __nv_bfloat16* Tbl = Tbh + 3 * 64 * TST;
    __shared__ float sh_base[32];
    __shared__ float sh_r[32];

    const int t    = threadIdx.x;
    const int lane = t & 31;
    const int warp = t >> 5;
    const int jg   = blockIdx.x * 32;
    const int mw   = (warp & 3) * 16;
    const int nw   = (warp >> 2) * 16;
    const int lr   = lane & 15;
    const int g8   = (lane >> 4) * 8;

    for (int o = t; o < MDIM * MDIM; o += 256) {
        int r = o >> 6, c = o & 63;
        __nv_bfloat16 h, l;
        bf16split(g_Gt[o], h, l);
        Gh[r * GST + c] = h;
        Gl[r * GST + c] = l;
    }
    for (int o = t; o < MDIM * 32; o += 256) {
        int r = o >> 5, c = o & 31;
        __nv_bfloat16 h, l;
        bf16split(g_Y[(size_t)r * NDIM + jg + c], h, l);
        Tbh[r * TST + c] = h;
        Tbl[r * TST + c] = l;
    }
    if (t < 32) {
        float gam = gammap[0];
        float a = gam * lamS[jg + t];
        float base, r;
        if (fabsf(a) < 1e-7f) {
            base = 1.0f; r = 0.0f;
        } else {
            float b  = 2.0f / a - 1.0f;
            float ab = fabsf(b);
            float s  = sqrtf(fmaf(ab, ab, -1.0f));
            float q  = 1.0f / (ab + s);
            float sg = (a > 0.0f) ? 1.0f : -1.0f;
            r    = sg * q;
            base = (2.0f / a) * sg * 2.0f * q / (1.0f - q * q);
        }
        sh_base[t] = base;
        sh_r[t]    = r;
    }
    __syncthreads();

    uint32_t gh[4][4], gl[4][4];
#pragma unroll
    for (int ks = 0; ks < 4; ks++) {
        ldsm4(gh[ks], sptr(Gh + (mw + lr) * GST + ks * 16 + g8));
        ldsm4(gl[ks], sptr(Gl + (mw + lr) * GST + ks * 16 + g8));
    }

    const int row0 = mw + (lane >> 2);
    float basev[2][2], rv[2][2], pv[2][2];
#pragma unroll
    for (int nt = 0; nt < 2; nt++) {
        int c0 = nw + nt * 8 + 2 * (lane & 3);
        basev[nt][0] = sh_base[c0];     basev[nt][1] = sh_base[c0 + 1];
        rv[nt][0]    = sh_r[c0];        rv[nt][1]    = sh_r[c0 + 1];
        pv[nt][0] = 2.0f * basev[nt][0] * rv[nt][0];
        pv[nt][1] = 2.0f * basev[nt][1] * rv[nt][1];
    }

    float acc[2][4], prev[2][4], tp[2][4];
#pragma unroll
    for (int nt = 0; nt < 2; nt++) {
        int c0 = nw + nt * 8 + 2 * (lane & 3);
        float2 y0 = *(const float2*)&g_Y[(size_t)row0 * NDIM + jg + c0];
        float2 y1 = *(const float2*)&g_Y[(size_t)(row0 + 8) * NDIM + jg + c0];
        prev[nt][0] = y0.x; prev[nt][1] = y0.y; prev[nt][2] = y1.x; prev[nt][3] = y1.y;
        acc[nt][0] = basev[nt][0] * y0.x;
        acc[nt][1] = basev[nt][1] * y0.y;
        acc[nt][2] = basev[nt][0] * y1.x;
        acc[nt][3] = basev[nt][1] * y1.y;
        tp[nt][0] = tp[nt][1] = tp[nt][2] = tp[nt][3] = 0.0f;
    }

    for (int k = 1; k < KCHEB; k++) {
        __syncthreads();
        const __nv_bfloat16* Th = Tbh + ((k - 1) % 3) * (64 * TST);
        const __nv_bfloat16* Tl = Tbl + ((k - 1) % 3) * (64 * TST);
        float u[2][4];
#pragma unroll
        for (int nt = 0; nt < 2; nt++)
#pragma unroll
            for (int i = 0; i < 4; i++) u[nt][i] = 0.0f;
#pragma unroll
        for (int ks = 0; ks < 4; ks++) {
            uint32_t th[4], tl[4];
            ldsm4t(th, sptr(Th + (ks * 16 + lr) * TST + nw + g8));
            ldsm4t(tl, sptr(Tl + (ks * 16 + lr) * TST + nw + g8));
            mma16816(u[0], gh[ks], th[0], th[1]);
            mma16816(u[0], gh[ks], tl[0], tl[1]);
            mma16816(u[0], gl[ks], th[0], th[1]);
            mma16816(u[1], gh[ks], th[2], th[3]);
            mma16816(u[1], gh[ks], tl[2], tl[3]);
            mma16816(u[1], gl[ks], th[2], th[3]);
        }
        float tn[2][4];
#pragma unroll
        for (int nt = 0; nt < 2; nt++)
#pragma unroll
            for (int i = 0; i < 4; i++)
                tn[nt][i] = (k == 1) ? u[nt][i] : fmaf(2.0f, u[nt][i], -tp[nt][i]);
#pragma unroll
        for (int nt = 0; nt < 2; nt++) {
            acc[nt][0] = fmaf(pv[nt][0], tn[nt][0], acc[nt][0]);
            acc[nt][1] = fmaf(pv[nt][1], tn[nt][1], acc[nt][1]);
            acc[nt][2] = fmaf(pv[nt][0], tn[nt][2], acc[nt][2]);
            acc[nt][3] = fmaf(pv[nt][1], tn[nt][3], acc[nt][3]);
            pv[nt][0] *= rv[nt][0];
            pv[nt][1] *= rv[nt][1];
        }
        if (k < KCHEB - 1) {
            __nv_bfloat16* Wh = Tbh + (k % 3) * (64 * TST);
            __nv_bfloat16* Wl = Tbl + (k % 3) * (64 * TST);
#pragma unroll
            for (int nt = 0; nt < 2; nt++) {
                int c0 = nw + nt * 8 + 2 * (lane & 3);
                uint32_t hp, lp;
                split2pack(tn[nt][0], tn[nt][1], hp, lp);
                *(uint32_t*)(Wh + row0 * TST + c0) = hp;
                *(uint32_t*)(Wl + row0 * TST + c0) = lp;
                split2pack(tn[nt][2], tn[nt][3], hp, lp);
                *(uint32_t*)(Wh + (row0 + 8) * TST + c0) = hp;
                *(uint32_t*)(Wl + (row0 + 8) * TST + c0) = lp;
            }
        }
#pragma unroll
        for (int nt = 0; nt < 2; nt++)
#pragma unroll
            for (int i = 0; i < 4; i++) {
                tp[nt][i]   = prev[nt][i];
                prev[nt][i] = tn[nt][i];
            }
    }

#pragma unroll
    for (int nt = 0; nt < 2; nt++) {
        int c0 = nw + nt * 8 + 2 * (lane & 3);
        uint32_t hp, lp;
        split2pack(acc[nt][0], acc[nt][1], hp, lp);
        *(uint32_t*)(g_Zh + (size_t)row0 * NDIM + jg + c0) = hp;
        *(uint32_t*)(g_Zl + (size_t)row0 * NDIM + jg + c0) = lp;
        split2pack(acc[nt][2], acc[nt][3], hp, lp);
        *(uint32_t*)(g_Zh + (size_t)(row0 + 8) * NDIM + jg + c0) = hp;
        *(uint32_t*)(g_Zl + (size_t)(row0 + 8) * NDIM + jg + c0) = lp;
    }
}

#define CHEB_SMEM ((2 * 64 * GST + 6 * 64 * TST) * 2)

// ---------------------------------------------------------------------------
extern "C" void kernel_launch(void* const* d_in, const int* in_sizes, int n_in,
                              void* d_out, int out_size) {
    const float* X    = (const float*)d_in[0];   // (64, 4096)
    const float* F    = (const float*)d_in[1];   // (64, 64)
    const float* Q_S  = (const float*)d_in[2];   // (4096, 4096)
    const float* lamS = (const float*)d_in[3];   // (4096,)
    const float* gam  = (const float*)d_in[4];   // scalar
    float* Z = (float*)d_out;                    // (64, 4096)

    float *Y;
    __nv_bfloat16 *Qh, *Ql, *Xh, *Xl, *Zh, *Zl;
    cudaGetSymbolAddress((void**)&Y,  g_Y);
    cudaGetSymbolAddress((void**)&Qh, g_Qh);
    cudaGetSymbolAddress((void**)&Ql, g_Ql);
    cudaGetSymbolAddress((void**)&Xh, g_Xh);
    cudaGetSymbolAddress((void**)&Xl, g_Xl);
    cudaGetSymbolAddress((void**)&Zh, g_Zh);
    cudaGetSymbolAddress((void**)&Zl, g_Zl);

    static bool attr_set = false;
    if (!attr_set) {
        cudaFuncSetAttribute(gemm_bf<0>, cudaFuncAttributeMaxDynamicSharedMemorySize, GEMM_SMEM);
        cudaFuncSetAttribute(gemm_bf<1>, cudaFuncAttributeMaxDynamicSharedMemorySize, GEMM_SMEM);
        cudaFuncSetAttribute(cheb_tc,    cudaFuncAttributeMaxDynamicSharedMemorySize, CHEB_SMEM);
        attr_set = true;
    }

    const int conv_blocks = (NDIM * NDIM / 4 + MDIM * NDIM / 4) / 256;  // 16640
    dim3 ggrid(NDIM / BN, NSPLIT);

    conv_kernel<<<conv_blocks, 256>>>((const float4*)Q_S, (const float4*)X);
    zero_kernel<<<(MDIM * NDIM) / 256, 256>>>(Y, Z);
    prep_kernel<<<1, 256>>>(F);
    gemm_bf<0><<<ggrid, 256, GEMM_SMEM>>>(Xh, Xl, Qh, Ql, Y);   // Y += X @ Q_S
    cheb_tc<<<NDIM / 32, 256, CHEB_SMEM>>>(lamS, gam);          // Zh/Zl = f(G) Y
    gemm_bf<1><<<ggrid, 256, GEMM_SMEM>>>(Zh, Zl, Qh, Ql, Z);   // Z += Z~ @ Q_S^T
}

// round 10
// speedup vs baseline: 2.9346x; 1.0021x over previous
#include <cuda_runtime.h>
#include <cuda_bf16.h>
#include <cstdint>
#include <math.h>

#define MDIM 64
#define NDIM 4096
#define BN   64
#define KB   64
#define NST  3
#define KSPL 1024
#define NCH  (KSPL / KB)     // 16 chunks per K-split
#define NSPLIT (NDIM / KSPL) // 4
#define KCHEB 14

#define ROWB 144                       // smem row stride bytes (128B data + 16 pad)
#define TILE_BYTES (64 * ROWB)         // 9216
#define STAGE_BYTES (4 * TILE_BYTES)   // 36864 (Ah, Al, Bh, Bl)
#define TX_BYTES (256 * 128)           // 32768 actual bytes delivered per stage
#define GEMM_SMEM (128 + NST * STAGE_BYTES)   // 110720

#define GST 72
#define TST 40

// Scratch (allocation-free rule: __device__ globals)
__device__ float g_Gt[MDIM * MDIM];
__device__ float g_Y [MDIM * NDIM];
__device__ __align__(128) __nv_bfloat16 g_Qh[(size_t)NDIM * NDIM];
__device__ __align__(128) __nv_bfloat16 g_Ql[(size_t)NDIM * NDIM];
__device__ __align__(128) __nv_bfloat16 g_Xh[MDIM * NDIM];
__device__ __align__(128) __nv_bfloat16 g_Xl[MDIM * NDIM];
__device__ __align__(128) __nv_bfloat16 g_Zh[MDIM * NDIM];
__device__ __align__(128) __nv_bfloat16 g_Zl[MDIM * NDIM];

// ---------------------------------------------------------------------------
// PTX helpers
// ---------------------------------------------------------------------------
__device__ __forceinline__ uint32_t sptr(const void* p) {
    return (uint32_t)__cvta_generic_to_shared(p);
}
__device__ __forceinline__ void ldsm4(uint32_t r[4], uint32_t addr) {
    asm volatile("ldmatrix.sync.aligned.m8n8.x4.shared.b16 {%0,%1,%2,%3}, [%4];"
                 : "=r"(r[0]), "=r"(r[1]), "=r"(r[2]), "=r"(r[3]) : "r"(addr));
}
__device__ __forceinline__ void ldsm4t(uint32_t r[4], uint32_t addr) {
    asm volatile("ldmatrix.sync.aligned.m8n8.x4.trans.shared.b16 {%0,%1,%2,%3}, [%4];"
                 : "=r"(r[0]), "=r"(r[1]), "=r"(r[2]), "=r"(r[3]) : "r"(addr));
}
__device__ __forceinline__ void mma16816(float d[4], const uint32_t a[4],
                                         uint32_t b0, uint32_t b1) {
    asm volatile("mma.sync.aligned.m16n8k16.row.col.f32.bf16.bf16.f32 "
                 "{%0,%1,%2,%3}, {%4,%5,%6,%7}, {%8,%9}, {%0,%1,%2,%3};"
                 : "+f"(d[0]), "+f"(d[1]), "+f"(d[2]), "+f"(d[3])
                 : "r"(a[0]), "r"(a[1]), "r"(a[2]), "r"(a[3]),
                   "r"(b0), "r"(b1));
}
// TMA 1D bulk: global -> shared, completion via mbarrier tx-bytes
__device__ __forceinline__ void bulk_ld(uint32_t dst, const void* src,
                                        uint32_t bytes, uint32_t mbar) {
    asm volatile("cp.async.bulk.shared::cluster.global.mbarrier::complete_tx::bytes "
                 "[%0], [%1], %2, [%3];"
                 :: "r"(dst), "l"(src), "r"(bytes), "r"(mbar) : "memory");
}
__device__ __forceinline__ void mbar_init(uint32_t a, uint32_t cnt) {
    asm volatile("mbarrier.init.shared.b64 [%0], %1;" :: "r"(a), "r"(cnt) : "memory");
}
__device__ __forceinline__ void mbar_expect_tx(uint32_t a, uint32_t bytes) {
    asm volatile("mbarrier.arrive.expect_tx.shared.b64 _, [%0], %1;"
                 :: "r"(a), "r"(bytes) : "memory");
}
__device__ __forceinline__ void mbar_arrive(uint32_t a) {
    asm volatile("mbarrier.arrive.shared.b64 _, [%0];" :: "r"(a) : "memory");
}
__device__ __forceinline__ void mbar_wait(uint32_t a, uint32_t parity) {
    asm volatile(
        "{\n\t.reg .pred P;\n\t"
        "WAIT_%=:\n\t"
        "mbarrier.try_wait.parity.acquire.cta.shared::cta.b64 P, [%0], %1, 0x989680;\n\t"
        "@P bra.uni DONE_%=;\n\t"
        "bra.uni WAIT_%=;\n\t"
        "DONE_%=:\n\t}"
        :: "r"(a), "r"(parity) : "memory");
}
__device__ __forceinline__ void fence_async_init() {
    asm volatile("fence.proxy.async.shared::cta;" ::: "memory");
}

__device__ __forceinline__ void bf16split(float x, __nv_bfloat16& h, __nv_bfloat16& l) {
    h = __float2bfloat16(x);
    l = __float2bfloat16(x - __bfloat162float(h));
}
__device__ __forceinline__ void split2pack(float a, float b, uint32_t& hp, uint32_t& lp) {
    __nv_bfloat16 ha, la, hb, lb;
    bf16split(a, ha, la);
    bf16split(b, hb, lb);
    __nv_bfloat162 h; h.x = ha; h.y = hb;
    __nv_bfloat162 l; l.x = la; l.y = lb;
    hp = *(uint32_t*)&h;
    lp = *(uint32_t*)&l;
}

// ---------------------------------------------------------------------------
// Convert Q_S and X to bf16 hi/lo (one float4 per thread)
// ---------------------------------------------------------------------------
__global__ __launch_bounds__(256) void conv_kernel(const float4* __restrict__ Q,
                                                   const float4* __restrict__ X) {
    const size_t QN4 = (size_t)NDIM * NDIM / 4;
    size_t gid = (size_t)blockIdx.x * 256 + threadIdx.x;
    float4 v;
    __nv_bfloat16 *dh, *dl;
    size_t off;
    if (gid < QN4) { v = Q[gid]; dh = g_Qh; dl = g_Ql; off = gid * 4; }
    else { size_t x = gid - QN4; v = X[x]; dh = g_Xh; dl = g_Xl; off = x * 4; }
    uint32_t h0, l0, h1, l1;
    split2pack(v.x, v.y, h0, l0);
    split2pack(v.z, v.w, h1, l1);
    *(uint2*)(dh + off) = make_uint2(h0, h1);
    *(uint2*)(dl + off) = make_uint2(l0, l1);
}

// ---------------------------------------------------------------------------
// Zero-init Y and Z (outputs accumulated via atomicAdd each replay)
// ---------------------------------------------------------------------------
__global__ __launch_bounds__(256) void zero_kernel(float* __restrict__ a,
                                                   float* __restrict__ b) {
    int i = blockIdx.x * 256 + threadIdx.x;
    a[i] = 0.0f;
    b[i] = 0.0f;
}

// ---------------------------------------------------------------------------
// G~ = 2 * (F^T F) / (||F^T F||_F + 1e-12) - I
// ---------------------------------------------------------------------------
__global__ __launch_bounds__(256) void prep_kernel(const float* __restrict__ F) {
    __shared__ float Fs[MDIM][MDIM + 1];
    __shared__ float FFs[MDIM][MDIM + 4];
    __shared__ float red[8];
    __shared__ float s_inv;

    int t = threadIdx.x;
    for (int o = t; o < MDIM * MDIM; o += 256)
        Fs[o >> 6][o & 63] = F[o];
    __syncthreads();

    int i  = t >> 2;
    int j0 = (t & 3) * 16;
    float acc[16];
#pragma unroll
    for (int u = 0; u < 16; u++) acc[u] = 0.0f;
    for (int k = 0; k < MDIM; k++) {
        float a = Fs[k][i];
#pragma unroll
        for (int u = 0; u < 16; u++) acc[u] = fmaf(a, Fs[k][j0 + u], acc[u]);
    }
    float ss = 0.0f;
#pragma unroll
    for (int u = 0; u < 16; u++) {
        FFs[i][j0 + u] = acc[u];
        ss = fmaf(acc[u], acc[u], ss);
    }
#pragma unroll
    for (int off = 16; off > 0; off >>= 1)
        ss += __shfl_xor_sync(0xffffffffu, ss, off);
    if ((t & 31) == 0) red[t >> 5] = ss;
    __syncthreads();
    if (t == 0) {
        float tot = 0.0f;
        for (int w = 0; w < 8; w++) tot += red[w];
        s_inv = 2.0f / (sqrtf(tot) + 1e-12f);
    }
    __syncthreads();
    float inv = s_inv;
#pragma unroll
    for (int u = 0; u < 16; u++) {
        int j = j0 + u;
        g_Gt[i * MDIM + j] = FFs[i][j] * inv - (i == j ? 1.0f : 0.0f);
    }
}

// ---------------------------------------------------------------------------
// TMA-staged pure-bf16 tensor GEMM, 3-term hi/lo split, BN=64, KB=64,
// NST=3 ring. Lean mbarrier protocol: full count=1 (thread0 expect_tx of
// TX_BYTES = actual delivered bytes), empty count=8 (per-warp arrive).
// TRANSB=0: C += A @ B (B is K x N);  TRANSB=1: C += A @ B^T (B is N x K)
// ---------------------------------------------------------------------------
template <int TRANSB>
__global__ __launch_bounds__(256) void gemm_bf(const __nv_bfloat16* __restrict__ Agh,
                                               const __nv_bfloat16* __restrict__ Agl,
                                               const __nv_bfloat16* __restrict__ Bgh,
                                               const __nv_bfloat16* __restrict__ Bgl,
                                               float* __restrict__ C) {
    extern __shared__ __align__(128) char sm[];
    const uint32_t smb = sptr(sm);

    const int t    = threadIdx.x;
    const int lane = t & 31;
    const int warp = t >> 5;
    const int jg   = blockIdx.x * BN;
    const int k0g  = blockIdx.y * KSPL;
    const int mw   = (warp & 3) * 16;
    const int nw   = (warp >> 2) * 32;
    const int lr   = lane & 15;
    const int g8   = (lane >> 4) * 8;

    // mbarriers: full[s] at smb + s*16, empty[s] at smb + s*16 + 8
    if (t == 0) {
#pragma unroll
        for (int s = 0; s < NST; s++) {
            mbar_init(smb + s * 16, 1);     // full: thread0's expect_tx only
            mbar_init(smb + s * 16 + 8, 8); // empty: one arrive per warp
        }
        fence_async_init();
    }
    __syncthreads();

    // copy role: tile (0=Ah,1=Al,2=Bh,3=Bl), row within tile; precomputed base
    const int tile = t >> 6;
    const int rowc = t & 63;
    const char* srcb;     // byte address of this thread's row at chunk 0
    long  delta;          // byte advance per chunk
    {
        const __nv_bfloat16* base;
        size_t eoff;
        if (tile == 0)      { base = Agh; eoff = (size_t)rowc * NDIM + k0g; delta = KB * 2; }
        else if (tile == 1) { base = Agl; eoff = (size_t)rowc * NDIM + k0g; delta = KB * 2; }
        else {
            base = (tile == 2) ? Bgh : Bgl;
            if (TRANSB) { eoff = (size_t)(jg + rowc) * NDIM + k0g; delta = KB * 2; }
            else        { eoff = (size_t)(k0g + rowc) * NDIM + jg; delta = (long)KB * NDIM * 2; }
        }
        srcb = (const char*)(base + eoff);
    }
    const uint32_t dst0 = smb + 128 + tile * TILE_BYTES + rowc * ROWB;

    float acc[4][4];
#pragma unroll
    for (int nt = 0; nt < 4; nt++)
#pragma unroll
        for (int u = 0; u < 4; u++) acc[nt][u] = 0.0f;

    // prologue: fill stages 0..NST-2
#pragma unroll
    for (int cn = 0; cn < NST - 1; cn++) {
        uint32_t full = smb + cn * 16;
        if (t == 0) mbar_expect_tx(full, TX_BYTES);
        bulk_ld(dst0 + cn * STAGE_BYTES, srcb + cn * delta, 128, full);
    }

    for (int c = 0; c < NCH; c++) {
        // issue chunk cn into its stage (after the stage drains)
        int cn = c + NST - 1;
        if (cn < NCH) {
            int s2 = cn % NST;
            if (cn >= NST)
                mbar_wait(smb + s2 * 16 + 8, ((cn - NST) / NST) & 1);
            uint32_t full = smb + s2 * 16;
            if (t == 0) mbar_expect_tx(full, TX_BYTES);
            bulk_ld(dst0 + s2 * STAGE_BYTES, srcb + (long)cn * delta, 128, full);
        }

        // consume chunk c
        const int s = c % NST;
        mbar_wait(smb + s * 16, (c / NST) & 1);

        const uint32_t Ah = smb + 128 + s * STAGE_BYTES;
        const uint32_t Al = Ah + TILE_BYTES;
        const uint32_t Bh = Ah + 2 * TILE_BYTES;
        const uint32_t Bl = Ah + 3 * TILE_BYTES;

#pragma unroll
        for (int ks = 0; ks < 4; ks++) {
            uint32_t ah[4], al[4];
            ldsm4(ah, Ah + (mw + lr) * ROWB + (ks * 16 + g8) * 2);
            ldsm4(al, Al + (mw + lr) * ROWB + (ks * 16 + g8) * 2);
#pragma unroll
            for (int half = 0; half < 2; half++) {
                uint32_t bh[4], bl[4];
                if (TRANSB == 0) {
                    ldsm4t(bh, Bh + (ks * 16 + lr) * ROWB + (nw + half * 16 + g8) * 2);
                    ldsm4t(bl, Bl + (ks * 16 + lr) * ROWB + (nw + half * 16 + g8) * 2);
                    mma16816(acc[half * 2],     ah, bh[0], bh[1]);
                    mma16816(acc[half * 2],     ah, bl[0], bl[1]);
                    mma16816(acc[half * 2],     al, bh[0], bh[1]);
                    mma16816(acc[half * 2 + 1], ah, bh[2], bh[3]);
                    mma16816(acc[half * 2 + 1], ah, bl[2], bl[3]);
                    mma16816(acc[half * 2 + 1], al, bh[2], bh[3]);
                } else {
                    ldsm4(bh, Bh + (nw + half * 16 + lr) * ROWB + (ks * 16 + g8) * 2);
                    ldsm4(bl, Bl + (nw + half * 16 + lr) * ROWB + (ks * 16 + g8) * 2);
                    mma16816(acc[half * 2],     ah, bh[0], bh[2]);
                    mma16816(acc[half * 2],     ah, bl[0], bl[2]);
                    mma16816(acc[half * 2],     al, bh[0], bh[2]);
                    mma16816(acc[half * 2 + 1], ah, bh[1], bh[3]);
                    mma16816(acc[half * 2 + 1], ah, bl[1], bl[3]);
                    mma16816(acc[half * 2 + 1], al, bh[1], bh[3]);
                }
            }
        }
        if (lane == 0) mbar_arrive(smb + s * 16 + 8);   // this warp's reads done
    }

    const int row = mw + (lane >> 2);
#pragma unroll
    for (int nt = 0; nt < 4; nt++) {
        const int col = jg + nw + (nt >> 1) * 16 + (nt & 1) * 8 + (lane & 3) * 2;
        atomicAdd(&C[(size_t)row * NDIM + col],           acc[nt][0]);
        atomicAdd(&C[(size_t)row * NDIM + col + 1],       acc[nt][1]);
        atomicAdd(&C[(size_t)(row + 8) * NDIM + col],     acc[nt][2]);
        atomicAdd(&C[(size_t)(row + 8) * NDIM + col + 1], acc[nt][3]);
    }
}

// ---------------------------------------------------------------------------
// Tensor-core Chebyshev: G~ fragments resident, T recurrence via 3 rotating
// bf16 hi/lo smem buffers, fp32 fragment accumulation, bf16 hi/lo output.
// ---------------------------------------------------------------------------
__global__ __launch_bounds__(256) void cheb_tc(const float* __restrict__ lamS,
                                               const float* __restrict__ gammap) {
    extern __shared__ __align__(16) __nv_bfloat16 cs[];
    __nv_bfloat16* Gh = cs;
    __nv_bfloat16* Gl = cs + 64 * GST;
    __nv_bfloat16* Tbh = cs + 2 * 64 * GST;
    __nv_bfloat16* Tbl = Tbh + 3 * 64 * TST;
    __shared__ float sh_base[32];
    __shared__ float sh_r[32];

    const int t    = threadIdx.x;
    const int lane = t & 31;
    const int warp = t >> 5;
    const int jg   = blockIdx.x * 32;
    const int mw   = (warp & 3) * 16;
    const int nw   = (warp >> 2) * 16;
    const int lr   = lane & 15;
    const int g8   = (lane >> 4) * 8;

    for (int o = t; o < MDIM * MDIM; o += 256) {
        int r = o >> 6, c = o & 63;
        __nv_bfloat16 h, l;
        bf16split(g_Gt[o], h, l);
        Gh[r * GST + c] = h;
        Gl[r * GST + c] = l;
    }
    for (int o = t; o < MDIM * 32; o += 256) {
        int r = o >> 5, c = o & 31;
        __nv_bfloat16 h, l;
        bf16split(g_Y[(size_t)r * NDIM + jg + c], h, l);
        Tbh[r * TST + c] = h;
        Tbl[r * TST + c] = l;
    }
    if (t < 32) {
        float gam = gammap[0];
        float a = gam * lamS[jg + t];
        float base, r;
        if (fabsf(a) < 1e-7f) {
            base = 1.0f; r = 0.0f;
        } else {
            float b  = 2.0f / a - 1.0f;
            float ab = fabsf(b);
            float s  = sqrtf(fmaf(ab, ab, -1.0f));
            float q  = 1.0f / (ab + s);
            float sg = (a > 0.0f) ? 1.0f : -1.0f;
            r    = sg * q;
            base = (2.0f / a) * sg * 2.0f * q / (1.0f - q * q);
        }
        sh_base[t] = base;
        sh_r[t]    = r;
    }
    __syncthreads();

    uint32_t gh[4][4], gl[4][4];
#pragma unroll
    for (int ks = 0; ks < 4; ks++) {
        ldsm4(gh[ks], sptr(Gh + (mw + lr) * GST + ks * 16 + g8));
        ldsm4(gl[ks], sptr(Gl + (mw + lr) * GST + ks * 16 + g8));
    }

    const int row0 = mw + (lane >> 2);
    float basev[2][2], rv[2][2], pv[2][2];
#pragma unroll
    for (int nt = 0; nt < 2; nt++) {
        int c0 = nw + nt * 8 + 2 * (lane & 3);
        basev[nt][0] = sh_base[c0];     basev[nt][1] = sh_base[c0 + 1];
        rv[nt][0]    = sh_r[c0];        rv[nt][1]    = sh_r[c0 + 1];
        pv[nt][0] = 2.0f * basev[nt][0] * rv[nt][0];
        pv[nt][1] = 2.0f * basev[nt][1] * rv[nt][1];
    }

    float acc[2][4], prev[2][4], tp[2][4];
#pragma unroll
    for (int nt = 0; nt < 2; nt++) {
        int c0 = nw + nt * 8 + 2 * (lane & 3);
        float2 y0 = *(const float2*)&g_Y[(size_t)row0 * NDIM + jg + c0];
        float2 y1 = *(const float2*)&g_Y[(size_t)(row0 + 8) * NDIM + jg + c0];
        prev[nt][0] = y0.x; prev[nt][1] = y0.y; prev[nt][2] = y1.x; prev[nt][3] = y1.y;
        acc[nt][0] = basev[nt][0] * y0.x;
        acc[nt][1] = basev[nt][1] * y0.y;
        acc[nt][2] = basev[nt][0] * y1.x;
        acc[nt][3] = basev[nt][1] * y1.y;
        tp[nt][0] = tp[nt][1] = tp[nt][2] = tp[nt][3] = 0.0f;
    }

    for (int k = 1; k < KCHEB; k++) {
        __syncthreads();
        const __nv_bfloat16* Th = Tbh + ((k - 1) % 3) * (64 * TST);
        const __nv_bfloat16* Tl = Tbl + ((k - 1) % 3) * (64 * TST);
        float u[2][4];
#pragma unroll
        for (int nt = 0; nt < 2; nt++)
#pragma unroll
            for (int i = 0; i < 4; i++) u[nt][i] = 0.0f;
#pragma unroll
        for (int ks = 0; ks < 4; ks++) {
            uint32_t th[4], tl[4];
            ldsm4t(th, sptr(Th + (ks * 16 + lr) * TST + nw + g8));
            ldsm4t(tl, sptr(Tl + (ks * 16 + lr) * TST + nw + g8));
            mma16816(u[0], gh[ks], th[0], th[1]);
            mma16816(u[0], gh[ks], tl[0], tl[1]);
            mma16816(u[0], gl[ks], th[0], th[1]);
            mma16816(u[1], gh[ks], th[2], th[3]);
            mma16816(u[1], gh[ks], tl[2], tl[3]);
            mma16816(u[1], gl[ks], th[2], th[3]);
        }
        float tn[2][4];
#pragma unroll
        for (int nt = 0; nt < 2; nt++)
#pragma unroll
            for (int i = 0; i < 4; i++)
                tn[nt][i] = (k == 1) ? u[nt][i] : fmaf(2.0f, u[nt][i], -tp[nt][i]);
#pragma unroll
        for (int nt = 0; nt < 2; nt++) {
            acc[nt][0] = fmaf(pv[nt][0], tn[nt][0], acc[nt][0]);
            acc[nt][1] = fmaf(pv[nt][1], tn[nt][1], acc[nt][1]);
            acc[nt][2] = fmaf(pv[nt][0], tn[nt][2], acc[nt][2]);
            acc[nt][3] = fmaf(pv[nt][1], tn[nt][3], acc[nt][3]);
            pv[nt][0] *= rv[nt][0];
            pv[nt][1] *= rv[nt][1];
        }
        if (k < KCHEB - 1) {
            __nv_bfloat16* Wh = Tbh + (k % 3) * (64 * TST);
            __nv_bfloat16* Wl = Tbl + (k % 3) * (64 * TST);
#pragma unroll
            for (int nt = 0; nt < 2; nt++) {
                int c0 = nw + nt * 8 + 2 * (lane & 3);
                uint32_t hp, lp;
                split2pack(tn[nt][0], tn[nt][1], hp, lp);
                *(uint32_t*)(Wh + row0 * TST + c0) = hp;
                *(uint32_t*)(Wl + row0 * TST + c0) = lp;
                split2pack(tn[nt][2], tn[nt][3], hp, lp);
                *(uint32_t*)(Wh + (row0 + 8) * TST + c0) = hp;
                *(uint32_t*)(Wl + (row0 + 8) * TST + c0) = lp;
            }
        }
#pragma unroll
        for (int nt = 0; nt < 2; nt++)
#pragma unroll
            for (int i = 0; i < 4; i++) {
                tp[nt][i]   = prev[nt][i];
                prev[nt][i] = tn[nt][i];
            }
    }

#pragma unroll
    for (int nt = 0; nt < 2; nt++) {
        int c0 = nw + nt * 8 + 2 * (lane & 3);
        uint32_t hp, lp;
        split2pack(acc[nt][0], acc[nt][1], hp, lp);
        *(uint32_t*)(g_Zh + (size_t)row0 * NDIM + jg + c0) = hp;
        *(uint32_t*)(g_Zl + (size_t)row0 * NDIM + jg + c0) = lp;
        split2pack(acc[nt][2], acc[nt][3], hp, lp);
        *(uint32_t*)(g_Zh + (size_t)(row0 + 8) * NDIM + jg + c0) = hp;
        *(uint32_t*)(g_Zl + (size_t)(row0 + 8) * NDIM + jg + c0) = lp;
    }
}

#define CHEB_SMEM ((2 * 64 * GST + 6 * 64 * TST) * 2)

// ---------------------------------------------------------------------------
extern "C" void kernel_launch(void* const* d_in, const int* in_sizes, int n_in,
                              void* d_out, int out_size) {
    const float* X    = (const float*)d_in[0];   // (64, 4096)
    const float* F    = (const float*)d_in[1];   // (64, 64)
    const float* Q_S  = (const float*)d_in[2];   // (4096, 4096)
    const float* lamS = (const float*)d_in[3];   // (4096,)
    const float* gam  = (const float*)d_in[4];   // scalar
    float* Z = (float*)d_out;                    // (64, 4096)

    float *Y;
    __nv_bfloat16 *Qh, *Ql, *Xh, *Xl, *Zh, *Zl;
    cudaGetSymbolAddress((void**)&Y,  g_Y);
    cudaGetSymbolAddress((void**)&Qh, g_Qh);
    cudaGetSymbolAddress((void**)&Ql, g_Ql);
    cudaGetSymbolAddress((void**)&Xh, g_Xh);
    cudaGetSymbolAddress((void**)&Xl, g_Xl);
    cudaGetSymbolAddress((void**)&Zh, g_Zh);
    cudaGetSymbolAddress((void**)&Zl, g_Zl);

    static bool attr_set = false;
    if (!attr_set) {
        cudaFuncSetAttribute(gemm_bf<0>, cudaFuncAttributeMaxDynamicSharedMemorySize, GEMM_SMEM);
        cudaFuncSetAttribute(gemm_bf<1>, cudaFuncAttributeMaxDynamicSharedMemorySize, GEMM_SMEM);
        cudaFuncSetAttribute(cheb_tc,    cudaFuncAttributeMaxDynamicSharedMemorySize, CHEB_SMEM);
        attr_set = true;
    }

    const int conv_blocks = (NDIM * NDIM / 4 + MDIM * NDIM / 4) / 256;  // 16640
    dim3 ggrid(NDIM / BN, NSPLIT);

    conv_kernel<<<conv_blocks, 256>>>((const float4*)Q_S, (const float4*)X);
    zero_kernel<<<(MDIM * NDIM) / 256, 256>>>(Y, Z);
    prep_kernel<<<1, 256>>>(F);
    gemm_bf<0><<<ggrid, 256, GEMM_SMEM>>>(Xh, Xl, Qh, Ql, Y);   // Y += X @ Q_S
    cheb_tc<<<NDIM / 32, 256, CHEB_SMEM>>>(lamS, gam);          // Zh/Zl = f(G) Y
    gemm_bf<1><<<ggrid, 256, GEMM_SMEM>>>(Zh, Zl, Qh, Ql, Z);   // Z += Z~ @ Q_S^T
}

// round 11
// speedup vs baseline: 3.0346x; 1.0341x over previous
#include <cuda_runtime.h>
#include <cuda_bf16.h>
#include <cstdint>
#include <math.h>

#define MDIM 64
#define NDIM 4096
#define BN   64
#define KB   64
#define NST  3
#define KSPL 1024
#define NCH  (KSPL / KB)     // 16 chunks per K-split
#define NSPLIT (NDIM / KSPL) // 4
#define KCHEB 14

#define ROWB 144                       // smem row stride bytes (128B data + 16 pad)
#define TILE_BYTES (64 * ROWB)         // 9216
#define STAGE_BYTES (4 * TILE_BYTES)   // 36864 (Ah, Al, Bh, Bl)
#define TX_BYTES (256 * 128)           // 32768 actual bytes delivered per stage
#define GEMM_SMEM (128 + NST * STAGE_BYTES)   // 110720

#define GST 72
#define TST 40

// Scratch (allocation-free rule: __device__ globals)
__device__ float g_Gt[MDIM * MDIM];
__device__ float g_Y [MDIM * NDIM];
__device__ __align__(128) __nv_bfloat16 g_Qh[(size_t)NDIM * NDIM];
__device__ __align__(128) __nv_bfloat16 g_Ql[(size_t)NDIM * NDIM];
__device__ __align__(128) __nv_bfloat16 g_Xh[MDIM * NDIM];
__device__ __align__(128) __nv_bfloat16 g_Xl[MDIM * NDIM];
__device__ __align__(128) __nv_bfloat16 g_Zh[MDIM * NDIM];
__device__ __align__(128) __nv_bfloat16 g_Zl[MDIM * NDIM];

// ---------------------------------------------------------------------------
// PTX helpers
// ---------------------------------------------------------------------------
__device__ __forceinline__ uint32_t sptr(const void* p) {
    return (uint32_t)__cvta_generic_to_shared(p);
}
__device__ __forceinline__ void ldsm4(uint32_t r[4], uint32_t addr) {
    asm volatile("ldmatrix.sync.aligned.m8n8.x4.shared.b16 {%0,%1,%2,%3}, [%4];"
                 : "=r"(r[0]), "=r"(r[1]), "=r"(r[2]), "=r"(r[3]) : "r"(addr));
}
__device__ __forceinline__ void ldsm4t(uint32_t r[4], uint32_t addr) {
    asm volatile("ldmatrix.sync.aligned.m8n8.x4.trans.shared.b16 {%0,%1,%2,%3}, [%4];"
                 : "=r"(r[0]), "=r"(r[1]), "=r"(r[2]), "=r"(r[3]) : "r"(addr));
}
__device__ __forceinline__ void mma16816(float d[4], const uint32_t a[4],
                                         uint32_t b0, uint32_t b1) {
    asm volatile("mma.sync.aligned.m16n8k16.row.col.f32.bf16.bf16.f32 "
                 "{%0,%1,%2,%3}, {%4,%5,%6,%7}, {%8,%9}, {%0,%1,%2,%3};"
                 : "+f"(d[0]), "+f"(d[1]), "+f"(d[2]), "+f"(d[3])
                 : "r"(a[0]), "r"(a[1]), "r"(a[2]), "r"(a[3]),
                   "r"(b0), "r"(b1));
}
// TMA 1D bulk: global -> shared, completion via mbarrier tx-bytes
__device__ __forceinline__ void bulk_ld(uint32_t dst, const void* src,
                                        uint32_t bytes, uint32_t mbar) {
    asm volatile("cp.async.bulk.shared::cluster.global.mbarrier::complete_tx::bytes "
                 "[%0], [%1], %2, [%3];"
                 :: "r"(dst), "l"(src), "r"(bytes), "r"(mbar) : "memory");
}
__device__ __forceinline__ void mbar_init(uint32_t a, uint32_t cnt) {
    asm volatile("mbarrier.init.shared.b64 [%0], %1;" :: "r"(a), "r"(cnt) : "memory");
}
__device__ __forceinline__ void mbar_expect_tx(uint32_t a, uint32_t bytes) {
    asm volatile("mbarrier.arrive.expect_tx.shared.b64 _, [%0], %1;"
                 :: "r"(a), "r"(bytes) : "memory");
}
__device__ __forceinline__ void mbar_arrive(uint32_t a) {
    asm volatile("mbarrier.arrive.shared.b64 _, [%0];" :: "r"(a) : "memory");
}
__device__ __forceinline__ void mbar_wait(uint32_t a, uint32_t parity) {
    asm volatile(
        "{\n\t.reg .pred P;\n\t"
        "WAIT_%=:\n\t"
        "mbarrier.try_wait.parity.acquire.cta.shared::cta.b64 P, [%0], %1, 0x989680;\n\t"
        "@P bra.uni DONE_%=;\n\t"
        "bra.uni WAIT_%=;\n\t"
        "DONE_%=:\n\t}"
        :: "r"(a), "r"(parity) : "memory");
}
__device__ __forceinline__ void fence_async_init() {
    asm volatile("fence.proxy.async.shared::cta;" ::: "memory");
}

__device__ __forceinline__ void bf16split(float x, __nv_bfloat16& h, __nv_bfloat16& l) {
    h = __float2bfloat16(x);
    l = __float2bfloat16(x - __bfloat162float(h));
}
__device__ __forceinline__ void split2pack(float a, float b, uint32_t& hp, uint32_t& lp) {
    __nv_bfloat16 ha, la, hb, lb;
    bf16split(a, ha, la);
    bf16split(b, hb, lb);
    __nv_bfloat162 h; h.x = ha; h.y = hb;
    __nv_bfloat162 l; l.x = la; l.y = lb;
    hp = *(uint32_t*)&h;
    lp = *(uint32_t*)&l;
}

// ---------------------------------------------------------------------------
// Convert Q_S and X to bf16 hi/lo (one float4 per thread)
// ---------------------------------------------------------------------------
__global__ __launch_bounds__(256) void conv_kernel(const float4* __restrict__ Q,
                                                   const float4* __restrict__ X) {
    const size_t QN4 = (size_t)NDIM * NDIM / 4;
    size_t gid = (size_t)blockIdx.x * 256 + threadIdx.x;
    float4 v;
    __nv_bfloat16 *dh, *dl;
    size_t off;
    if (gid < QN4) { v = Q[gid]; dh = g_Qh; dl = g_Ql; off = gid * 4; }
    else { size_t x = gid - QN4; v = X[x]; dh = g_Xh; dl = g_Xl; off = x * 4; }
    uint32_t h0, l0, h1, l1;
    split2pack(v.x, v.y, h0, l0);
    split2pack(v.z, v.w, h1, l1);
    *(uint2*)(dh + off) = make_uint2(h0, h1);
    *(uint2*)(dl + off) = make_uint2(l0, l1);
}

// ---------------------------------------------------------------------------
// Zero-init Y and Z (outputs accumulated via atomicAdd each replay)
// ---------------------------------------------------------------------------
__global__ __launch_bounds__(256) void zero_kernel(float* __restrict__ a,
                                                   float* __restrict__ b) {
    int i = blockIdx.x * 256 + threadIdx.x;
    a[i] = 0.0f;
    b[i] = 0.0f;
}

// ---------------------------------------------------------------------------
// G~ = 2 * (F^T F) / (||F^T F||_F + 1e-12) - I
// ---------------------------------------------------------------------------
__global__ __launch_bounds__(256) void prep_kernel(const float* __restrict__ F) {
    __shared__ float Fs[MDIM][MDIM + 1];
    __shared__ float FFs[MDIM][MDIM + 4];
    __shared__ float red[8];
    __shared__ float s_inv;

    int t = threadIdx.x;
    for (int o = t; o < MDIM * MDIM; o += 256)
        Fs[o >> 6][o & 63] = F[o];
    __syncthreads();

    int i  = t >> 2;
    int j0 = (t & 3) * 16;
    float acc[16];
#pragma unroll
    for (int u = 0; u < 16; u++) acc[u] = 0.0f;
    for (int k = 0; k < MDIM; k++) {
        float a = Fs[k][i];
#pragma unroll
        for (int u = 0; u < 16; u++) acc[u] = fmaf(a, Fs[k][j0 + u], acc[u]);
    }
    float ss = 0.0f;
#pragma unroll
    for (int u = 0; u < 16; u++) {
        FFs[i][j0 + u] = acc[u];
        ss = fmaf(acc[u], acc[u], ss);
    }
#pragma unroll
    for (int off = 16; off > 0; off >>= 1)
        ss += __shfl_xor_sync(0xffffffffu, ss, off);
    if ((t & 31) == 0) red[t >> 5] = ss;
    __syncthreads();
    if (t == 0) {
        float tot = 0.0f;
        for (int w = 0; w < 8; w++) tot += red[w];
        s_inv = 2.0f / (sqrtf(tot) + 1e-12f);
    }
    __syncthreads();
    float inv = s_inv;
#pragma unroll
    for (int u = 0; u < 16; u++) {
        int j = j0 + u;
        g_Gt[i * MDIM + j] = FFs[i][j] * inv - (i == j ? 1.0f : 0.0f);
    }
}

// ---------------------------------------------------------------------------
// TMA-staged pure-bf16 tensor GEMM, 3-term hi/lo split, BN=64, KB=64,
// NST=3 ring, FULLY UNROLLED pipeline (compile-time stage bases, ldsm
// offsets, mbarrier parities). Lean protocol: full count=1, empty count=8.
// TRANSB=0: C += A @ B (B is K x N);  TRANSB=1: C += A @ B^T (B is N x K)
// ---------------------------------------------------------------------------
template <int TRANSB>
__global__ __launch_bounds__(256) void gemm_bf(const __nv_bfloat16* __restrict__ Agh,
                                               const __nv_bfloat16* __restrict__ Agl,
                                               const __nv_bfloat16* __restrict__ Bgh,
                                               const __nv_bfloat16* __restrict__ Bgl,
                                               float* __restrict__ C) {
    extern __shared__ __align__(128) char sm[];
    const uint32_t smb = sptr(sm);

    const int t    = threadIdx.x;
    const int lane = t & 31;
    const int warp = t >> 5;
    const int jg   = blockIdx.x * BN;
    const int k0g  = blockIdx.y * KSPL;
    const int mw   = (warp & 3) * 16;
    const int nw   = (warp >> 2) * 32;
    const int lr   = lane & 15;
    const int g8   = (lane >> 4) * 8;

    // mbarriers: full[s] at smb + s*16, empty[s] at smb + s*16 + 8
    if (t == 0) {
#pragma unroll
        for (int s = 0; s < NST; s++) {
            mbar_init(smb + s * 16, 1);     // full: thread0's expect_tx only
            mbar_init(smb + s * 16 + 8, 8); // empty: one arrive per warp
        }
        fence_async_init();
    }
    __syncthreads();

    // copy role: tile (0=Ah,1=Al,2=Bh,3=Bl), row within tile
    const int tile = t >> 6;
    const int rowc = t & 63;
    const char* src;      // byte address of this thread's row for NEXT chunk to issue
    long  delta;          // byte advance per chunk
    {
        const __nv_bfloat16* base;
        size_t eoff;
        if (tile == 0)      { base = Agh; eoff = (size_t)rowc * NDIM + k0g; delta = KB * 2; }
        else if (tile == 1) { base = Agl; eoff = (size_t)rowc * NDIM + k0g; delta = KB * 2; }
        else {
            base = (tile == 2) ? Bgh : Bgl;
            if (TRANSB) { eoff = (size_t)(jg + rowc) * NDIM + k0g; delta = KB * 2; }
            else        { eoff = (size_t)(k0g + rowc) * NDIM + jg; delta = (long)KB * NDIM * 2; }
        }
        src = (const char*)(base + eoff);
    }
    const uint32_t dst0 = smb + 128 + tile * TILE_BYTES + rowc * ROWB;

    // per-thread ldsm base offsets (loop-invariant)
    const uint32_t aoff = (uint32_t)((mw + lr) * ROWB + g8 * 2);
    const uint32_t boff = TRANSB ? (uint32_t)((nw + lr) * ROWB + g8 * 2)
                                 : (uint32_t)(lr * ROWB + (nw + g8) * 2);

    float acc[4][4];
#pragma unroll
    for (int nt = 0; nt < 4; nt++)
#pragma unroll
        for (int u = 0; u < 4; u++) acc[nt][u] = 0.0f;

    // prologue: fill stages 0..NST-2 (chunks 0,1)
#pragma unroll
    for (int cn = 0; cn < NST - 1; cn++) {
        uint32_t full = smb + cn * 16;
        if (t == 0) mbar_expect_tx(full, TX_BYTES);
        bulk_ld(dst0 + cn * STAGE_BYTES, src, 128, full);
        src += delta;
    }

#pragma unroll
    for (int cb = 0; cb < NCH; cb += NST) {
        const int q    = cb / NST;
        const int cpar = q & 1;
#pragma unroll
        for (int s = 0; s < NST; s++) {
            const int cc = cb + s;
            if (cc >= NCH) break;
            const int cn = cc + NST - 1;          // chunk to issue
            const int istage = (s + NST - 1) % NST;
            if (cn < NCH) {
                if (cn >= NST) {
                    const int ipar = (s == 0) ? ((q - 1) & 1) : cpar;
                    mbar_wait(smb + istage * 16 + 8, ipar);
                }
                const uint32_t full = smb + istage * 16;
                if (t == 0) mbar_expect_tx(full, TX_BYTES);
                bulk_ld(dst0 + istage * STAGE_BYTES, src, 128, full);
                src += delta;
            }

            // consume chunk cc at stage s (compile-time base)
            mbar_wait(smb + s * 16, cpar);

            const uint32_t Ah = smb + 128 + s * STAGE_BYTES;
            const uint32_t Al = Ah + TILE_BYTES;
            const uint32_t Bh = Ah + 2 * TILE_BYTES;
            const uint32_t Bl = Ah + 3 * TILE_BYTES;

#pragma unroll
            for (int ks = 0; ks < 4; ks++) {
                uint32_t ah[4], al[4];
                ldsm4(ah, Ah + aoff + ks * 32);
                ldsm4(al, Al + aoff + ks * 32);
#pragma unroll
                for (int half = 0; half < 2; half++) {
                    uint32_t bh[4], bl[4];
                    if (TRANSB == 0) {
                        const uint32_t bo = boff + ks * (16 * ROWB) + half * 32;
                        ldsm4t(bh, Bh + bo);
                        ldsm4t(bl, Bl + bo);
                        mma16816(acc[half * 2],     ah, bh[0], bh[1]);
                        mma16816(acc[half * 2],     ah, bl[0], bl[1]);
                        mma16816(acc[half * 2],     al, bh[0], bh[1]);
                        mma16816(acc[half * 2 + 1], ah, bh[2], bh[3]);
                        mma16816(acc[half * 2 + 1], ah, bl[2], bl[3]);
                        mma16816(acc[half * 2 + 1], al, bh[2], bh[3]);
                    } else {
                        const uint32_t bo = boff + half * (16 * ROWB) + ks * 32;
                        ldsm4(bh, Bh + bo);
                        ldsm4(bl, Bl + bo);
                        mma16816(acc[half * 2],     ah, bh[0], bh[2]);
                        mma16816(acc[half * 2],     ah, bl[0], bl[2]);
                        mma16816(acc[half * 2],     al, bh[0], bh[2]);
                        mma16816(acc[half * 2 + 1], ah, bh[1], bh[3]);
                        mma16816(acc[half * 2 + 1], ah, bl[1], bl[3]);
                        mma16816(acc[half * 2 + 1], al, bh[1], bh[3]);
                    }
                }
            }
            if (lane == 0) mbar_arrive(smb + s * 16 + 8);   // this warp's reads done
        }
    }

    const int row = mw + (lane >> 2);
#pragma unroll
    for (int nt = 0; nt < 4; nt++) {
        const int col = jg + nw + (nt >> 1) * 16 + (nt & 1) * 8 + (lane & 3) * 2;
        atomicAdd(&C[(size_t)row * NDIM + col],           acc[nt][0]);
        atomicAdd(&C[(size_t)row * NDIM + col + 1],       acc[nt][1]);
        atomicAdd(&C[(size_t)(row + 8) * NDIM + col],     acc[nt][2]);
        atomicAdd(&C[(size_t)(row + 8) * NDIM + col + 1], acc[nt][3]);
    }
}

// ---------------------------------------------------------------------------
// Tensor-core Chebyshev: G~ fragments resident, T recurrence via 3 rotating
// bf16 hi/lo smem buffers, fp32 fragment accumulation, bf16 hi/lo output.
// ---------------------------------------------------------------------------
__global__ __launch_bounds__(256) void cheb_tc(const float* __restrict__ lamS,
                                               const float* __restrict__ gammap) {
    extern __shared__ __align__(16) __nv_bfloat16 cs[];
    __nv_bfloat16* Gh = cs;
    __nv_bfloat16* Gl = cs + 64 * GST;
    __nv_bfloat16* Tbh = cs + 2 * 64 * GST;
    __nv_bfloat16* Tbl = Tbh + 3 * 64 * TST;
    __shared__ float sh_base[32];
    __shared__ float sh_r[32];

    const int t    = threadIdx.x;
    const int lane = t & 31;
    const int warp = t >> 5;
    const int jg   = blockIdx.x * 32;
    const int mw   = (warp & 3) * 16;
    const int nw   = (warp >> 2) * 16;
    const int lr   = lane & 15;
    const int g8   = (lane >> 4) * 8;

    for (int o = t; o < MDIM * MDIM; o += 256) {
        int r = o >> 6, c = o & 63;
        __nv_bfloat16 h, l;
        bf16split(g_Gt[o], h, l);
        Gh[r * GST + c] = h;
        Gl[r * GST + c] = l;
    }
    for (int o = t; o < MDIM * 32; o += 256) {
        int r = o >> 5, c = o & 31;
        __nv_bfloat16 h, l;
        bf16split(g_Y[(size_t)r * NDIM + jg + c], h, l);
        Tbh[r * TST + c] = h;
        Tbl[r * TST + c] = l;
    }
    if (t < 32) {
        float gam = gammap[0];
        float a = gam * lamS[jg + t];
        float base, r;
        if (fabsf(a) < 1e-7f) {
            base = 1.0f; r = 0.0f;
        } else {
            float b  = 2.0f / a - 1.0f;
            float ab = fabsf(b);
            float s  = sqrtf(fmaf(ab, ab, -1.0f));
            float q  = 1.0f / (ab + s);
            float sg = (a > 0.0f) ? 1.0f : -1.0f;
            r    = sg * q;
            base = (2.0f / a) * sg * 2.0f * q / (1.0f - q * q);
        }
        sh_base[t] = base;
        sh_r[t]    = r;
    }
    __syncthreads();

    uint32_t gh[4][4], gl[4][4];
#pragma unroll
    for (int ks = 0; ks < 4; ks++) {
        ldsm4(gh[ks], sptr(Gh + (mw + lr) * GST + ks * 16 + g8));
        ldsm4(gl[ks], sptr(Gl + (mw + lr) * GST + ks * 16 + g8));
    }

    const int row0 = mw + (lane >> 2);
    float basev[2][2], rv[2][2], pv[2][2];
#pragma unroll
    for (int nt = 0; nt < 2; nt++) {
        int c0 = nw + nt * 8 + 2 * (lane & 3);
        basev[nt][0] = sh_base[c0];     basev[nt][1] = sh_base[c0 + 1];
        rv[nt][0]    = sh_r[c0];        rv[nt][1]    = sh_r[c0 + 1];
        pv[nt][0] = 2.0f * basev[nt][0] * rv[nt][0];
        pv[nt][1] = 2.0f * basev[nt][1] * rv[nt][1];
    }

    float acc[2][4], prev[2][4], tp[2][4];
#pragma unroll
    for (int nt = 0; nt < 2; nt++) {
        int c0 = nw + nt * 8 + 2 * (lane & 3);
        float2 y0 = *(const float2*)&g_Y[(size_t)row0 * NDIM + jg + c0];
        float2 y1 = *(const float2*)&g_Y[(size_t)(row0 + 8) * NDIM + jg + c0];
        prev[nt][0] = y0.x; prev[nt][1] = y0.y; prev[nt][2] = y1.x; prev[nt][3] = y1.y;
        acc[nt][0] = basev[nt][0] * y0.x;
        acc[nt][1] = basev[nt][1] * y0.y;
        acc[nt][2] = basev[nt][0] * y1.x;
        acc[nt][3] = basev[nt][1] * y1.y;
        tp[nt][0] = tp[nt][1] = tp[nt][2] = tp[nt][3] = 0.0f;
    }

    for (int k = 1; k < KCHEB; k++) {
        __syncthreads();
        const __nv_bfloat16* Th = Tbh + ((k - 1) % 3) * (64 * TST);
        const __nv_bfloat16* Tl = Tbl + ((k - 1) % 3) * (64 * TST);
        float u[2][4];
#pragma unroll
        for (int nt = 0; nt < 2; nt++)
#pragma unroll
            for (int i = 0; i < 4; i++) u[nt][i] = 0.0f;
#pragma unroll
        for (int ks = 0; ks < 4; ks++) {
            uint32_t th[4], tl[4];
            ldsm4t(th, sptr(Th + (ks * 16 + lr) * TST + nw + g8));
            ldsm4t(tl, sptr(Tl + (ks * 16 + lr) * TST + nw + g8));
            mma16816(u[0], gh[ks], th[0], th[1]);
            mma16816(u[0], gh[ks], tl[0], tl[1]);
            mma16816(u[0], gl[ks], th[0], th[1]);
            mma16816(u[1], gh[ks], th[2], th[3]);
            mma16816(u[1], gh[ks], tl[2], tl[3]);
            mma16816(u[1], gl[ks], th[2], th[3]);
        }
        float tn[2][4];
#pragma unroll
        for (int nt = 0; nt < 2; nt++)
#pragma unroll
            for (int i = 0; i < 4; i++)
                tn[nt][i] = (k == 1) ? u[nt][i] : fmaf(2.0f, u[nt][i], -tp[nt][i]);
#pragma unroll
        for (int nt = 0; nt < 2; nt++) {
            acc[nt][0] = fmaf(pv[nt][0], tn[nt][0], acc[nt][0]);
            acc[nt][1] = fmaf(pv[nt][1], tn[nt][1], acc[nt][1]);
            acc[nt][2] = fmaf(pv[nt][0], tn[nt][2], acc[nt][2]);
            acc[nt][3] = fmaf(pv[nt][1], tn[nt][3], acc[nt][3]);
            pv[nt][0] *= rv[nt][0];
            pv[nt][1] *= rv[nt][1];
        }
        if (k < KCHEB - 1) {
            __nv_bfloat16* Wh = Tbh + (k % 3) * (64 * TST);
            __nv_bfloat16* Wl = Tbl + (k % 3) * (64 * TST);
#pragma unroll
            for (int nt = 0; nt < 2; nt++) {
                int c0 = nw + nt * 8 + 2 * (lane & 3);
                uint32_t hp, lp;
                split2pack(tn[nt][0], tn[nt][1], hp, lp);
                *(uint32_t*)(Wh + row0 * TST + c0) = hp;
                *(uint32_t*)(Wl + row0 * TST + c0) = lp;
                split2pack(tn[nt][2], tn[nt][3], hp, lp);
                *(uint32_t*)(Wh + (row0 + 8) * TST + c0) = hp;
                *(uint32_t*)(Wl + (row0 + 8) * TST + c0) = lp;
            }
        }
#pragma unroll
        for (int nt = 0; nt < 2; nt++)
#pragma unroll
            for (int i = 0; i < 4; i++) {
                tp[nt][i]   = prev[nt][i];
                prev[nt][i] = tn[nt][i];
            }
    }

#pragma unroll
    for (int nt = 0; nt < 2; nt++) {
        int c0 = nw + nt * 8 + 2 * (lane & 3);
        uint32_t hp, lp;
        split2pack(acc[nt][0], acc[nt][1], hp, lp);
        *(uint32_t*)(g_Zh + (size_t)row0 * NDIM + jg + c0) = hp;
        *(uint32_t*)(g_Zl + (size_t)row0 * NDIM + jg + c0) = lp;
        split2pack(acc[nt][2], acc[nt][3], hp, lp);
        *(uint32_t*)(g_Zh + (size_t)(row0 + 8) * NDIM + jg + c0) = hp;
        *(uint32_t*)(g_Zl + (size_t)(row0 + 8) * NDIM + jg + c0) = lp;
    }
}

#define CHEB_SMEM ((2 * 64 * GST + 6 * 64 * TST) * 2)

// ---------------------------------------------------------------------------
extern "C" void kernel_launch(void* const* d_in, const int* in_sizes, int n_in,
                              void* d_out, int out_size) {
    const float* X    = (const float*)d_in[0];   // (64, 4096)
    const float* F    = (const float*)d_in[1];   // (64, 64)
    const float* Q_S  = (const float*)d_in[2];   // (4096, 4096)
    const float* lamS = (const float*)d_in[3];   // (4096,)
    const float* gam  = (const float*)d_in[4];   // scalar
    float* Z = (float*)d_out;                    // (64, 4096)

    float *Y;
    __nv_bfloat16 *Qh, *Ql, *Xh, *Xl, *Zh, *Zl;
    cudaGetSymbolAddress((void**)&Y,  g_Y);
    cudaGetSymbolAddress((void**)&Qh, g_Qh);
    cudaGetSymbolAddress((void**)&Ql, g_Ql);
    cudaGetSymbolAddress((void**)&Xh, g_Xh);
    cudaGetSymbolAddress((void**)&Xl, g_Xl);
    cudaGetSymbolAddress((void**)&Zh, g_Zh);
    cudaGetSymbolAddress((void**)&Zl, g_Zl);

    static bool attr_set = false;
    if (!attr_set) {
        cudaFuncSetAttribute(gemm_bf<0>, cudaFuncAttributeMaxDynamicSharedMemorySize, GEMM_SMEM);
        cudaFuncSetAttribute(gemm_bf<1>, cudaFuncAttributeMaxDynamicSharedMemorySize, GEMM_SMEM);
        cudaFuncSetAttribute(cheb_tc,    cudaFuncAttributeMaxDynamicSharedMemorySize, CHEB_SMEM);
        attr_set = true;
    }

    const int conv_blocks = (NDIM * NDIM / 4 + MDIM * NDIM / 4) / 256;  // 16640
    dim3 ggrid(NDIM / BN, NSPLIT);

    conv_kernel<<<conv_blocks, 256>>>((const float4*)Q_S, (const float4*)X);
    zero_kernel<<<(MDIM * NDIM) / 256, 256>>>(Y, Z);
    prep_kernel<<<1, 256>>>(F);
    gemm_bf<0><<<ggrid, 256, GEMM_SMEM>>>(Xh, Xl, Qh, Ql, Y);   // Y += X @ Q_S
    cheb_tc<<<NDIM / 32, 256, CHEB_SMEM>>>(lamS, gam);          // Zh/Zl = f(G) Y
    gemm_bf<1><<<ggrid, 256, GEMM_SMEM>>>(Zh, Zl, Qh, Ql, Z);   // Z += Z~ @ Q_S^T
}

// round 12
// speedup vs baseline: 3.7411x; 1.2328x over previous
#include <cuda_runtime.h>
#include <cuda_bf16.h>
#include <cstdint>
#include <math.h>

#define MDIM 64
#define NDIM 4096
#define BN   64
#define KB   64
#define NST  3
#define KSPL 1024
#define NCH  (KSPL / KB)     // 16 chunks per K-split
#define NSPLIT (NDIM / KSPL) // 4
#define KCHEB 14

#define TILEP 16384                    // one 64x64 hi+lo tile pair (8192 hi + 8192 lo)
#define STAGE_BYTES 32768              // A pair + B pair
#define TX_BYTES 32768
#define GEMM_SMEM (128 + NST * STAGE_BYTES)   // 98432

#define GST 72
#define TST 40

// Scratch (allocation-free rule: __device__ globals)
__device__ float g_Gt[MDIM * MDIM];
__device__ float g_Y [MDIM * NDIM];
// tiled, pre-swizzled bf16 hi/lo tile pairs (16KB each)
__device__ __align__(128) char g_Qt[(size_t)64 * 64 * TILEP];  // Q_S: [rb][cc]
__device__ __align__(128) char g_Xt[64 * TILEP];               // X:   [kc]
__device__ __align__(128) char g_Ztt[64 * TILEP];              // Z~:  [kc]

// ---------------------------------------------------------------------------
// PTX helpers
// ---------------------------------------------------------------------------
__device__ __forceinline__ uint32_t sptr(const void* p) {
    return (uint32_t)__cvta_generic_to_shared(p);
}
__device__ __forceinline__ void ldsm4(uint32_t r[4], uint32_t addr) {
    asm volatile("ldmatrix.sync.aligned.m8n8.x4.shared.b16 {%0,%1,%2,%3}, [%4];"
                 : "=r"(r[0]), "=r"(r[1]), "=r"(r[2]), "=r"(r[3]) : "r"(addr));
}
__device__ __forceinline__ void ldsm4t(uint32_t r[4], uint32_t addr) {
    asm volatile("ldmatrix.sync.aligned.m8n8.x4.trans.shared.b16 {%0,%1,%2,%3}, [%4];"
                 : "=r"(r[0]), "=r"(r[1]), "=r"(r[2]), "=r"(r[3]) : "r"(addr));
}
__device__ __forceinline__ void mma16816(float d[4], const uint32_t a[4],
                                         uint32_t b0, uint32_t b1) {
    asm volatile("mma.sync.aligned.m16n8k16.row.col.f32.bf16.bf16.f32 "
                 "{%0,%1,%2,%3}, {%4,%5,%6,%7}, {%8,%9}, {%0,%1,%2,%3};"
                 : "+f"(d[0]), "+f"(d[1]), "+f"(d[2]), "+f"(d[3])
                 : "r"(a[0]), "r"(a[1]), "r"(a[2]), "r"(a[3]),
                   "r"(b0), "r"(b1));
}
__device__ __forceinline__ void bulk_ld(uint32_t dst, const void* src,
                                        uint32_t bytes, uint32_t mbar) {
    asm volatile("cp.async.bulk.shared::cluster.global.mbarrier::complete_tx::bytes "
                 "[%0], [%1], %2, [%3];"
                 :: "r"(dst), "l"(src), "r"(bytes), "r"(mbar) : "memory");
}
__device__ __forceinline__ void mbar_init(uint32_t a, uint32_t cnt) {
    asm volatile("mbarrier.init.shared.b64 [%0], %1;" :: "r"(a), "r"(cnt) : "memory");
}
__device__ __forceinline__ void mbar_expect_tx(uint32_t a, uint32_t bytes) {
    asm volatile("mbarrier.arrive.expect_tx.shared.b64 _, [%0], %1;"
                 :: "r"(a), "r"(bytes) : "memory");
}
__device__ __forceinline__ void mbar_arrive(uint32_t a) {
    asm volatile("mbarrier.arrive.shared.b64 _, [%0];" :: "r"(a) : "memory");
}
__device__ __forceinline__ void mbar_wait(uint32_t a, uint32_t parity) {
    asm volatile(
        "{\n\t.reg .pred P;\n\t"
        "WAIT_%=:\n\t"
        "mbarrier.try_wait.parity.acquire.cta.shared::cta.b64 P, [%0], %1, 0x989680;\n\t"
        "@P bra.uni DONE_%=;\n\t"
        "bra.uni WAIT_%=;\n\t"
        "DONE_%=:\n\t}"
        :: "r"(a), "r"(parity) : "memory");
}
__device__ __forceinline__ void fence_async_init() {
    asm volatile("fence.proxy.async.shared::cta;" ::: "memory");
}

__device__ __forceinline__ void bf16split(float x, __nv_bfloat16& h, __nv_bfloat16& l) {
    h = __float2bfloat16(x);
    l = __float2bfloat16(x - __bfloat162float(h));
}
__device__ __forceinline__ void split2pack(float a, float b, uint32_t& hp, uint32_t& lp) {
    __nv_bfloat16 ha, la, hb, lb;
    bf16split(a, ha, la);
    bf16split(b, hb, lb);
    __nv_bfloat162 h; h.x = ha; h.y = hb;
    __nv_bfloat162 l; l.x = la; l.y = lb;
    hp = *(uint32_t*)&h;
    lp = *(uint32_t*)&l;
}

// ---------------------------------------------------------------------------
// Convert Q_S and X into tiled, pre-swizzled bf16 hi/lo tile pairs.
// Tile (rb,cc) pair base = (rb*64+cc)*TILEP; element (i,j):
//   off = i*128 + j*2; sw = off ^ ((i&7)<<4); hi at sw, lo at 8192+sw.
// ---------------------------------------------------------------------------
__global__ __launch_bounds__(256) void conv_kernel(const float4* __restrict__ Q,
                                                   const float4* __restrict__ X) {
    const size_t QN4 = (size_t)NDIM * NDIM / 4;
    size_t gid = (size_t)blockIdx.x * 256 + threadIdx.x;
    float4 v;
    char* base;
    uint32_t r, c;
    if (gid < QN4) {
        v = Q[gid];
        r = (uint32_t)(gid >> 10);
        c = ((uint32_t)gid & 1023) * 4;
        base = g_Qt + ((size_t)((r >> 6) * 64 + (c >> 6))) * TILEP;
    } else {
        size_t x = gid - QN4;
        v = X[x];
        r = (uint32_t)(x >> 10);
        c = ((uint32_t)x & 1023) * 4;
        base = g_Xt + (size_t)(c >> 6) * TILEP;
    }
    const uint32_t i = r & 63, j = c & 63;
    const uint32_t sw = (i * 128 + j * 2) ^ ((i & 7) << 4);
    uint32_t h0, l0, h1, l1;
    split2pack(v.x, v.y, h0, l0);
    split2pack(v.z, v.w, h1, l1);
    *(uint2*)(base + sw)        = make_uint2(h0, h1);
    *(uint2*)(base + 8192 + sw) = make_uint2(l0, l1);
}

// ---------------------------------------------------------------------------
// Zero-init Y and Z (outputs accumulated via atomicAdd each replay)
// ---------------------------------------------------------------------------
__global__ __launch_bounds__(256) void zero_kernel(float* __restrict__ a,
                                                   float* __restrict__ b) {
    int i = blockIdx.x * 256 + threadIdx.x;
    a[i] = 0.0f;
    b[i] = 0.0f;
}

// ---------------------------------------------------------------------------
// G~ = 2 * (F^T F) / (||F^T F||_F + 1e-12) - I
// ---------------------------------------------------------------------------
__global__ __launch_bounds__(256) void prep_kernel(const float* __restrict__ F) {
    __shared__ float Fs[MDIM][MDIM + 1];
    __shared__ float FFs[MDIM][MDIM + 4];
    __shared__ float red[8];
    __shared__ float s_inv;

    int t = threadIdx.x;
    for (int o = t; o < MDIM * MDIM; o += 256)
        Fs[o >> 6][o & 63] = F[o];
    __syncthreads();

    int i  = t >> 2;
    int j0 = (t & 3) * 16;
    float acc[16];
#pragma unroll
    for (int u = 0; u < 16; u++) acc[u] = 0.0f;
    for (int k = 0; k < MDIM; k++) {
        float a = Fs[k][i];
#pragma unroll
        for (int u = 0; u < 16; u++) acc[u] = fmaf(a, Fs[k][j0 + u], acc[u]);
    }
    float ss = 0.0f;
#pragma unroll
    for (int u = 0; u < 16; u++) {
        FFs[i][j0 + u] = acc[u];
        ss = fmaf(acc[u], acc[u], ss);
    }
#pragma unroll
    for (int off = 16; off > 0; off >>= 1)
        ss += __shfl_xor_sync(0xffffffffu, ss, off);
    if ((t & 31) == 0) red[t >> 5] = ss;
    __syncthreads();
    if (t == 0) {
        float tot = 0.0f;
        for (int w = 0; w < 8; w++) tot += red[w];
        s_inv = 2.0f / (sqrtf(tot) + 1e-12f);
    }
    __syncthreads();
    float inv = s_inv;
#pragma unroll
    for (int u = 0; u < 16; u++) {
        int j = j0 + u;
        g_Gt[i * MDIM + j] = FFs[i][j] * inv - (i == j ? 1.0f : 0.0f);
    }
}

// ---------------------------------------------------------------------------
// TMA-staged bf16 tensor GEMM on pre-swizzled tiles. Per chunk: exactly TWO
// 16KB bulk copies (A tile pair, B tile pair), issued by thread 0 only.
// NST=3 ring, fully unrolled, full count=1, empty count=8.
// TRANSB=0: C += A @ B (B tile = Qt[kc][jb]);
// TRANSB=1: C += A @ B^T (B tile = Qt[jb][kc]).
// ---------------------------------------------------------------------------
template <int TRANSB>
__global__ __launch_bounds__(256) void gemm_bf(const char* __restrict__ At,
                                               const char* __restrict__ Bt,
                                               float* __restrict__ C) {
    extern __shared__ __align__(128) char sm[];
    const uint32_t smb = sptr(sm);

    const int t    = threadIdx.x;
    const int lane = t & 31;
    const int warp = t >> 5;
    const int jb   = blockIdx.x;
    const int jg   = jb * BN;
    const int kb0  = blockIdx.y * (KSPL / 64);
    const int mw   = (warp & 3) * 16;
    const int nw   = (warp >> 2) * 32;
    const int lr   = lane & 15;
    const int g8   = (lane >> 4) * 8;

    if (t == 0) {
#pragma unroll
        for (int s = 0; s < NST; s++) {
            mbar_init(smb + s * 16, 1);     // full
            mbar_init(smb + s * 16 + 8, 8); // empty (one arrive per warp)
        }
        fence_async_init();
    }
    __syncthreads();

    const char* srcA = At + (size_t)kb0 * TILEP;
    const char* srcB = Bt + (TRANSB ? ((size_t)jb * 64 + kb0)
                                    : ((size_t)kb0 * 64 + jb)) * TILEP;
    const long dB = TRANSB ? TILEP : (long)64 * TILEP;

    // per-thread swizzled ldsm offsets (loop-invariant)
    const uint32_t xorv = (uint32_t)(lane & 7) << 4;
    uint32_t aoffs[4];
#pragma unroll
    for (int ks = 0; ks < 4; ks++)
        aoffs[ks] = (uint32_t)(mw + lr) * 128 + (((uint32_t)(ks * 32 + g8 * 2)) ^ xorv);
    uint32_t boffs[4][2];
#pragma unroll
    for (int ks = 0; ks < 4; ks++)
#pragma unroll
        for (int half = 0; half < 2; half++) {
            if (TRANSB == 0)
                boffs[ks][half] = (uint32_t)(ks * 16 + lr) * 128 +
                                  (((uint32_t)((nw + half * 16 + g8) * 2)) ^ xorv);
            else
                boffs[ks][half] = (uint32_t)(nw + half * 16 + lr) * 128 +
                                  (((uint32_t)(ks * 32 + g8 * 2)) ^ xorv);
        }

    float acc[4][4];
#pragma unroll
    for (int nt = 0; nt < 4; nt++)
#pragma unroll
        for (int u = 0; u < 4; u++) acc[nt][u] = 0.0f;

    // prologue: fill stages 0..NST-2
    if (t == 0) {
#pragma unroll
        for (int cn = 0; cn < NST - 1; cn++) {
            uint32_t full = smb + cn * 16;
            mbar_expect_tx(full, TX_BYTES);
            bulk_ld(smb + 128 + cn * STAGE_BYTES,         srcA + (long)cn * TILEP, TILEP, full);
            bulk_ld(smb + 128 + cn * STAGE_BYTES + TILEP, srcB + (long)cn * dB,    TILEP, full);
        }
    }

#pragma unroll
    for (int cb = 0; cb < NCH; cb += NST) {
        const int q    = cb / NST;
        const int cpar = q & 1;
#pragma unroll
        for (int s = 0; s < NST; s++) {
            const int cc = cb + s;
            if (cc >= NCH) break;
            const int cn = cc + NST - 1;          // chunk to issue
            const int istage = (s + NST - 1) % NST;
            if (cn < NCH && t == 0) {
                if (cn >= NST) {
                    const int ipar = (s == 0) ? ((q - 1) & 1) : cpar;
                    mbar_wait(smb + istage * 16 + 8, ipar);
                }
                const uint32_t full = smb + istage * 16;
                mbar_expect_tx(full, TX_BYTES);
                bulk_ld(smb + 128 + istage * STAGE_BYTES,         srcA + (long)cn * TILEP, TILEP, full);
                bulk_ld(smb + 128 + istage * STAGE_BYTES + TILEP, srcB + (long)cn * dB,    TILEP, full);
            }

            // consume chunk cc at stage s
            mbar_wait(smb + s * 16, cpar);

            const uint32_t Ah = smb + 128 + s * STAGE_BYTES;
            const uint32_t Al = Ah + 8192;
            const uint32_t Bh = Ah + TILEP;
            const uint32_t Bl = Bh + 8192;

#pragma unroll
            for (int ks = 0; ks < 4; ks++) {
                uint32_t ah[4], al[4];
                ldsm4(ah, Ah + aoffs[ks]);
                ldsm4(al, Al + aoffs[ks]);
#pragma unroll
                for (int half = 0; half < 2; half++) {
                    uint32_t bh[4], bl[4];
                    if (TRANSB == 0) {
                        ldsm4t(bh, Bh + boffs[ks][half]);
                        ldsm4t(bl, Bl + boffs[ks][half]);
                        mma16816(acc[half * 2],     ah, bh[0], bh[1]);
                        mma16816(acc[half * 2],     ah, bl[0], bl[1]);
                        mma16816(acc[half * 2],     al, bh[0], bh[1]);
                        mma16816(acc[half * 2 + 1], ah, bh[2], bh[3]);
                        mma16816(acc[half * 2 + 1], ah, bl[2], bl[3]);
                        mma16816(acc[half * 2 + 1], al, bh[2], bh[3]);
                    } else {
                        ldsm4(bh, Bh + boffs[ks][half]);
                        ldsm4(bl, Bl + boffs[ks][half]);
                        mma16816(acc[half * 2],     ah, bh[0], bh[2]);
                        mma16816(acc[half * 2],     ah, bl[0], bl[2]);
                        mma16816(acc[half * 2],     al, bh[0], bh[2]);
                        mma16816(acc[half * 2 + 1], ah, bh[1], bh[3]);
                        mma16816(acc[half * 2 + 1], ah, bl[1], bl[3]);
                        mma16816(acc[half * 2 + 1], al, bh[1], bh[3]);
                    }
                }
            }
            if (lane == 0) mbar_arrive(smb + s * 16 + 8);
        }
    }

    const int row = mw + (lane >> 2);
#pragma unroll
    for (int nt = 0; nt < 4; nt++) {
        const int col = jg + nw + (nt >> 1) * 16 + (nt & 1) * 8 + (lane & 3) * 2;
        atomicAdd(&C[(size_t)row * NDIM + col],           acc[nt][0]);
        atomicAdd(&C[(size_t)row * NDIM + col + 1],       acc[nt][1]);
        atomicAdd(&C[(size_t)(row + 8) * NDIM + col],     acc[nt][2]);
        atomicAdd(&C[(size_t)(row + 8) * NDIM + col + 1], acc[nt][3]);
    }
}

// ---------------------------------------------------------------------------
// Tensor-core Chebyshev. Output goes into the tiled/pre-swizzled g_Ztt so the
// second GEMM can TMA-load it.
// ---------------------------------------------------------------------------
__global__ __launch_bounds__(256) void cheb_tc(const float* __restrict__ lamS,
                                               const float* __restrict__ gammap) {
    extern __shared__ __align__(16) __nv_bfloat16 cs[];
    __nv_bfloat16* Gh = cs;
    __nv_bfloat16* Gl = cs + 64 * GST;
    __nv_bfloat16* Tbh = cs + 2 * 64 * GST;
    __nv_bfloat16* Tbl = Tbh + 3 * 64 * TST;
    __shared__ float sh_base[32];
    __shared__ float sh_r[32];

    const int t    = threadIdx.x;
    const int lane = t & 31;
    const int warp = t >> 5;
    const int jg   = blockIdx.x * 32;
    const int mw   = (warp & 3) * 16;
    const int nw   = (warp >> 2) * 16;
    const int lr   = lane & 15;
    const int g8   = (lane >> 4) * 8;

    for (int o = t; o < MDIM * MDIM; o += 256) {
        int r = o >> 6, c = o & 63;
        __nv_bfloat16 h, l;
        bf16split(g_Gt[o], h, l);
        Gh[r * GST + c] = h;
        Gl[r * GST + c] = l;
    }
    for (int o = t; o < MDIM * 32; o += 256) {
        int r = o >> 5, c = o & 31;
        __nv_bfloat16 h, l;
        bf16split(g_Y[(size_t)r * NDIM + jg + c], h, l);
        Tbh[r * TST + c] = h;
        Tbl[r * TST + c] = l;
    }
    if (t < 32) {
        float gam = gammap[0];
        float a = gam * lamS[jg + t];
        float base, r;
        if (fabsf(a) < 1e-7f) {
            base = 1.0f; r = 0.0f;
        } else {
            float b  = 2.0f / a - 1.0f;
            float ab = fabsf(b);
            float s  = sqrtf(fmaf(ab, ab, -1.0f));
            float q  = 1.0f / (ab + s);
            float sg = (a > 0.0f) ? 1.0f : -1.0f;
            r    = sg * q;
            base = (2.0f / a) * sg * 2.0f * q / (1.0f - q * q);
        }
        sh_base[t] = base;
        sh_r[t]    = r;
    }
    __syncthreads();

    uint32_t gh[4][4], gl[4][4];
#pragma unroll
    for (int ks = 0; ks < 4; ks++) {
        ldsm4(gh[ks], sptr(Gh + (mw + lr) * GST + ks * 16 + g8));
        ldsm4(gl[ks], sptr(Gl + (mw + lr) * GST + ks * 16 + g8));
    }

    const int row0 = mw + (lane >> 2);
    float basev[2][2], rv[2][2], pv[2][2];
#pragma unroll
    for (int nt = 0; nt < 2; nt++) {
        int c0 = nw + nt * 8 + 2 * (lane & 3);
        basev[nt][0] = sh_base[c0];     basev[nt][1] = sh_base[c0 + 1];
        rv[nt][0]    = sh_r[c0];        rv[nt][1]    = sh_r[c0 + 1];
        pv[nt][0] = 2.0f * basev[nt][0] * rv[nt][0];
        pv[nt][1] = 2.0f * basev[nt][1] * rv[nt][1];
    }

    float acc[2][4], prev[2][4], tp[2][4];
#pragma unroll
    for (int nt = 0; nt < 2; nt++) {
        int c0 = nw + nt * 8 + 2 * (lane & 3);
        float2 y0 = *(const float2*)&g_Y[(size_t)row0 * NDIM + jg + c0];
        float2 y1 = *(const float2*)&g_Y[(size_t)(row0 + 8) * NDIM + jg + c0];
        prev[nt][0] = y0.x; prev[nt][1] = y0.y; prev[nt][2] = y1.x; prev[nt][3] = y1.y;
        acc[nt][0] = basev[nt][0] * y0.x;
        acc[nt][1] = basev[nt][1] * y0.y;
        acc[nt][2] = basev[nt][0] * y1.x;
        acc[nt][3] = basev[nt][1] * y1.y;
        tp[nt][0] = tp[nt][1] = tp[nt][2] = tp[nt][3] = 0.0f;
    }

    for (int k = 1; k < KCHEB; k++) {
        __syncthreads();
        const __nv_bfloat16* Th = Tbh + ((k - 1) % 3) * (64 * TST);
        const __nv_bfloat16* Tl = Tbl + ((k - 1) % 3) * (64 * TST);
        float u[2][4];
#pragma unroll
        for (int nt = 0; nt < 2; nt++)
#pragma unroll
            for (int i = 0; i < 4; i++) u[nt][i] = 0.0f;
#pragma unroll
        for (int ks = 0; ks < 4; ks++) {
            uint32_t th[4], tl[4];
            ldsm4t(th, sptr(Th + (ks * 16 + lr) * TST + nw + g8));
            ldsm4t(tl, sptr(Tl + (ks * 16 + lr) * TST + nw + g8));
            mma16816(u[0], gh[ks], th[0], th[1]);
            mma16816(u[0], gh[ks], tl[0], tl[1]);
            mma16816(u[0], gl[ks], th[0], th[1]);
            mma16816(u[1], gh[ks], th[2], th[3]);
            mma16816(u[1], gh[ks], tl[2], tl[3]);
            mma16816(u[1], gl[ks], th[2], th[3]);
        }
        float tn[2][4];
#pragma unroll
        for (int nt = 0; nt < 2; nt++)
#pragma unroll
            for (int i = 0; i < 4; i++)
                tn[nt][i] = (k == 1) ? u[nt][i] : fmaf(2.0f, u[nt][i], -tp[nt][i]);
#pragma unroll
        for (int nt = 0; nt < 2; nt++) {
            acc[nt][0] = fmaf(pv[nt][0], tn[nt][0], acc[nt][0]);
            acc[nt][1] = fmaf(pv[nt][1], tn[nt][1], acc[nt][1]);
            acc[nt][2] = fmaf(pv[nt][0], tn[nt][2], acc[nt][2]);
            acc[nt][3] = fmaf(pv[nt][1], tn[nt][3], acc[nt][3]);
            pv[nt][0] *= rv[nt][0];
            pv[nt][1] *= rv[nt][1];
        }
        if (k < KCHEB - 1) {
            __nv_bfloat16* Wh = Tbh + (k % 3) * (64 * TST);
            __nv_bfloat16* Wl = Tbl + (k % 3) * (64 * TST);
#pragma unroll
            for (int nt = 0; nt < 2; nt++) {
                int c0 = nw + nt * 8 + 2 * (lane & 3);
                uint32_t hp, lp;
                split2pack(tn[nt][0], tn[nt][1], hp, lp);
                *(uint32_t*)(Wh + row0 * TST + c0) = hp;
                *(uint32_t*)(Wl + row0 * TST + c0) = lp;
                split2pack(tn[nt][2], tn[nt][3], hp, lp);
                *(uint32_t*)(Wh + (row0 + 8) * TST + c0) = hp;
                *(uint32_t*)(Wl + (row0 + 8) * TST + c0) = lp;
            }
        }
#pragma unroll
        for (int nt = 0; nt < 2; nt++)
#pragma unroll
            for (int i = 0; i < 4; i++) {
                tp[nt][i]   = prev[nt][i];
                prev[nt][i] = tn[nt][i];
            }
    }

    // write Z~ into tiled/pre-swizzled g_Ztt: tile kc = jg/64, col jo + c0
    {
        char* Zt = g_Ztt + (size_t)(jg >> 6) * TILEP;
        const uint32_t jo = jg & 63;
#pragma unroll
        for (int nt = 0; nt < 2; nt++) {
            const uint32_t c0 = nw + nt * 8 + 2 * (lane & 3);
            uint32_t hp, lp;
            split2pack(acc[nt][0], acc[nt][1], hp, lp);
            uint32_t o0 = (uint32_t)row0 * 128 + (((jo + c0) * 2) ^ (((uint32_t)row0 & 7) << 4));
            *(uint32_t*)(Zt + o0)        = hp;
            *(uint32_t*)(Zt + 8192 + o0) = lp;
            split2pack(acc[nt][2], acc[nt][3], hp, lp);
            uint32_t o1 = (uint32_t)(row0 + 8) * 128 + (((jo + c0) * 2) ^ (((uint32_t)row0 & 7) << 4));
            *(uint32_t*)(Zt + o1)        = hp;
            *(uint32_t*)(Zt + 8192 + o1) = lp;
        }
    }
}

#define CHEB_SMEM ((2 * 64 * GST + 6 * 64 * TST) * 2)

// ---------------------------------------------------------------------------
extern "C" void kernel_launch(void* const* d_in, const int* in_sizes, int n_in,
                              void* d_out, int out_size) {
    const float* X    = (const float*)d_in[0];   // (64, 4096)
    const float* F    = (const float*)d_in[1];   // (64, 64)
    const float* Q_S  = (const float*)d_in[2];   // (4096, 4096)
    const float* lamS = (const float*)d_in[3];   // (4096,)
    const float* gam  = (const float*)d_in[4];   // scalar
    float* Z = (float*)d_out;                    // (64, 4096)

    float* Y;
    char *Qt, *Xt, *Ztt;
    cudaGetSymbolAddress((void**)&Y,   g_Y);
    cudaGetSymbolAddress((void**)&Qt,  g_Qt);
    cudaGetSymbolAddress((void**)&Xt,  g_Xt);
    cudaGetSymbolAddress((void**)&Ztt, g_Ztt);

    static bool attr_set = false;
    if (!attr_set) {
        cudaFuncSetAttribute(gemm_bf<0>, cudaFuncAttributeMaxDynamicSharedMemorySize, GEMM_SMEM);
        cudaFuncSetAttribute(gemm_bf<1>, cudaFuncAttributeMaxDynamicSharedMemorySize, GEMM_SMEM);
        cudaFuncSetAttribute(cheb_tc,    cudaFuncAttributeMaxDynamicSharedMemorySize, CHEB_SMEM);
        attr_set = true;
    }

    const int conv_blocks = (NDIM * NDIM / 4 + MDIM * NDIM / 4) / 256;  // 16640
    dim3 ggrid(NDIM / BN, NSPLIT);

    conv_kernel<<<conv_blocks, 256>>>((const float4*)Q_S, (const float4*)X);
    zero_kernel<<<(MDIM * NDIM) / 256, 256>>>(Y, Z);
    prep_kernel<<<1, 256>>>(F);
    gemm_bf<0><<<ggrid, 256, GEMM_SMEM>>>(Xt, Qt, Y);    // Y += X @ Q_S
    cheb_tc<<<NDIM / 32, 256, CHEB_SMEM>>>(lamS, gam);   // Ztt = f(G) Y (tiled)
    gemm_bf<1><<<ggrid, 256, GEMM_SMEM>>>(Ztt, Qt, Z);   // Z += Z~ @ Q_S^T
}